// round 12
// baseline (speedup 1.0000x reference)
#include <cuda_runtime.h>
#include <cuda_bf16.h>
#include <cstdint>

#define H      1024
#define NHEADS 16
#define HDIM   64
#define NQ     256
#define BATCH  4
#define LAYERS 4
#define DOC    2048
#define KVLEN  8192
#define FFN_D  4096
#define M1     (BATCH*NQ)      /* 1024  */
#define MH     (BATCH*KVLEN)   /* 32768 */

// ---------------- device scratch ----------------
__device__ float g_xln [M1*H];
__device__ float g_qkv [3*M1*H];
__device__ float g_attn[M1*H];
__device__ float g_qt1 [M1*H];
__device__ float g_qt2 [M1*H];
__device__ float g_h1  [M1*FFN_D];
__device__ float g_qk  [(size_t)NHEADS*M1*H];   // bf16 qk lives in low half; also w3 split-K float partials
__device__ float g_hbar[(size_t)NHEADS*M1*H];   // [h][row][i] fp32 (tf32-rounded)

// ---------------- helpers ----------------
__device__ __forceinline__ uint32_t f2tf32(float x) {
    uint32_t r;
    asm("cvt.rna.tf32.f32 %0, %1;" : "=r"(r) : "f"(x));
    return r;
}
__device__ __forceinline__ float rtf(float x) { return __uint_as_float(f2tf32(x)); }

__device__ __forceinline__ void mma_tf32(float c[4], const uint32_t a[4], const uint32_t b[2]) {
    asm volatile(
        "mma.sync.aligned.m16n8k8.row.col.f32.tf32.tf32.f32 "
        "{%0,%1,%2,%3}, {%4,%5,%6,%7}, {%8,%9}, {%0,%1,%2,%3};\n"
        : "+f"(c[0]), "+f"(c[1]), "+f"(c[2]), "+f"(c[3])
        : "r"(a[0]), "r"(a[1]), "r"(a[2]), "r"(a[3]), "r"(b[0]), "r"(b[1]));
}
__device__ __forceinline__ void ldm4(uint32_t a[4], uint32_t addr) {
    asm volatile("ldmatrix.sync.aligned.m8n8.x4.shared.b16 {%0,%1,%2,%3}, [%4];\n"
                 : "=r"(a[0]), "=r"(a[1]), "=r"(a[2]), "=r"(a[3]) : "r"(addr));
}
__device__ __forceinline__ void cp16(float* s, const float* g) {
    uint32_t sa = (uint32_t)__cvta_generic_to_shared(s);
    asm volatile("cp.async.cg.shared.global [%0], [%1], 16;\n" :: "r"(sa), "l"(g));
}
#define CP_COMMIT() asm volatile("cp.async.commit_group;\n")
#define CP_WAIT(n)  asm volatile("cp.async.wait_group %0;\n" :: "n"(n))

// ---------------- LayerNorm (output rounded to tf32 — feeds GEMMs only) ----------------
__global__ void ln_kernel(const float* __restrict__ x, const float* __restrict__ g,
                          const float* __restrict__ b, float* __restrict__ y)
{
    __shared__ float red[16];
    const int row = blockIdx.x, tid = threadIdx.x;
    const float* xr = x + (size_t)row * H;
    float v[4]; float s = 0.f, s2 = 0.f;
#pragma unroll
    for (int i = 0; i < 4; i++) { v[i] = xr[tid + i*256]; s += v[i]; s2 += v[i]*v[i]; }
#pragma unroll
    for (int o = 16; o > 0; o >>= 1) { s += __shfl_xor_sync(~0u, s, o); s2 += __shfl_xor_sync(~0u, s2, o); }
    if ((tid & 31) == 0) { red[tid>>5] = s; red[8 + (tid>>5)] = s2; }
    __syncthreads();
    if (tid < 32) {
        s  = (tid < 8) ? red[tid]     : 0.f;
        s2 = (tid < 8) ? red[8 + tid] : 0.f;
#pragma unroll
        for (int o = 4; o > 0; o >>= 1) { s += __shfl_xor_sync(~0u, s, o); s2 += __shfl_xor_sync(~0u, s2, o); }
        if (tid == 0) { red[0] = s; red[1] = s2; }
    }
    __syncthreads();
    const float mu  = red[0] * (1.f / H);
    const float var = red[1] * (1.f / H) - mu * mu;
    const float rs  = rsqrtf(var + 1e-5f);
    float* yr = y + (size_t)row * H;
#pragma unroll
    for (int i = 0; i < 4; i++) { int c = tid + i*256; yr[c] = rtf((v[i] - mu) * rs * g[c] + b[c]); }
}

// ================= Unified GEMM (ldmatrix, 3-stage cp.async, 2x4 warp grid) =================
// BT=1: C = A@B^T (B stored [N,K]);  BT=0: C = A@B (B stored [K,N]) — BK must be 32 for BT=0.
// epi 0: store tf32-rounded; epi 1: C = R + acc raw (dup to C2); epi 3: store raw;
// epi 4: store bf16x2 (C treated as __nv_bfloat16 base, ldc in elements).
constexpr int smem_g2(int BM, int BN, int BT, int BK) {
    return (3*BM*(BK+4) + (BT ? 3*BN*(BK+4) : 3*32*(BN+8))) * 4;
}

template<int BT, int BM, int BN, int BK>
__global__ void __launch_bounds__(256) gemm2(
    const float* __restrict__ A, int lda, long Az,
    const float* __restrict__ B, int ldb, long Bz,
    float* __restrict__ C, int ldc, long Cz,
    const float* __restrict__ R, float* __restrict__ C2,
    int K, int epi)
{
    extern __shared__ float sm[];
    constexpr int RS  = BK + 4;
    constexpr int ASZ = BM * RS;
    constexpr int BSZ = BT ? BN * RS : 32*(BN+8);
    constexpr int MI = BM / 32;
    constexpr int NI = BN / 32;
    constexpr int KCN = BK / 8;
    constexpr int TPR = BK / 4;
    float* As = sm;
    float* Bs = sm + 3*ASZ;

    const int tid  = threadIdx.x;
    const int lane = tid & 31, warp = tid >> 5;
    const int wm = (warp & 1) * (BM/2);
    const int wn = (warp >> 1) * (BN/4);
    const int lr = lane >> 2, lc = lane & 3;
    const int g8 = lane >> 3, r8 = lane & 7;
    const int m0 = blockIdx.y * BM, n0 = blockIdx.x * BN;
    const float* Ab = A + (size_t)blockIdx.z * Az;
    const float* Bb = B + (size_t)blockIdx.z * Bz;
    float*       Cb = C + (size_t)blockIdx.z * Cz;

    const uint32_t As_u = (uint32_t)__cvta_generic_to_shared(As);
    const uint32_t Bs_u = (uint32_t)__cvta_generic_to_shared(Bs);
    const uint32_t aoff = ((wm + (g8 & 1) * 8 + r8) * RS + (g8 >> 1) * 4) * 4;
    const uint32_t boff = ((wn + (g8 >> 1) * 8 + r8) * RS + (g8 & 1) * 4) * 4;

    float acc[MI][NI][4];
#pragma unroll
    for (int i = 0; i < MI; i++)
#pragma unroll
        for (int j = 0; j < NI; j++)
#pragma unroll
            for (int r = 0; r < 4; r++) acc[i][j][r] = 0.f;

    auto loadA = [&](int buf, int k0) {
        float* dst = As + buf * ASZ;
#pragma unroll
        for (int i = 0; i < BM*BK/1024; i++) {
            const int c = tid + i * 256;
            const int r = c / TPR, cc = (c % TPR) * 4;
            cp16(dst + r * RS + cc, Ab + (size_t)(m0 + r) * lda + k0 + cc);
        }
    };
    auto loadB = [&](int buf, int k0) {
        float* dst = Bs + buf * BSZ;
        if (BT) {
#pragma unroll
            for (int i = 0; i < BN*BK/1024; i++) {
                const int c = tid + i * 256;
                const int r = c / TPR, cc = (c % TPR) * 4;
                cp16(dst + r * RS + cc, Bb + (size_t)(n0 + r) * ldb + k0 + cc);
            }
        } else {
#pragma unroll
            for (int i = 0; i < BN/32; i++) {
                const int c = tid + i * 256;
                const int r = c / (BN/4), cc = (c % (BN/4)) * 4;
                cp16(dst + r * (BN+8) + cc, Bb + (size_t)(k0 + r) * ldb + n0 + cc);
            }
        }
    };

    const int ntiles = K / BK;
    loadA(0, 0); loadB(0, 0); CP_COMMIT();
    if (ntiles > 1) { loadA(1, BK); loadB(1, BK); CP_COMMIT(); }

    for (int t = 0; t < ntiles; t++) {
        const int cur = t % 3;
        if (t < ntiles - 1) CP_WAIT(1); else CP_WAIT(0);
        __syncthreads();
        if (t + 2 < ntiles) {
            const int s = (t + 2) % 3;
            loadA(s, (t + 2) * BK);
            loadB(s, (t + 2) * BK);
            CP_COMMIT();
        }
        const uint32_t aB = As_u + cur * ASZ * 4;
        const uint32_t bB = Bs_u + cur * BSZ * 4;
        const float* Bsb = Bs + cur * BSZ;
#pragma unroll
        for (int kc = 0; kc < KCN; kc++) {
            const uint32_t kk4 = kc * 32;
            uint32_t af[MI][4], bf[NI][2];
#pragma unroll
            for (int mi = 0; mi < MI; mi++)
                ldm4(af[mi], aB + aoff + kk4 + mi * 16*RS*4);
            if (BT) {
#pragma unroll
                for (int p = 0; p < NI/2; p++) {
                    uint32_t bt[4];
                    ldm4(bt, bB + boff + kk4 + p * 16*RS*4);
                    bf[2*p  ][0] = bt[0]; bf[2*p  ][1] = bt[1];
                    bf[2*p+1][0] = bt[2]; bf[2*p+1][1] = bt[3];
                }
            } else {
                const int kk = kc * 8;
#pragma unroll
                for (int ni = 0; ni < NI; ni++) {
                    const int nb = wn + ni * 8;
                    bf[ni][0] = __float_as_uint(Bsb[(kk + lc    ) * (BN+8) + nb + lr]);
                    bf[ni][1] = __float_as_uint(Bsb[(kk + lc + 4) * (BN+8) + nb + lr]);
                }
            }
#pragma unroll
            for (int mi = 0; mi < MI; mi++)
#pragma unroll
                for (int ni = 0; ni < NI; ni++)
                    mma_tf32(acc[mi][ni], af[mi], bf[ni]);
        }
    }
    __syncthreads();

#pragma unroll
    for (int mi = 0; mi < MI; mi++)
#pragma unroll
        for (int ni = 0; ni < NI; ni++)
#pragma unroll
            for (int hh = 0; hh < 2; hh++) {
                const int row = m0 + wm + mi*16 + lr + hh*8;
                const int col = n0 + wn + ni*8  + lc*2;
                const float v0 = acc[mi][ni][hh*2+0];
                const float v1 = acc[mi][ni][hh*2+1];
                if (epi == 0) {
                    *(float2*)(Cb + (size_t)row * ldc + col) = make_float2(rtf(v0), rtf(v1));
                } else if (epi == 3) {
                    *(float2*)(Cb + (size_t)row * ldc + col) = make_float2(v0, v1);
                } else if (epi == 4) {
                    __nv_bfloat16* Ch = (__nv_bfloat16*)Cb;
                    *(__nv_bfloat162*)(Ch + (size_t)row * ldc + col) = __floats2bfloat162_rn(v0, v1);
                } else {
                    const size_t o = (size_t)row * ldc + col;
                    const float r0 = R[o] + v0, r1 = R[o+1] + v1;
                    *(float2*)(Cb + o) = make_float2(r0, r1);
                    if (C2) *(float2*)(C2 + o) = make_float2(r0, r1);
                }
            }
}

// ---- batched QKV (BM128/BN64/BK32, 4x2 warp grid — validated; unchanged) ----
__global__ void __launch_bounds__(256) gemm_qkv(
    const float* __restrict__ A,
    const float* __restrict__ B0, const float* __restrict__ B1, const float* __restrict__ B2,
    float* __restrict__ C)
{
    extern __shared__ float sm[];
    float* As = sm;
    float* Bs = sm + 3*128*36;
    const int z = blockIdx.z;
    const float* B = (z == 0) ? B0 : (z == 1) ? B1 : B2;
    float* Cb = C + (size_t)z * M1 * H;

    const int tid  = threadIdx.x;
    const int lane = tid & 31, warp = tid >> 5;
    const int wm = (warp & 3) * 32, wn = (warp >> 2) * 32;
    const int lr = lane >> 2, lc = lane & 3;
    const int g8 = lane >> 3, r8 = lane & 7;
    const int m0 = blockIdx.y * 128, n0 = blockIdx.x * 64;

    const uint32_t As_u = (uint32_t)__cvta_generic_to_shared(As);
    const uint32_t Bs_u = (uint32_t)__cvta_generic_to_shared(Bs);
    const uint32_t aoff = ((wm + (g8 & 1) * 8 + r8) * 36 + (g8 >> 1) * 4) * 4;
    const uint32_t boff = ((wn + (g8 >> 1) * 8 + r8) * 36 + (g8 & 1) * 4) * 4;

    float acc[2][4][4];
#pragma unroll
    for (int i = 0; i < 2; i++)
#pragma unroll
        for (int j = 0; j < 4; j++)
#pragma unroll
            for (int r = 0; r < 4; r++) acc[i][j][r] = 0.f;

    auto loadA = [&](int buf, int k0) {
        float* dst = As + buf * 4608;
#pragma unroll
        for (int i = 0; i < 4; i++) {
            const int c = tid + i * 256;
            const int r = c >> 3, cc = (c & 7) * 4;
            cp16(dst + r * 36 + cc, A + (size_t)(m0 + r) * H + k0 + cc);
        }
    };
    auto loadB = [&](int buf, int k0) {
        float* dst = Bs + buf * 2304;
#pragma unroll
        for (int i = 0; i < 2; i++) {
            const int c = tid + i * 256;
            const int r = c >> 3, cc = (c & 7) * 4;
            cp16(dst + r * 36 + cc, B + (size_t)(n0 + r) * H + k0 + cc);
        }
    };

    loadA(0, 0); loadB(0, 0); CP_COMMIT();
    loadA(1, 32); loadB(1, 32); CP_COMMIT();
    for (int t = 0; t < 32; t++) {
        const int cur = t % 3;
        if (t < 31) CP_WAIT(1); else CP_WAIT(0);
        __syncthreads();
        if (t + 2 < 32) {
            const int s = (t + 2) % 3;
            loadA(s, (t + 2) << 5); loadB(s, (t + 2) << 5); CP_COMMIT();
        }
        const uint32_t aB = As_u + cur * 4608 * 4;
        const uint32_t bB = Bs_u + cur * 2304 * 4;
#pragma unroll
        for (int kc = 0; kc < 4; kc++) {
            const uint32_t kk4 = kc * 32;
            uint32_t af[2][4], bf[4][2], bt[4];
            ldm4(af[0], aB + aoff + kk4);
            ldm4(af[1], aB + aoff + kk4 + 16*36*4);
            ldm4(bt, bB + boff + kk4);
            bf[0][0] = bt[0]; bf[0][1] = bt[1]; bf[1][0] = bt[2]; bf[1][1] = bt[3];
            ldm4(bt, bB + boff + kk4 + 16*36*4);
            bf[2][0] = bt[0]; bf[2][1] = bt[1]; bf[3][0] = bt[2]; bf[3][1] = bt[3];
#pragma unroll
            for (int mi = 0; mi < 2; mi++)
#pragma unroll
                for (int ni = 0; ni < 4; ni++)
                    mma_tf32(acc[mi][ni], af[mi], bf[ni]);
        }
    }
    __syncthreads();
#pragma unroll
    for (int mi = 0; mi < 2; mi++)
#pragma unroll
        for (int ni = 0; ni < 4; ni++)
#pragma unroll
            for (int hh = 0; hh < 2; hh++) {
                const int row = m0 + wm + mi*16 + lr + hh*8;
                const int col = n0 + wn + ni*8  + lc*2;
                *(float2*)(Cb + (size_t)row * H + col) =
                    make_float2(acc[mi][ni][hh*2], acc[mi][ni][hh*2+1]);
            }
}

// ---- fused FFN (2-stage pipeline, 2 CTAs/SM): C = silu(A@W1^T) * (A@W2^T) ----
#define FFN_SMEM ((2*128*36 + 4*2304) * 4)
__global__ void __launch_bounds__(256) gemm_ffn(
    const float* __restrict__ A, const float* __restrict__ W1, const float* __restrict__ W2,
    float* __restrict__ C)
{
    extern __shared__ float sm[];
    float* As  = sm;                 // 2 x 4608
    float* Bs1 = sm + 2*4608;        // 2 x 2304
    float* Bs2 = Bs1 + 2*2304;       // 2 x 2304

    const int tid  = threadIdx.x;
    const int lane = tid & 31, warp = tid >> 5;
    const int wm = (warp & 3) * 32, wn = (warp >> 2) * 32;
    const int lr = lane >> 2, lc = lane & 3;
    const int g8 = lane >> 3, r8 = lane & 7;
    const int m0 = blockIdx.y * 128, n0 = blockIdx.x * 64;

    const uint32_t As_u  = (uint32_t)__cvta_generic_to_shared(As);
    const uint32_t Bs1_u = (uint32_t)__cvta_generic_to_shared(Bs1);
    const uint32_t Bs2_u = (uint32_t)__cvta_generic_to_shared(Bs2);
    const uint32_t aoff = ((wm + (g8 & 1) * 8 + r8) * 36 + (g8 >> 1) * 4) * 4;
    const uint32_t boff = ((wn + (g8 >> 1) * 8 + r8) * 36 + (g8 & 1) * 4) * 4;

    float a1[2][4][4], a2[2][4][4];
#pragma unroll
    for (int i = 0; i < 2; i++)
#pragma unroll
        for (int j = 0; j < 4; j++)
#pragma unroll
            for (int r = 0; r < 4; r++) { a1[i][j][r] = 0.f; a2[i][j][r] = 0.f; }

    auto loadA = [&](int buf, int k0) {
        float* dst = As + buf * 4608;
#pragma unroll
        for (int i = 0; i < 4; i++) {
            const int c = tid + i * 256;
            const int r = c >> 3, cc = (c & 7) * 4;
            cp16(dst + r * 36 + cc, A + (size_t)(m0 + r) * H + k0 + cc);
        }
    };
    auto loadB = [&](int buf, int k0) {
#pragma unroll
        for (int i = 0; i < 2; i++) {
            const int c = tid + i * 256;
            const int r = c >> 3, cc = (c & 7) * 4;
            cp16(Bs1 + buf * 2304 + r * 36 + cc, W1 + (size_t)(n0 + r) * H + k0 + cc);
            cp16(Bs2 + buf * 2304 + r * 36 + cc, W2 + (size_t)(n0 + r) * H + k0 + cc);
        }
    };

    loadA(0, 0); loadB(0, 0); CP_COMMIT();
    for (int t = 0; t < 32; t++) {
        const int cur = t & 1;
        if (t + 1 < 32) {
            loadA(cur ^ 1, (t + 1) << 5);
            loadB(cur ^ 1, (t + 1) << 5);
            CP_COMMIT();
            CP_WAIT(1);
        } else {
            CP_WAIT(0);
        }
        __syncthreads();
        const uint32_t aB  = As_u  + cur * 4608 * 4;
        const uint32_t b1B = Bs1_u + cur * 2304 * 4;
        const uint32_t b2B = Bs2_u + cur * 2304 * 4;
#pragma unroll
        for (int kc = 0; kc < 4; kc++) {
            const uint32_t kk4 = kc * 32;
            uint32_t af[2][4], b1f[4][2], b2f[4][2], bt[4];
            ldm4(af[0], aB + aoff + kk4);
            ldm4(af[1], aB + aoff + kk4 + 16*36*4);
            ldm4(bt, b1B + boff + kk4);
            b1f[0][0]=bt[0]; b1f[0][1]=bt[1]; b1f[1][0]=bt[2]; b1f[1][1]=bt[3];
            ldm4(bt, b1B + boff + kk4 + 16*36*4);
            b1f[2][0]=bt[0]; b1f[2][1]=bt[1]; b1f[3][0]=bt[2]; b1f[3][1]=bt[3];
            ldm4(bt, b2B + boff + kk4);
            b2f[0][0]=bt[0]; b2f[0][1]=bt[1]; b2f[1][0]=bt[2]; b2f[1][1]=bt[3];
            ldm4(bt, b2B + boff + kk4 + 16*36*4);
            b2f[2][0]=bt[0]; b2f[2][1]=bt[1]; b2f[3][0]=bt[2]; b2f[3][1]=bt[3];
#pragma unroll
            for (int mi = 0; mi < 2; mi++)
#pragma unroll
                for (int ni = 0; ni < 4; ni++) {
                    mma_tf32(a1[mi][ni], af[mi], b1f[ni]);
                    mma_tf32(a2[mi][ni], af[mi], b2f[ni]);
                }
        }
        __syncthreads();
    }
#pragma unroll
    for (int mi = 0; mi < 2; mi++)
#pragma unroll
        for (int ni = 0; ni < 4; ni++)
#pragma unroll
            for (int hh = 0; hh < 2; hh++) {
                const int row = m0 + wm + mi*16 + lr + hh*8;
                const int col = n0 + wn + ni*8  + lc*2;
                const float x0 = a1[mi][ni][hh*2],  x1 = a1[mi][ni][hh*2+1];
                const float g0 = x0 / (1.f + __expf(-x0));
                const float g1 = x1 / (1.f + __expf(-x1));
                *(float2*)(C + (size_t)row * FFN_D + col) =
                    make_float2(rtf(g0 * a2[mi][ni][hh*2]), rtf(g1 * a2[mi][ni][hh*2+1]));
            }
}

// ---- batched out K/V projections (2-stage, 2 CTAs/SM), 128x128 tiles, staged epilogue ----
#define OKV_SMEM ((2*128*36 + 2*128*36) * 4)
__global__ void __launch_bounds__(256) gemm_okv(
    const float* __restrict__ A,
    const float* __restrict__ BK_, const float* __restrict__ BV_,
    float* __restrict__ OutBase)
{
    extern __shared__ float sm[];
    float* As = sm;                  // 2 x 4608
    float* Bs = sm + 2*4608;         // 2 x 4608
    const int z = blockIdx.z;
    const float* B = z ? BV_ : BK_;
    float* Ob = OutBase + (size_t)z * 4194304;

    const int tid  = threadIdx.x;
    const int lane = tid & 31, warp = tid >> 5;
    const int wm = (warp & 1) * 64, wn = (warp >> 1) * 32;
    const int lr = lane >> 2, lc = lane & 3;
    const int g8 = lane >> 3, r8 = lane & 7;
    const int m0 = blockIdx.y * 128, n0 = blockIdx.x * 128;

    const uint32_t As_u = (uint32_t)__cvta_generic_to_shared(As);
    const uint32_t Bs_u = (uint32_t)__cvta_generic_to_shared(Bs);
    const uint32_t aoff = ((wm + (g8 & 1) * 8 + r8) * 36 + (g8 >> 1) * 4) * 4;
    const uint32_t boff = ((wn + (g8 >> 1) * 8 + r8) * 36 + (g8 & 1) * 4) * 4;

    float acc[4][4][4];
#pragma unroll
    for (int i = 0; i < 4; i++)
#pragma unroll
        for (int j = 0; j < 4; j++)
#pragma unroll
            for (int r = 0; r < 4; r++) acc[i][j][r] = 0.f;

    auto loadA = [&](int buf, int k0) {
        float* dst = As + buf * 4608;
#pragma unroll
        for (int i = 0; i < 4; i++) {
            const int c = tid + i * 256;
            const int r = c >> 3, cc = (c & 7) * 4;
            cp16(dst + r * 36 + cc, A + (size_t)(m0 + r) * H + k0 + cc);
        }
    };
    auto loadB = [&](int buf, int k0) {
        float* dst = Bs + buf * 4608;
#pragma unroll
        for (int i = 0; i < 4; i++) {
            const int c = tid + i * 256;
            const int r = c >> 3, cc = (c & 7) * 4;
            cp16(dst + r * 36 + cc, B + (size_t)(n0 + r) * H + k0 + cc);
        }
    };

    loadA(0, 0); loadB(0, 0); CP_COMMIT();
    for (int t = 0; t < 32; t++) {
        const int cur = t & 1;
        if (t + 1 < 32) {
            loadA(cur ^ 1, (t + 1) << 5);
            loadB(cur ^ 1, (t + 1) << 5);
            CP_COMMIT();
            CP_WAIT(1);
        } else {
            CP_WAIT(0);
        }
        __syncthreads();
        const uint32_t aB = As_u + cur * 4608 * 4;
        const uint32_t bB = Bs_u + cur * 4608 * 4;
#pragma unroll
        for (int kc = 0; kc < 4; kc++) {
            const uint32_t kk4 = kc * 32;
            uint32_t af[4][4], bf[4][2], bt[4];
#pragma unroll
            for (int mi = 0; mi < 4; mi++)
                ldm4(af[mi], aB + aoff + kk4 + mi * 16*36*4);
            ldm4(bt, bB + boff + kk4);
            bf[0][0]=bt[0]; bf[0][1]=bt[1]; bf[1][0]=bt[2]; bf[1][1]=bt[3];
            ldm4(bt, bB + boff + kk4 + 16*36*4);
            bf[2][0]=bt[0]; bf[2][1]=bt[1]; bf[3][0]=bt[2]; bf[3][1]=bt[3];
#pragma unroll
            for (int mi = 0; mi < 4; mi++)
#pragma unroll
                for (int ni = 0; ni < 4; ni++)
                    mma_tf32(acc[mi][ni], af[mi], bf[ni]);
        }
        __syncthreads();
    }

    // Stage the 128x128 tile in smem (stride 132), then write one contiguous
    // 64KB block: the n-tile covers exactly one (l, kvh) and the m-tile one bb.
#pragma unroll
    for (int mi = 0; mi < 4; mi++)
#pragma unroll
        for (int ni = 0; ni < 4; ni++)
#pragma unroll
            for (int hh = 0; hh < 2; hh++) {
                const int rr = wm + mi*16 + lr + hh*8;
                const int cc = wn + ni*8  + lc*2;
                sm[rr*132 + cc    ] = acc[mi][ni][hh*2+0];
                sm[rr*132 + cc + 1] = acc[mi][ni][hh*2+1];
            }
    __syncthreads();
    const int l = n0 >> 10, kvh = (n0 & 1023) >> 7;
    const int bb = m0 >> 8, q0 = m0 & 255;
    float* ob = Ob + ((((size_t)l * BATCH + bb) * 8 + kvh) * NQ + q0) * 128;
#pragma unroll
    for (int i = 0; i < 16; i++) {
        const int idx = tid + i * 256;            // 4096 float4 = full 128x128 tile
        const int q = idx >> 5, c4 = (idx & 31) * 4;
        const float4 v = *(const float4*)(sm + q*132 + c4);
        *(float4*)(ob + q*128 + c4) = v;
    }
}

// ---- split-K(2) reduce for w3 ----
__global__ void reduce_w3(const float* __restrict__ P, const float* __restrict__ R,
                          float* __restrict__ C, float* __restrict__ C2)
{
    const int i = blockIdx.x * 256 + threadIdx.x;   // float4 index
    const float4 a = ((const float4*)P)[i];
    const float4 b = ((const float4*)(P + M1*H))[i];
    const float4 r = ((const float4*)R)[i];
    float4 o;
    o.x = r.x + a.x + b.x;
    o.y = r.y + a.y + b.y;
    o.z = r.z + a.z + b.z;
    o.w = r.w + a.w + b.w;
    ((float4*)C2)[i] = o;
    float4 q; q.x = rtf(o.x); q.y = rtf(o.y); q.z = rtf(o.z); q.w = rtf(o.w);
    ((float4*)C)[i] = q;
}

// ---------------- dense self-attention (output rounded) ----------------
#define SATT_SMEM ((2*64*65 + 64*257) * (int)sizeof(float))
__global__ void self_attn_kernel(const float* __restrict__ Q, const float* __restrict__ K,
                                 const float* __restrict__ V, float* __restrict__ O)
{
    extern __shared__ float sm[];
    float* Qs = sm;
    float* Ks = sm + 64*65;
    float* S  = sm + 2*64*65;
    const int bh = blockIdx.y;
    const int b = bh >> 4, h = bh & 15;
    const int q0 = blockIdx.x * 64;
    const int tid = threadIdx.x;
    const size_t base = ((size_t)b * NQ) * H + h * HDIM;

    for (int idx = tid; idx < 64*64; idx += 256) {
        const int r = idx >> 6, d = idx & 63;
        Qs[r*65 + d] = Q[base + (size_t)(q0 + r) * H + d] * 0.125f;
    }
    const int q = tid >> 2, g4 = tid & 3;

    for (int t = 0; t < 4; t++) {
        __syncthreads();
        for (int idx = tid; idx < 64*64; idx += 256) {
            const int r = idx >> 6, d = idx & 63;
            Ks[r*65 + d] = K[base + (size_t)(t*64 + r) * H + d];
        }
        __syncthreads();
#pragma unroll
        for (int jj = 0; jj < 16; jj++) {
            const int j = g4 * 16 + jj;
            float s = 0.f;
#pragma unroll
            for (int d = 0; d < 64; d++) s += Qs[q*65 + d] * Ks[j*65 + d];
            S[q*257 + t*64 + j] = s;
        }
    }
    __syncthreads();

    float mx = -1e30f;
    for (int i = g4; i < 256; i += 4) mx = fmaxf(mx, S[q*257 + i]);
    mx = fmaxf(mx, __shfl_xor_sync(~0u, mx, 1));
    mx = fmaxf(mx, __shfl_xor_sync(~0u, mx, 2));
    float sum = 0.f;
    for (int i = g4; i < 256; i += 4) { const float e = __expf(S[q*257 + i] - mx); S[q*257 + i] = e; sum += e; }
    sum += __shfl_xor_sync(~0u, sum, 1);
    sum += __shfl_xor_sync(~0u, sum, 2);
    const float inv = 1.f / sum;

    float acc[16];
#pragma unroll
    for (int i = 0; i < 16; i++) acc[i] = 0.f;

    for (int t = 0; t < 4; t++) {
        __syncthreads();
        for (int idx = tid; idx < 64*64; idx += 256) {
            const int r = idx >> 6, d = idx & 63;
            Ks[r*65 + d] = V[base + (size_t)(t*64 + r) * H + d];
        }
        __syncthreads();
        for (int j = 0; j < 64; j++) {
            const float p = S[q*257 + t*64 + j];
#pragma unroll
            for (int i = 0; i < 16; i++) acc[i] += p * Ks[j*65 + g4*16 + i];
        }
    }
#pragma unroll
    for (int i = 0; i < 16; i++)
        O[base + (size_t)(q0 + q) * H + g4*16 + i] = rtf(acc[i] * inv);
}

// ---------------- fused windowed cross-attention core (bf16 staging, 2 blocks/SM) ----------------
#define SCORE_SMEM (36*1024*2 + 2*1024*4)
__global__ void __launch_bounds__(512) cross_score_kernel(
    const __nv_bfloat16* __restrict__ qk, const float* __restrict__ hs,
    const float* __restrict__ g, const float* __restrict__ b,
    float* __restrict__ hbar)
{
    extern __shared__ char smraw[];
    __nv_bfloat16* srows = (__nv_bfloat16*)smraw;        // [36][1024] bf16
    float* sg = (float*)(smraw + 36*1024*2);             // [1024]
    float* sb = sg + 1024;
    __shared__ float sc[16*40];
    __shared__ float smu[36], srs[36];
    __shared__ int spos[36];

    const int row = blockIdx.x;      // b*256 + q
    const int bb = row >> 8, q = row & 255;
    const int tid = threadIdx.x;
    const int base = q * 8;
    const int nj = (base + 9 <= DOC) ? 9 : (DOC - base);
    const int nkv = LAYERS * nj;

    for (int i = tid; i < 1024; i += 512) { sg[i] = g[i]; sb[i] = b[i]; }
    if (tid < nkv) { const int l = tid / nj, jj = tid - l * nj; spos[tid] = l * DOC + base + jj; }
    __syncthreads();

    for (int idx = tid; idx < nkv * 256; idx += 512) {
        const int j = idx >> 8, c4 = (idx & 255) << 2;
        const int gr = bb * KVLEN + spos[j];
        const float4 v = *(const float4*)(hs + (size_t)gr * H + c4);
        __nv_bfloat162* d = (__nv_bfloat162*)(srows + (j << 10) + c4);
        d[0] = __floats2bfloat162_rn(v.x, v.y);
        d[1] = __floats2bfloat162_rn(v.z, v.w);
    }
    __syncthreads();

    const int w = tid >> 5, lane = tid & 31;
    for (int j = w; j < nkv; j += 16) {
        const __nv_bfloat162* r2 = (const __nv_bfloat162*)(srows + (j << 10));
        float s = 0.f, s2 = 0.f;
#pragma unroll
        for (int i = 0; i < 16; i++) {
            const float2 v = __bfloat1622float2(r2[lane + 32*i]);
            s += v.x + v.y; s2 += v.x*v.x + v.y*v.y;
        }
#pragma unroll
        for (int o = 16; o > 0; o >>= 1) { s += __shfl_xor_sync(~0u, s, o); s2 += __shfl_xor_sync(~0u, s2, o); }
        if (lane == 0) {
            const float mu = s * (1.f / H);
            smu[j] = mu;
            srs[j] = rsqrtf(s2 * (1.f / H) - mu * mu + 1e-5f);
        }
    }
    __syncthreads();

    for (int idx = tid; idx < nkv * 512; idx += 512) {
        const int j = idx >> 9, p = idx & 511;
        const float mu = smu[j], rs = srs[j];
        __nv_bfloat162* d = (__nv_bfloat162*)(srows + (j << 10)) + p;
        float2 v = __bfloat1622float2(*d);
        v.x = (v.x - mu) * rs * sg[2*p  ] + sb[2*p  ];
        v.y = (v.y - mu) * rs * sg[2*p+1] + sb[2*p+1];
        *d = __floats2bfloat162_rn(v.x, v.y);
    }
    __syncthreads();

    float2 qv[16];
    const __nv_bfloat162* qrow2 = (const __nv_bfloat162*)(qk + ((size_t)w * M1 + row) * H);
#pragma unroll
    for (int i = 0; i < 16; i++) qv[i] = __bfloat1622float2(qrow2[lane + 32*i]);
    for (int j = 0; j < nkv; j++) {
        const __nv_bfloat162* r2 = (const __nv_bfloat162*)(srows + (j << 10));
        float s = 0.f;
#pragma unroll
        for (int i = 0; i < 16; i++) {
            const float2 v = __bfloat1622float2(r2[lane + 32*i]);
            s += qv[i].x * v.x + qv[i].y * v.y;
        }
#pragma unroll
        for (int o = 16; o > 0; o >>= 1) s += __shfl_xor_sync(~0u, s, o);
        if (lane == 0) sc[w*40 + j] = s * 0.125f;
    }
    __syncthreads();

    {
        float v0 = (lane      < nkv) ? sc[w*40 + lane     ] : -1e30f;
        float v1 = (lane + 32 < nkv) ? sc[w*40 + lane + 32] : -1e30f;
        float m = fmaxf(v0, v1);
#pragma unroll
        for (int o = 16; o > 0; o >>= 1) m = fmaxf(m, __shfl_xor_sync(~0u, m, o));
        float e0 = (lane      < nkv) ? __expf(v0 - m) : 0.f;
        float e1 = (lane + 32 < nkv) ? __expf(v1 - m) : 0.f;
        float su = e0 + e1;
#pragma unroll
        for (int o = 16; o > 0; o >>= 1) su += __shfl_xor_sync(~0u, su, o);
        const float inv = 1.f / su;
        if (lane      < nkv) sc[w*40 + lane     ] = e0 * inv;
        if (lane + 32 < nkv) sc[w*40 + lane + 32] = e1 * inv;
    }
    __syncthreads();

    float acc[16][2];
#pragma unroll
    for (int h = 0; h < 16; h++) { acc[h][0] = 0.f; acc[h][1] = 0.f; }
    for (int j = 0; j < nkv; j++) {
        const float2 v = __bfloat1622float2(((const __nv_bfloat162*)(srows + (j << 10)))[tid]);
#pragma unroll
        for (int h = 0; h < 16; h++) {
            const float p = sc[h*40 + j];
            acc[h][0] += p * v.x;
            acc[h][1] += p * v.y;
        }
    }
    const int c0 = tid * 2;
#pragma unroll
    for (int h = 0; h < 16; h++)
        *(float2*)(hbar + ((size_t)h * M1 + row) * H + c0) =
            make_float2(rtf(acc[h][0]), rtf(acc[h][1]));
}

// ---------------- launch ----------------
extern "C" void kernel_launch(void* const* d_in, const int* in_sizes, int n_in,
                              void* d_out_, int out_size)
{
    (void)in_sizes; (void)n_in; (void)out_size;
    const float* qtok = (const float*)d_in[0];
    const float* hs   = (const float*)d_in[1];
    const float* ln1g = (const float*)d_in[2];
    const float* ln1b = (const float*)d_in[3];
    const float* ln2g = (const float*)d_in[4];
    const float* ln2b = (const float*)d_in[5];
    const float* lnkvg= (const float*)d_in[6];
    const float* lnkvb= (const float*)d_in[7];
    const float* lnfg = (const float*)d_in[8];
    const float* lnfb = (const float*)d_in[9];
    const float* wqs  = (const float*)d_in[10];
    const float* wks  = (const float*)d_in[11];
    const float* wvs  = (const float*)d_in[12];
    const float* wos  = (const float*)d_in[13];
    const float* wqc  = (const float*)d_in[14];
    const float* wkc  = (const float*)d_in[15];
    const float* wvc  = (const float*)d_in[16];
    const float* woc  = (const float*)d_in[17];
    const float* w1   = (const float*)d_in[18];
    const float* w2   = (const float*)d_in[19];
    const float* w3   = (const float*)d_in[20];
    const float* okw  = (const float*)d_in[21];
    const float* ovw  = (const float*)d_in[22];
    float* out = (float*)d_out_;

    void* p;
    cudaGetSymbolAddress(&p, g_xln);  float* xln  = (float*)p;
    cudaGetSymbolAddress(&p, g_qkv);  float* qkv  = (float*)p;
    cudaGetSymbolAddress(&p, g_attn); float* ab   = (float*)p;
    cudaGetSymbolAddress(&p, g_qt1);  float* qt1  = (float*)p;
    cudaGetSymbolAddress(&p, g_qt2);  float* qt2  = (float*)p;
    cudaGetSymbolAddress(&p, g_h1);   float* h1   = (float*)p;
    cudaGetSymbolAddress(&p, g_qk);   float* qk   = (float*)p;
    cudaGetSymbolAddress(&p, g_hbar); float* hbar = (float*)p;

    constexpr int S_64_128  = smem_g2(64, 128, 1, 32);   // 82,944 B
    constexpr int S_64_64   = smem_g2(64, 64, 1, 32);    // 55,296 B
    constexpr int S_128_64n = smem_g2(128, 64, 0, 32);   // 82,944 B
    constexpr int S_QKV     = (3*128*36 + 3*2304) * 4;

    cudaFuncSetAttribute(self_attn_kernel,   cudaFuncAttributeMaxDynamicSharedMemorySize, SATT_SMEM);
    cudaFuncSetAttribute(cross_score_kernel, cudaFuncAttributeMaxDynamicSharedMemorySize, SCORE_SMEM);
    cudaFuncSetAttribute(gemm2<1,64,128,32>, cudaFuncAttributeMaxDynamicSharedMemorySize, S_64_128);
    cudaFuncSetAttribute(gemm2<1,64,64,32>,  cudaFuncAttributeMaxDynamicSharedMemorySize, S_64_64);
    cudaFuncSetAttribute(gemm2<0,128,64,32>, cudaFuncAttributeMaxDynamicSharedMemorySize, S_128_64n);
    cudaFuncSetAttribute(gemm_qkv,           cudaFuncAttributeMaxDynamicSharedMemorySize, S_QKV);
    cudaFuncSetAttribute(gemm_okv,           cudaFuncAttributeMaxDynamicSharedMemorySize, OKV_SMEM);
    cudaFuncSetAttribute(gemm_ffn,           cudaFuncAttributeMaxDynamicSharedMemorySize, FFN_SMEM);

    float* qb = qkv;
    float* kb = qkv + M1*H;
    float* vb = qkv + 2*M1*H;

    const dim3 gHH (H/128, M1/64, 1);       // 128 CTAs (single wave)
    const dim3 gQKV(H/64, M1/128, 3);       // 384
    const dim3 gFFN(FFN_D/64, M1/128, 1);   // 512
    const dim3 gQK (H/64, M1/128, NHEADS);  // 2048
    const dim3 gVP (1, M1/64, NHEADS);      // 256
    const dim3 gOKV(4096/128, M1/128, 2);   // 512
    const dim3 gW3 (H/128, M1/64, 2);       // 256, split-K=2

    // 1) self-attention block
    ln_kernel<<<M1, 256>>>(qtok, ln1g, ln1b, xln);
    gemm_qkv<<<gQKV, 256, S_QKV>>>(xln, wqs, wks, wvs, qkv);
    self_attn_kernel<<<dim3(4, 64), 256, SATT_SMEM>>>(qb, kb, vb, ab);
    gemm2<1,64,128,32><<<gHH, 256, S_64_128>>>(ab, H, 0, wos, H, 0, qt1, H, 0, qtok, nullptr, H, 1);

    // 2) windowed cross-attention (factorized; qk intermediate in bf16)
    ln_kernel<<<M1, 256>>>(qt1, ln2g, ln2b, xln);
    gemm2<1,64,128,32><<<gHH, 256, S_64_128>>>(xln, H, 0, wqc, H, 0, qb, H, 0, nullptr, nullptr, H, 0);
    gemm2<0,128,64,32><<<gQK, 256, S_128_64n>>>(qb, H, 64, wkc, H, (long)64*H,
                                                qk, H, (long)M1*H/2, nullptr, nullptr, 64, 4);
    cross_score_kernel<<<M1, 512, SCORE_SMEM>>>((const __nv_bfloat16*)qk, hs, lnkvg, lnkvb, hbar);
    gemm2<1,64,64,32><<<gVP, 256, S_64_64>>>(hbar, H, (long)M1*H, wvc, H, (long)64*H,
                                             ab, H, 64, nullptr, nullptr, H, 0);
    gemm2<1,64,128,32><<<gHH, 256, S_64_128>>>(ab, H, 0, woc, H, 0, qt2, H, 0, qt1, nullptr, H, 1);

    // 3) SwiGLU FFN (fused w1/w2 + silu; w3 via split-K=2 + reduce)
    ln_kernel<<<M1, 256>>>(qt2, lnfg, lnfb, xln);
    gemm_ffn<<<gFFN, 256, FFN_SMEM>>>(xln, w1, w2, h1);
    gemm2<1,64,128,32><<<gW3, 256, S_64_128>>>(h1, FFN_D, 2048, w3, FFN_D, 2048,
                                               qk, H, (long)M1*H, nullptr, nullptr, 2048, 3);
    reduce_w3<<<M1*H/1024, 256>>>(qk, qt2, qt1, out);

    // 4) per-layer K/V output projections (batched, 128x128, staged epilogue)
    gemm_okv<<<gOKV, 256, OKV_SMEM>>>(qt1, okw, ovw, out + (size_t)M1*H);
}

// round 14
// speedup vs baseline: 1.1004x; 1.1004x over previous
#include <cuda_runtime.h>
#include <cuda_bf16.h>
#include <cuda_fp16.h>
#include <cstdint>

#define H      1024
#define NHEADS 16
#define HDIM   64
#define NQ     256
#define BATCH  4
#define LAYERS 4
#define DOC    2048
#define KVLEN  8192
#define FFN_D  4096
#define M1     (BATCH*NQ)      /* 1024  */
#define MH     (BATCH*KVLEN)   /* 32768 */

// ---------------- device scratch ----------------
__device__ float  g_xln [M1*H];
__device__ float  g_qkv [3*M1*H];
__device__ float  g_attn[M1*H];
__device__ float  g_qt1 [M1*H];
__device__ float  g_qt2 [M1*H];
__device__ float  g_qk  [(size_t)NHEADS*M1*H];   // bf16 qk (low half); later w3 split-K float partials
__device__ float  g_hbar[(size_t)NHEADS*M1*H];
__device__ __half g_w1h [(size_t)FFN_D*H];
__device__ __half g_w2h [(size_t)FFN_D*H];
__device__ __half g_w3h [(size_t)H*FFN_D];
__device__ __half g_okwh[(size_t)LAYERS*H*H];
__device__ __half g_ovwh[(size_t)LAYERS*H*H];
__device__ __half g_xlnh[M1*H];
__device__ __half g_h1h [(size_t)M1*FFN_D];
__device__ __half g_qt1h[M1*H];

// ---------------- helpers ----------------
__device__ __forceinline__ uint32_t f2tf32(float x) {
    uint32_t r;
    asm("cvt.rna.tf32.f32 %0, %1;" : "=r"(r) : "f"(x));
    return r;
}
__device__ __forceinline__ float rtf(float x) { return __uint_as_float(f2tf32(x)); }

__device__ __forceinline__ void mma_tf32(float c[4], const uint32_t a[4], const uint32_t b[2]) {
    asm volatile(
        "mma.sync.aligned.m16n8k8.row.col.f32.tf32.tf32.f32 "
        "{%0,%1,%2,%3}, {%4,%5,%6,%7}, {%8,%9}, {%0,%1,%2,%3};\n"
        : "+f"(c[0]), "+f"(c[1]), "+f"(c[2]), "+f"(c[3])
        : "r"(a[0]), "r"(a[1]), "r"(a[2]), "r"(a[3]), "r"(b[0]), "r"(b[1]));
}
__device__ __forceinline__ void mma_f16(float c[4], const uint32_t a[4], const uint32_t b[2]) {
    asm volatile(
        "mma.sync.aligned.m16n8k16.row.col.f32.f16.f16.f32 "
        "{%0,%1,%2,%3}, {%4,%5,%6,%7}, {%8,%9}, {%0,%1,%2,%3};\n"
        : "+f"(c[0]), "+f"(c[1]), "+f"(c[2]), "+f"(c[3])
        : "r"(a[0]), "r"(a[1]), "r"(a[2]), "r"(a[3]), "r"(b[0]), "r"(b[1]));
}
__device__ __forceinline__ void ldm4(uint32_t a[4], uint32_t addr) {
    asm volatile("ldmatrix.sync.aligned.m8n8.x4.shared.b16 {%0,%1,%2,%3}, [%4];\n"
                 : "=r"(a[0]), "=r"(a[1]), "=r"(a[2]), "=r"(a[3]) : "r"(addr));
}
__device__ __forceinline__ void cp16(float* s, const float* g) {
    uint32_t sa = (uint32_t)__cvta_generic_to_shared(s);
    asm volatile("cp.async.cg.shared.global [%0], [%1], 16;\n" :: "r"(sa), "l"(g));
}
__device__ __forceinline__ void cp16h(__half* s, const __half* g) {
    uint32_t sa = (uint32_t)__cvta_generic_to_shared(s);
    asm volatile("cp.async.cg.shared.global [%0], [%1], 16;\n" :: "r"(sa), "l"(g));
}
#define CP_COMMIT() asm volatile("cp.async.commit_group;\n")
#define CP_WAIT(n)  asm volatile("cp.async.wait_group %0;\n" :: "n"(n))

// ---------------- weight fp32 -> fp16 conversion ----------------
__global__ void convert_h(const float* __restrict__ s, __half* __restrict__ d, int n4)
{
    const int i = blockIdx.x * 256 + threadIdx.x;
    if (i < n4) {
        const float4 v = ((const float4*)s)[i];
        __half2* d2 = (__half2*)d;
        d2[2*i    ] = __floats2half2_rn(v.x, v.y);
        d2[2*i + 1] = __floats2half2_rn(v.z, v.w);
    }
}

// ---------------- LayerNorm (fp32-out, tf32-rounded) ----------------
__global__ void ln_kernel(const float* __restrict__ x, const float* __restrict__ g,
                          const float* __restrict__ b, float* __restrict__ y)
{
    __shared__ float red[16];
    const int row = blockIdx.x, tid = threadIdx.x;
    const float* xr = x + (size_t)row * H;
    float v[4]; float s = 0.f, s2 = 0.f;
#pragma unroll
    for (int i = 0; i < 4; i++) { v[i] = xr[tid + i*256]; s += v[i]; s2 += v[i]*v[i]; }
#pragma unroll
    for (int o = 16; o > 0; o >>= 1) { s += __shfl_xor_sync(~0u, s, o); s2 += __shfl_xor_sync(~0u, s2, o); }
    if ((tid & 31) == 0) { red[tid>>5] = s; red[8 + (tid>>5)] = s2; }
    __syncthreads();
    if (tid < 32) {
        s  = (tid < 8) ? red[tid]     : 0.f;
        s2 = (tid < 8) ? red[8 + tid] : 0.f;
#pragma unroll
        for (int o = 4; o > 0; o >>= 1) { s += __shfl_xor_sync(~0u, s, o); s2 += __shfl_xor_sync(~0u, s2, o); }
        if (tid == 0) { red[0] = s; red[1] = s2; }
    }
    __syncthreads();
    const float mu  = red[0] * (1.f / H);
    const float var = red[1] * (1.f / H) - mu * mu;
    const float rs  = rsqrtf(var + 1e-5f);
    float* yr = y + (size_t)row * H;
#pragma unroll
    for (int i = 0; i < 4; i++) { int c = tid + i*256; yr[c] = rtf((v[i] - mu) * rs * g[c] + b[c]); }
}

// ---------------- LayerNorm with fp16 output (feeds fp16 FFN) ----------------
__global__ void ln_kernel_h(const float* __restrict__ x, const float* __restrict__ g,
                            const float* __restrict__ b, __half* __restrict__ y)
{
    __shared__ float red[16];
    const int row = blockIdx.x, tid = threadIdx.x;
    const float* xr = x + (size_t)row * H;
    float v[4]; float s = 0.f, s2 = 0.f;
#pragma unroll
    for (int i = 0; i < 4; i++) { v[i] = xr[tid + i*256]; s += v[i]; s2 += v[i]*v[i]; }
#pragma unroll
    for (int o = 16; o > 0; o >>= 1) { s += __shfl_xor_sync(~0u, s, o); s2 += __shfl_xor_sync(~0u, s2, o); }
    if ((tid & 31) == 0) { red[tid>>5] = s; red[8 + (tid>>5)] = s2; }
    __syncthreads();
    if (tid < 32) {
        s  = (tid < 8) ? red[tid]     : 0.f;
        s2 = (tid < 8) ? red[8 + tid] : 0.f;
#pragma unroll
        for (int o = 4; o > 0; o >>= 1) { s += __shfl_xor_sync(~0u, s, o); s2 += __shfl_xor_sync(~0u, s2, o); }
        if (tid == 0) { red[0] = s; red[1] = s2; }
    }
    __syncthreads();
    const float mu  = red[0] * (1.f / H);
    const float var = red[1] * (1.f / H) - mu * mu;
    const float rs  = rsqrtf(var + 1e-5f);
    __half* yr = y + (size_t)row * H;
#pragma unroll
    for (int i = 0; i < 4; i++) { int c = tid + i*256; yr[c] = __float2half_rn((v[i] - mu) * rs * g[c] + b[c]); }
}

// ================= tf32 GEMM (unchanged, validated) =================
constexpr int smem_g2(int BM, int BN, int BT, int BK) {
    return (3*BM*(BK+4) + (BT ? 3*BN*(BK+4) : 3*32*(BN+8))) * 4;
}

template<int BT, int BM, int BN, int BK>
__global__ void __launch_bounds__(256) gemm2(
    const float* __restrict__ A, int lda, long Az,
    const float* __restrict__ B, int ldb, long Bz,
    float* __restrict__ C, int ldc, long Cz,
    const float* __restrict__ R, float* __restrict__ C2,
    int K, int epi)
{
    extern __shared__ float sm[];
    constexpr int RS  = BK + 4;
    constexpr int ASZ = BM * RS;
    constexpr int BSZ = BT ? BN * RS : 32*(BN+8);
    constexpr int MI = BM / 32;
    constexpr int NI = BN / 32;
    constexpr int KCN = BK / 8;
    constexpr int TPR = BK / 4;
    float* As = sm;
    float* Bs = sm + 3*ASZ;

    const int tid  = threadIdx.x;
    const int lane = tid & 31, warp = tid >> 5;
    const int wm = (warp & 1) * (BM/2);
    const int wn = (warp >> 1) * (BN/4);
    const int lr = lane >> 2, lc = lane & 3;
    const int g8 = lane >> 3, r8 = lane & 7;
    const int m0 = blockIdx.y * BM, n0 = blockIdx.x * BN;
    const float* Ab = A + (size_t)blockIdx.z * Az;
    const float* Bb = B + (size_t)blockIdx.z * Bz;
    float*       Cb = C + (size_t)blockIdx.z * Cz;

    const uint32_t As_u = (uint32_t)__cvta_generic_to_shared(As);
    const uint32_t Bs_u = (uint32_t)__cvta_generic_to_shared(Bs);
    const uint32_t aoff = ((wm + (g8 & 1) * 8 + r8) * RS + (g8 >> 1) * 4) * 4;
    const uint32_t boff = ((wn + (g8 >> 1) * 8 + r8) * RS + (g8 & 1) * 4) * 4;

    float acc[MI][NI][4];
#pragma unroll
    for (int i = 0; i < MI; i++)
#pragma unroll
        for (int j = 0; j < NI; j++)
#pragma unroll
            for (int r = 0; r < 4; r++) acc[i][j][r] = 0.f;

    auto loadA = [&](int buf, int k0) {
        float* dst = As + buf * ASZ;
#pragma unroll
        for (int i = 0; i < BM*BK/1024; i++) {
            const int c = tid + i * 256;
            const int r = c / TPR, cc = (c % TPR) * 4;
            cp16(dst + r * RS + cc, Ab + (size_t)(m0 + r) * lda + k0 + cc);
        }
    };
    auto loadB = [&](int buf, int k0) {
        float* dst = Bs + buf * BSZ;
        if (BT) {
#pragma unroll
            for (int i = 0; i < BN*BK/1024; i++) {
                const int c = tid + i * 256;
                const int r = c / TPR, cc = (c % TPR) * 4;
                cp16(dst + r * RS + cc, Bb + (size_t)(n0 + r) * ldb + k0 + cc);
            }
        } else {
#pragma unroll
            for (int i = 0; i < BN/32; i++) {
                const int c = tid + i * 256;
                const int r = c / (BN/4), cc = (c % (BN/4)) * 4;
                cp16(dst + r * (BN+8) + cc, Bb + (size_t)(k0 + r) * ldb + n0 + cc);
            }
        }
    };

    const int ntiles = K / BK;
    loadA(0, 0); loadB(0, 0); CP_COMMIT();
    if (ntiles > 1) { loadA(1, BK); loadB(1, BK); CP_COMMIT(); }

    for (int t = 0; t < ntiles; t++) {
        const int cur = t % 3;
        if (t < ntiles - 1) CP_WAIT(1); else CP_WAIT(0);
        __syncthreads();
        if (t + 2 < ntiles) {
            const int s = (t + 2) % 3;
            loadA(s, (t + 2) * BK);
            loadB(s, (t + 2) * BK);
            CP_COMMIT();
        }
        const uint32_t aB = As_u + cur * ASZ * 4;
        const uint32_t bB = Bs_u + cur * BSZ * 4;
        const float* Bsb = Bs + cur * BSZ;
#pragma unroll
        for (int kc = 0; kc < KCN; kc++) {
            const uint32_t kk4 = kc * 32;
            uint32_t af[MI][4], bf[NI][2];
#pragma unroll
            for (int mi = 0; mi < MI; mi++)
                ldm4(af[mi], aB + aoff + kk4 + mi * 16*RS*4);
            if (BT) {
#pragma unroll
                for (int p = 0; p < NI/2; p++) {
                    uint32_t bt[4];
                    ldm4(bt, bB + boff + kk4 + p * 16*RS*4);
                    bf[2*p  ][0] = bt[0]; bf[2*p  ][1] = bt[1];
                    bf[2*p+1][0] = bt[2]; bf[2*p+1][1] = bt[3];
                }
            } else {
                const int kk = kc * 8;
#pragma unroll
                for (int ni = 0; ni < NI; ni++) {
                    const int nb = wn + ni * 8;
                    bf[ni][0] = __float_as_uint(Bsb[(kk + lc    ) * (BN+8) + nb + lr]);
                    bf[ni][1] = __float_as_uint(Bsb[(kk + lc + 4) * (BN+8) + nb + lr]);
                }
            }
#pragma unroll
            for (int mi = 0; mi < MI; mi++)
#pragma unroll
                for (int ni = 0; ni < NI; ni++)
                    mma_tf32(acc[mi][ni], af[mi], bf[ni]);
        }
    }
    __syncthreads();

#pragma unroll
    for (int mi = 0; mi < MI; mi++)
#pragma unroll
        for (int ni = 0; ni < NI; ni++)
#pragma unroll
            for (int hh = 0; hh < 2; hh++) {
                const int row = m0 + wm + mi*16 + lr + hh*8;
                const int col = n0 + wn + ni*8  + lc*2;
                const float v0 = acc[mi][ni][hh*2+0];
                const float v1 = acc[mi][ni][hh*2+1];
                if (epi == 0) {
                    *(float2*)(Cb + (size_t)row * ldc + col) = make_float2(rtf(v0), rtf(v1));
                } else if (epi == 3) {
                    *(float2*)(Cb + (size_t)row * ldc + col) = make_float2(v0, v1);
                } else if (epi == 4) {
                    __nv_bfloat16* Ch = (__nv_bfloat16*)Cb;
                    *(__nv_bfloat162*)(Ch + (size_t)row * ldc + col) = __floats2bfloat162_rn(v0, v1);
                } else {
                    const size_t o = (size_t)row * ldc + col;
                    const float r0 = R[o] + v0, r1 = R[o+1] + v1;
                    *(float2*)(Cb + o) = make_float2(r0, r1);
                    if (C2) *(float2*)(C2 + o) = make_float2(r0, r1);
                }
            }
}

// ---- batched QKV (tf32, validated, unchanged) ----
__global__ void __launch_bounds__(256) gemm_qkv(
    const float* __restrict__ A,
    const float* __restrict__ B0, const float* __restrict__ B1, const float* __restrict__ B2,
    float* __restrict__ C)
{
    extern __shared__ float sm[];
    float* As = sm;
    float* Bs = sm + 3*128*36;
    const int z = blockIdx.z;
    const float* B = (z == 0) ? B0 : (z == 1) ? B1 : B2;
    float* Cb = C + (size_t)z * M1 * H;

    const int tid  = threadIdx.x;
    const int lane = tid & 31, warp = tid >> 5;
    const int wm = (warp & 3) * 32, wn = (warp >> 2) * 32;
    const int lr = lane >> 2, lc = lane & 3;
    const int g8 = lane >> 3, r8 = lane & 7;
    const int m0 = blockIdx.y * 128, n0 = blockIdx.x * 64;

    const uint32_t As_u = (uint32_t)__cvta_generic_to_shared(As);
    const uint32_t Bs_u = (uint32_t)__cvta_generic_to_shared(Bs);
    const uint32_t aoff = ((wm + (g8 & 1) * 8 + r8) * 36 + (g8 >> 1) * 4) * 4;
    const uint32_t boff = ((wn + (g8 >> 1) * 8 + r8) * 36 + (g8 & 1) * 4) * 4;

    float acc[2][4][4];
#pragma unroll
    for (int i = 0; i < 2; i++)
#pragma unroll
        for (int j = 0; j < 4; j++)
#pragma unroll
            for (int r = 0; r < 4; r++) acc[i][j][r] = 0.f;

    auto loadA = [&](int buf, int k0) {
        float* dst = As + buf * 4608;
#pragma unroll
        for (int i = 0; i < 4; i++) {
            const int c = tid + i * 256;
            const int r = c >> 3, cc = (c & 7) * 4;
            cp16(dst + r * 36 + cc, A + (size_t)(m0 + r) * H + k0 + cc);
        }
    };
    auto loadB = [&](int buf, int k0) {
        float* dst = Bs + buf * 2304;
#pragma unroll
        for (int i = 0; i < 2; i++) {
            const int c = tid + i * 256;
            const int r = c >> 3, cc = (c & 7) * 4;
            cp16(dst + r * 36 + cc, B + (size_t)(n0 + r) * H + k0 + cc);
        }
    };

    loadA(0, 0); loadB(0, 0); CP_COMMIT();
    loadA(1, 32); loadB(1, 32); CP_COMMIT();
    for (int t = 0; t < 32; t++) {
        const int cur = t % 3;
        if (t < 31) CP_WAIT(1); else CP_WAIT(0);
        __syncthreads();
        if (t + 2 < 32) {
            const int s = (t + 2) % 3;
            loadA(s, (t + 2) << 5); loadB(s, (t + 2) << 5); CP_COMMIT();
        }
        const uint32_t aB = As_u + cur * 4608 * 4;
        const uint32_t bB = Bs_u + cur * 2304 * 4;
#pragma unroll
        for (int kc = 0; kc < 4; kc++) {
            const uint32_t kk4 = kc * 32;
            uint32_t af[2][4], bf[4][2], bt[4];
            ldm4(af[0], aB + aoff + kk4);
            ldm4(af[1], aB + aoff + kk4 + 16*36*4);
            ldm4(bt, bB + boff + kk4);
            bf[0][0] = bt[0]; bf[0][1] = bt[1]; bf[1][0] = bt[2]; bf[1][1] = bt[3];
            ldm4(bt, bB + boff + kk4 + 16*36*4);
            bf[2][0] = bt[0]; bf[2][1] = bt[1]; bf[3][0] = bt[2]; bf[3][1] = bt[3];
#pragma unroll
            for (int mi = 0; mi < 2; mi++)
#pragma unroll
                for (int ni = 0; ni < 4; ni++)
                    mma_tf32(acc[mi][ni], af[mi], bf[ni]);
        }
    }
    __syncthreads();
#pragma unroll
    for (int mi = 0; mi < 2; mi++)
#pragma unroll
        for (int ni = 0; ni < 4; ni++)
#pragma unroll
            for (int hh = 0; hh < 2; hh++) {
                const int row = m0 + wm + mi*16 + lr + hh*8;
                const int col = n0 + wn + ni*8  + lc*2;
                *(float2*)(Cb + (size_t)row * H + col) =
                    make_float2(acc[mi][ni][hh*2], acc[mi][ni][hh*2+1]);
            }
}

// ================= fp16 GEMM cores (m16n8k16, 2-stage, RS=40 halfs) =================
// Fragment map: A tiles (row-group g8&1, k-half g8>>1); B tiles (n-group g8>>1, k-half g8&1).
// Accumulator layout identical to m16n8k8 — epilogues unchanged.

// ---- fused FFN fp16: C = silu(A@W1^T) * (A@W2^T), half output ----
#define FFNH_SMEM ((2*128*40 + 2*64*40 + 2*64*40) * 2)
__global__ void __launch_bounds__(256) gemm_ffn_h(
    const __half* __restrict__ A, const __half* __restrict__ W1, const __half* __restrict__ W2,
    __half* __restrict__ C)
{
    extern __shared__ __half smh[];
    __half* As  = smh;                 // 2 x 128*40
    __half* Bs1 = smh + 2*5120;        // 2 x 64*40
    __half* Bs2 = Bs1 + 2*2560;

    const int tid  = threadIdx.x;
    const int lane = tid & 31, warp = tid >> 5;
    const int wm = (warp & 3) * 32, wn = (warp >> 2) * 32;
    const int lr = lane >> 2, lc = lane & 3;
    const int g8 = lane >> 3, r8 = lane & 7;
    const int m0 = blockIdx.y * 128, n0 = blockIdx.x * 64;

    const uint32_t As_u  = (uint32_t)__cvta_generic_to_shared(As);
    const uint32_t Bs1_u = (uint32_t)__cvta_generic_to_shared(Bs1);
    const uint32_t Bs2_u = (uint32_t)__cvta_generic_to_shared(Bs2);
    const uint32_t aoff = ((wm + (g8 & 1) * 8 + r8) * 40 + (g8 >> 1) * 8) * 2;
    const uint32_t boff = ((wn + (g8 >> 1) * 8 + r8) * 40 + (g8 & 1) * 8) * 2;

    float a1[2][4][4], a2[2][4][4];
#pragma unroll
    for (int i = 0; i < 2; i++)
#pragma unroll
        for (int j = 0; j < 4; j++)
#pragma unroll
            for (int r = 0; r < 4; r++) { a1[i][j][r] = 0.f; a2[i][j][r] = 0.f; }

    auto loadA = [&](int buf, int k0) {
        __half* dst = As + buf * 5120;
#pragma unroll
        for (int i = 0; i < 2; i++) {                // 128 rows * 4 cp16 = 512
            const int c = tid + i * 256;
            const int r = c >> 2, c16 = c & 3;
            cp16h(dst + r * 40 + c16 * 8, A + (size_t)(m0 + r) * H + k0 + c16 * 8);
        }
    };
    auto loadB = [&](int buf, int k0) {
        const int r = tid >> 2, c16 = tid & 3;       // 64 rows * 4 = 256
        cp16h(Bs1 + buf * 2560 + r * 40 + c16 * 8, W1 + (size_t)(n0 + r) * H + k0 + c16 * 8);
        cp16h(Bs2 + buf * 2560 + r * 40 + c16 * 8, W2 + (size_t)(n0 + r) * H + k0 + c16 * 8);
    };

    loadA(0, 0); loadB(0, 0); CP_COMMIT();
    for (int t = 0; t < 32; t++) {
        const int cur = t & 1;
        if (t + 1 < 32) {
            loadA(cur ^ 1, (t + 1) << 5);
            loadB(cur ^ 1, (t + 1) << 5);
            CP_COMMIT();
            CP_WAIT(1);
        } else {
            CP_WAIT(0);
        }
        __syncthreads();
        const uint32_t aB  = As_u  + cur * 5120 * 2;
        const uint32_t b1B = Bs1_u + cur * 2560 * 2;
        const uint32_t b2B = Bs2_u + cur * 2560 * 2;
#pragma unroll
        for (int kc = 0; kc < 2; kc++) {
            const uint32_t kk = kc * 32;             // 16 halfs in bytes
            uint32_t af[2][4], b1f[4][2], b2f[4][2], bt[4];
            ldm4(af[0], aB + aoff + kk);
            ldm4(af[1], aB + aoff + kk + 16*40*2);
#pragma unroll
            for (int p = 0; p < 2; p++) {
                ldm4(bt, b1B + boff + kk + p * 16*40*2);
                b1f[2*p][0]=bt[0]; b1f[2*p][1]=bt[1]; b1f[2*p+1][0]=bt[2]; b1f[2*p+1][1]=bt[3];
                ldm4(bt, b2B + boff + kk + p * 16*40*2);
                b2f[2*p][0]=bt[0]; b2f[2*p][1]=bt[1]; b2f[2*p+1][0]=bt[2]; b2f[2*p+1][1]=bt[3];
            }
#pragma unroll
            for (int mi = 0; mi < 2; mi++)
#pragma unroll
                for (int ni = 0; ni < 4; ni++) {
                    mma_f16(a1[mi][ni], af[mi], b1f[ni]);
                    mma_f16(a2[mi][ni], af[mi], b2f[ni]);
                }
        }
        __syncthreads();
    }
#pragma unroll
    for (int mi = 0; mi < 2; mi++)
#pragma unroll
        for (int ni = 0; ni < 4; ni++)
#pragma unroll
            for (int hh = 0; hh < 2; hh++) {
                const int row = m0 + wm + mi*16 + lr + hh*8;
                const int col = n0 + wn + ni*8  + lc*2;
                const float x0 = a1[mi][ni][hh*2],  x1 = a1[mi][ni][hh*2+1];
                const float g0 = x0 / (1.f + __expf(-x0));
                const float g1 = x1 / (1.f + __expf(-x1));
                *(__half2*)(C + (size_t)row * FFN_D + col) =
                    __floats2half2_rn(g0 * a2[mi][ni][hh*2], g1 * a2[mi][ni][hh*2+1]);
            }
}

// ---- w3 fp16 (BM64/BN128, split-K via z, float partials) ----
#define W3H_SMEM ((2*64*40 + 2*128*40) * 2)
__global__ void __launch_bounds__(256) gemm_w3_h(
    const __half* __restrict__ A, const __half* __restrict__ B, float* __restrict__ P)
{
    extern __shared__ __half smh[];
    __half* As = smh;                  // 2 x 64*40
    __half* Bs = smh + 2*2560;         // 2 x 128*40

    const int tid  = threadIdx.x;
    const int lane = tid & 31, warp = tid >> 5;
    const int wm = (warp & 1) * 32, wn = (warp >> 1) * 32;
    const int lr = lane >> 2, lc = lane & 3;
    const int g8 = lane >> 3, r8 = lane & 7;
    const int m0 = blockIdx.y * 64, n0 = blockIdx.x * 128;
    const int z  = blockIdx.z;
    const __half* Ab = A + z * 2048;
    const __half* Bb = B + z * 2048;
    float* Pb = P + (size_t)z * M1 * H;

    const uint32_t As_u = (uint32_t)__cvta_generic_to_shared(As);
    const uint32_t Bs_u = (uint32_t)__cvta_generic_to_shared(Bs);
    const uint32_t aoff = ((wm + (g8 & 1) * 8 + r8) * 40 + (g8 >> 1) * 8) * 2;
    const uint32_t boff = ((wn + (g8 >> 1) * 8 + r8) * 40 + (g8 & 1) * 8) * 2;

    float acc[2][4][4];
#pragma unroll
    for (int i = 0; i < 2; i++)
#pragma unroll
        for (int j = 0; j < 4; j++)
#pragma unroll
            for (int r = 0; r < 4; r++) acc[i][j][r] = 0.f;

    auto loadA = [&](int buf, int k0) {
        const int r = tid >> 2, c16 = tid & 3;       // 64 rows * 4 = 256
        cp16h(As + buf * 2560 + r * 40 + c16 * 8, Ab + (size_t)(m0 + r) * FFN_D + k0 + c16 * 8);
    };
    auto loadB = [&](int buf, int k0) {
        __half* dst = Bs + buf * 5120;
#pragma unroll
        for (int i = 0; i < 2; i++) {                // 128 rows * 4 = 512
            const int c = tid + i * 256;
            const int r = c >> 2, c16 = c & 3;
            cp16h(dst + r * 40 + c16 * 8, Bb + (size_t)(n0 + r) * FFN_D + k0 + c16 * 8);
        }
    };

    loadA(0, 0); loadB(0, 0); CP_COMMIT();
    for (int t = 0; t < 64; t++) {
        const int cur = t & 1;
        if (t + 1 < 64) {
            loadA(cur ^ 1, (t + 1) << 5);
            loadB(cur ^ 1, (t + 1) << 5);
            CP_COMMIT();
            CP_WAIT(1);
        } else {
            CP_WAIT(0);
        }
        __syncthreads();
        const uint32_t aB = As_u + cur * 2560 * 2;
        const uint32_t bB = Bs_u + cur * 5120 * 2;
#pragma unroll
        for (int kc = 0; kc < 2; kc++) {
            const uint32_t kk = kc * 32;
            uint32_t af[2][4], bf[4][2], bt[4];
            ldm4(af[0], aB + aoff + kk);
            ldm4(af[1], aB + aoff + kk + 16*40*2);
#pragma unroll
            for (int p = 0; p < 2; p++) {
                ldm4(bt, bB + boff + kk + p * 16*40*2);
                bf[2*p][0]=bt[0]; bf[2*p][1]=bt[1]; bf[2*p+1][0]=bt[2]; bf[2*p+1][1]=bt[3];
            }
#pragma unroll
            for (int mi = 0; mi < 2; mi++)
#pragma unroll
                for (int ni = 0; ni < 4; ni++)
                    mma_f16(acc[mi][ni], af[mi], bf[ni]);
        }
        __syncthreads();
    }
#pragma unroll
    for (int mi = 0; mi < 2; mi++)
#pragma unroll
        for (int ni = 0; ni < 4; ni++)
#pragma unroll
            for (int hh = 0; hh < 2; hh++) {
                const int row = m0 + wm + mi*16 + lr + hh*8;
                const int col = n0 + wn + ni*8  + lc*2;
                *(float2*)(Pb + (size_t)row * H + col) =
                    make_float2(acc[mi][ni][hh*2], acc[mi][ni][hh*2+1]);
            }
}

// ---- okv fp16 (BM128/BN128), smem-staged coalesced epilogue ----
#define OKVH_SMEM (132*128*4)
__global__ void __launch_bounds__(256) gemm_okv_h(
    const __half* __restrict__ A,
    const __half* __restrict__ BK_, const __half* __restrict__ BV_,
    float* __restrict__ OutBase)
{
    extern __shared__ char smraw[];
    __half* As = (__half*)smraw;       // 2 x 128*40
    __half* Bs = As + 2*5120;          // 2 x 128*40
    float* smf = (float*)smraw;
    const int z = blockIdx.z;
    const __half* B = z ? BV_ : BK_;
    float* Ob = OutBase + (size_t)z * 4194304;

    const int tid  = threadIdx.x;
    const int lane = tid & 31, warp = tid >> 5;
    const int wm = (warp & 1) * 64, wn = (warp >> 1) * 32;
    const int lr = lane >> 2, lc = lane & 3;
    const int g8 = lane >> 3, r8 = lane & 7;
    const int m0 = blockIdx.y * 128, n0 = blockIdx.x * 128;

    const uint32_t As_u = (uint32_t)__cvta_generic_to_shared(As);
    const uint32_t Bs_u = (uint32_t)__cvta_generic_to_shared(Bs);
    const uint32_t aoff = ((wm + (g8 & 1) * 8 + r8) * 40 + (g8 >> 1) * 8) * 2;
    const uint32_t boff = ((wn + (g8 >> 1) * 8 + r8) * 40 + (g8 & 1) * 8) * 2;

    float acc[4][4][4];
#pragma unroll
    for (int i = 0; i < 4; i++)
#pragma unroll
        for (int j = 0; j < 4; j++)
#pragma unroll
            for (int r = 0; r < 4; r++) acc[i][j][r] = 0.f;

    auto loadT = [&](int buf, int k0) {
        __half* dA = As + buf * 5120;
        __half* dB = Bs + buf * 5120;
#pragma unroll
        for (int i = 0; i < 2; i++) {
            const int c = tid + i * 256;
            const int r = c >> 2, c16 = c & 3;
            cp16h(dA + r * 40 + c16 * 8, A + (size_t)(m0 + r) * H + k0 + c16 * 8);
            cp16h(dB + r * 40 + c16 * 8, B + (size_t)(n0 + r) * H + k0 + c16 * 8);
        }
    };

    loadT(0, 0); CP_COMMIT();
    for (int t = 0; t < 32; t++) {
        const int cur = t & 1;
        if (t + 1 < 32) {
            loadT(cur ^ 1, (t + 1) << 5);
            CP_COMMIT();
            CP_WAIT(1);
        } else {
            CP_WAIT(0);
        }
        __syncthreads();
        const uint32_t aB = As_u + cur * 5120 * 2;
        const uint32_t bB = Bs_u + cur * 5120 * 2;
#pragma unroll
        for (int kc = 0; kc < 2; kc++) {
            const uint32_t kk = kc * 32;
            uint32_t af[4][4], bf[4][2], bt[4];
#pragma unroll
            for (int mi = 0; mi < 4; mi++)
                ldm4(af[mi], aB + aoff + kk + mi * 16*40*2);
#pragma unroll
            for (int p = 0; p < 2; p++) {
                ldm4(bt, bB + boff + kk + p * 16*40*2);
                bf[2*p][0]=bt[0]; bf[2*p][1]=bt[1]; bf[2*p+1][0]=bt[2]; bf[2*p+1][1]=bt[3];
            }
#pragma unroll
            for (int mi = 0; mi < 4; mi++)
#pragma unroll
                for (int ni = 0; ni < 4; ni++)
                    mma_f16(acc[mi][ni], af[mi], bf[ni]);
        }
        __syncthreads();
    }

    // Stage 128x128 tile (stride 132) -> one contiguous 64KB block
#pragma unroll
    for (int mi = 0; mi < 4; mi++)
#pragma unroll
        for (int ni = 0; ni < 4; ni++)
#pragma unroll
            for (int hh = 0; hh < 2; hh++) {
                const int rr = wm + mi*16 + lr + hh*8;
                const int cc = wn + ni*8  + lc*2;
                smf[rr*132 + cc    ] = acc[mi][ni][hh*2+0];
                smf[rr*132 + cc + 1] = acc[mi][ni][hh*2+1];
            }
    __syncthreads();
    const int l = n0 >> 10, kvh = (n0 & 1023) >> 7;
    const int bb = m0 >> 8, q0 = m0 & 255;
    float* ob = Ob + ((((size_t)l * BATCH + bb) * 8 + kvh) * NQ + q0) * 128;
#pragma unroll
    for (int i = 0; i < 16; i++) {
        const int idx = tid + i * 256;
        const int q = idx >> 5, c4 = (idx & 31) * 4;
        *(float4*)(ob + q*128 + c4) = *(const float4*)(smf + q*132 + c4);
    }
}

// ---- split-K(2) reduce for w3: out(float, raw) + qt1h(half, feeds okv) ----
__global__ void reduce_w3(const float* __restrict__ P, const float* __restrict__ R,
                          __half* __restrict__ Ch, float* __restrict__ C2)
{
    const int i = blockIdx.x * 256 + threadIdx.x;   // float4 index
    const float4 a = ((const float4*)P)[i];
    const float4 b = ((const float4*)(P + M1*H))[i];
    const float4 r = ((const float4*)R)[i];
    float4 o;
    o.x = r.x + a.x + b.x;
    o.y = r.y + a.y + b.y;
    o.z = r.z + a.z + b.z;
    o.w = r.w + a.w + b.w;
    ((float4*)C2)[i] = o;
    __half2* ch2 = (__half2*)Ch;
    ch2[2*i    ] = __floats2half2_rn(o.x, o.y);
    ch2[2*i + 1] = __floats2half2_rn(o.z, o.w);
}

// ---------------- dense self-attention (unchanged) ----------------
#define SATT_SMEM ((2*64*65 + 64*257) * (int)sizeof(float))
__global__ void self_attn_kernel(const float* __restrict__ Q, const float* __restrict__ K,
                                 const float* __restrict__ V, float* __restrict__ O)
{
    extern __shared__ float sm[];
    float* Qs = sm;
    float* Ks = sm + 64*65;
    float* S  = sm + 2*64*65;
    const int bh = blockIdx.y;
    const int b = bh >> 4, h = bh & 15;
    const int q0 = blockIdx.x * 64;
    const int tid = threadIdx.x;
    const size_t base = ((size_t)b * NQ) * H + h * HDIM;

    for (int idx = tid; idx < 64*64; idx += 256) {
        const int r = idx >> 6, d = idx & 63;
        Qs[r*65 + d] = Q[base + (size_t)(q0 + r) * H + d] * 0.125f;
    }
    const int q = tid >> 2, g4 = tid & 3;

    for (int t = 0; t < 4; t++) {
        __syncthreads();
        for (int idx = tid; idx < 64*64; idx += 256) {
            const int r = idx >> 6, d = idx & 63;
            Ks[r*65 + d] = K[base + (size_t)(t*64 + r) * H + d];
        }
        __syncthreads();
#pragma unroll
        for (int jj = 0; jj < 16; jj++) {
            const int j = g4 * 16 + jj;
            float s = 0.f;
#pragma unroll
            for (int d = 0; d < 64; d++) s += Qs[q*65 + d] * Ks[j*65 + d];
            S[q*257 + t*64 + j] = s;
        }
    }
    __syncthreads();

    float mx = -1e30f;
    for (int i = g4; i < 256; i += 4) mx = fmaxf(mx, S[q*257 + i]);
    mx = fmaxf(mx, __shfl_xor_sync(~0u, mx, 1));
    mx = fmaxf(mx, __shfl_xor_sync(~0u, mx, 2));
    float sum = 0.f;
    for (int i = g4; i < 256; i += 4) { const float e = __expf(S[q*257 + i] - mx); S[q*257 + i] = e; sum += e; }
    sum += __shfl_xor_sync(~0u, sum, 1);
    sum += __shfl_xor_sync(~0u, sum, 2);
    const float inv = 1.f / sum;

    float acc[16];
#pragma unroll
    for (int i = 0; i < 16; i++) acc[i] = 0.f;

    for (int t = 0; t < 4; t++) {
        __syncthreads();
        for (int idx = tid; idx < 64*64; idx += 256) {
            const int r = idx >> 6, d = idx & 63;
            Ks[r*65 + d] = V[base + (size_t)(t*64 + r) * H + d];
        }
        __syncthreads();
        for (int j = 0; j < 64; j++) {
            const float p = S[q*257 + t*64 + j];
#pragma unroll
            for (int i = 0; i < 16; i++) acc[i] += p * Ks[j*65 + g4*16 + i];
        }
    }
#pragma unroll
    for (int i = 0; i < 16; i++)
        O[base + (size_t)(q0 + q) * H + g4*16 + i] = rtf(acc[i] * inv);
}

// ---------------- fused windowed cross-attention core (bf16 staging, unchanged) ----------------
#define SCORE_SMEM (36*1024*2 + 2*1024*4)
__global__ void __launch_bounds__(512) cross_score_kernel(
    const __nv_bfloat16* __restrict__ qk, const float* __restrict__ hs,
    const float* __restrict__ g, const float* __restrict__ b,
    float* __restrict__ hbar)
{
    extern __shared__ char smraw[];
    __nv_bfloat16* srows = (__nv_bfloat16*)smraw;        // [36][1024] bf16
    float* sg = (float*)(smraw + 36*1024*2);
    float* sb = sg + 1024;
    __shared__ float sc[16*40];
    __shared__ float smu[36], srs[36];
    __shared__ int spos[36];

    const int row = blockIdx.x;      // b*256 + q
    const int bb = row >> 8, q = row & 255;
    const int tid = threadIdx.x;
    const int base = q * 8;
    const int nj = (base + 9 <= DOC) ? 9 : (DOC - base);
    const int nkv = LAYERS * nj;

    for (int i = tid; i < 1024; i += 512) { sg[i] = g[i]; sb[i] = b[i]; }
    if (tid < nkv) { const int l = tid / nj, jj = tid - l * nj; spos[tid] = l * DOC + base + jj; }
    __syncthreads();

    for (int idx = tid; idx < nkv * 256; idx += 512) {
        const int j = idx >> 8, c4 = (idx & 255) << 2;
        const int gr = bb * KVLEN + spos[j];
        const float4 v = *(const float4*)(hs + (size_t)gr * H + c4);
        __nv_bfloat162* d = (__nv_bfloat162*)(srows + (j << 10) + c4);
        d[0] = __floats2bfloat162_rn(v.x, v.y);
        d[1] = __floats2bfloat162_rn(v.z, v.w);
    }
    __syncthreads();

    const int w = tid >> 5, lane = tid & 31;
    for (int j = w; j < nkv; j += 16) {
        const __nv_bfloat162* r2 = (const __nv_bfloat162*)(srows + (j << 10));
        float s = 0.f, s2 = 0.f;
#pragma unroll
        for (int i = 0; i < 16; i++) {
            const float2 v = __bfloat1622float2(r2[lane + 32*i]);
            s += v.x + v.y; s2 += v.x*v.x + v.y*v.y;
        }
#pragma unroll
        for (int o = 16; o > 0; o >>= 1) { s += __shfl_xor_sync(~0u, s, o); s2 += __shfl_xor_sync(~0u, s2, o); }
        if (lane == 0) {
            const float mu = s * (1.f / H);
            smu[j] = mu;
            srs[j] = rsqrtf(s2 * (1.f / H) - mu * mu + 1e-5f);
        }
    }
    __syncthreads();

    for (int idx = tid; idx < nkv * 512; idx += 512) {
        const int j = idx >> 9, p = idx & 511;
        const float mu = smu[j], rs = srs[j];
        __nv_bfloat162* d = (__nv_bfloat162*)(srows + (j << 10)) + p;
        float2 v = __bfloat1622float2(*d);
        v.x = (v.x - mu) * rs * sg[2*p  ] + sb[2*p  ];
        v.y = (v.y - mu) * rs * sg[2*p+1] + sb[2*p+1];
        *d = __floats2bfloat162_rn(v.x, v.y);
    }
    __syncthreads();

    float2 qv[16];
    const __nv_bfloat162* qrow2 = (const __nv_bfloat162*)(qk + ((size_t)w * M1 + row) * H);
#pragma unroll
    for (int i = 0; i < 16; i++) qv[i] = __bfloat1622float2(qrow2[lane + 32*i]);
    for (int j = 0; j < nkv; j++) {
        const __nv_bfloat162* r2 = (const __nv_bfloat162*)(srows + (j << 10));
        float s = 0.f;
#pragma unroll
        for (int i = 0; i < 16; i++) {
            const float2 v = __bfloat1622float2(r2[lane + 32*i]);
            s += qv[i].x * v.x + qv[i].y * v.y;
        }
#pragma unroll
        for (int o = 16; o > 0; o >>= 1) s += __shfl_xor_sync(~0u, s, o);
        if (lane == 0) sc[w*40 + j] = s * 0.125f;
    }
    __syncthreads();

    {
        float v0 = (lane      < nkv) ? sc[w*40 + lane     ] : -1e30f;
        float v1 = (lane + 32 < nkv) ? sc[w*40 + lane + 32] : -1e30f;
        float m = fmaxf(v0, v1);
#pragma unroll
        for (int o = 16; o > 0; o >>= 1) m = fmaxf(m, __shfl_xor_sync(~0u, m, o));
        float e0 = (lane      < nkv) ? __expf(v0 - m) : 0.f;
        float e1 = (lane + 32 < nkv) ? __expf(v1 - m) : 0.f;
        float su = e0 + e1;
#pragma unroll
        for (int o = 16; o > 0; o >>= 1) su += __shfl_xor_sync(~0u, su, o);
        const float inv = 1.f / su;
        if (lane      < nkv) sc[w*40 + lane     ] = e0 * inv;
        if (lane + 32 < nkv) sc[w*40 + lane + 32] = e1 * inv;
    }
    __syncthreads();

    float acc[16][2];
#pragma unroll
    for (int h = 0; h < 16; h++) { acc[h][0] = 0.f; acc[h][1] = 0.f; }
    for (int j = 0; j < nkv; j++) {
        const float2 v = __bfloat1622float2(((const __nv_bfloat162*)(srows + (j << 10)))[tid]);
#pragma unroll
        for (int h = 0; h < 16; h++) {
            const float p = sc[h*40 + j];
            acc[h][0] += p * v.x;
            acc[h][1] += p * v.y;
        }
    }
    const int c0 = tid * 2;
#pragma unroll
    for (int h = 0; h < 16; h++)
        *(float2*)(hbar + ((size_t)h * M1 + row) * H + c0) =
            make_float2(rtf(acc[h][0]), rtf(acc[h][1]));
}

// ---------------- launch ----------------
extern "C" void kernel_launch(void* const* d_in, const int* in_sizes, int n_in,
                              void* d_out_, int out_size)
{
    (void)in_sizes; (void)n_in; (void)out_size;
    const float* qtok = (const float*)d_in[0];
    const float* hs   = (const float*)d_in[1];
    const float* ln1g = (const float*)d_in[2];
    const float* ln1b = (const float*)d_in[3];
    const float* ln2g = (const float*)d_in[4];
    const float* ln2b = (const float*)d_in[5];
    const float* lnkvg= (const float*)d_in[6];
    const float* lnkvb= (const float*)d_in[7];
    const float* lnfg = (const float*)d_in[8];
    const float* lnfb = (const float*)d_in[9];
    const float* wqs  = (const float*)d_in[10];
    const float* wks  = (const float*)d_in[11];
    const float* wvs  = (const float*)d_in[12];
    const float* wos  = (const float*)d_in[13];
    const float* wqc  = (const float*)d_in[14];
    const float* wkc  = (const float*)d_in[15];
    const float* wvc  = (const float*)d_in[16];
    const float* woc  = (const float*)d_in[17];
    const float* w1   = (const float*)d_in[18];
    const float* w2   = (const float*)d_in[19];
    const float* w3   = (const float*)d_in[20];
    const float* okw  = (const float*)d_in[21];
    const float* ovw  = (const float*)d_in[22];
    float* out = (float*)d_out_;

    void* p;
    cudaGetSymbolAddress(&p, g_xln);  float*  xln  = (float*)p;
    cudaGetSymbolAddress(&p, g_qkv);  float*  qkv  = (float*)p;
    cudaGetSymbolAddress(&p, g_attn); float*  ab   = (float*)p;
    cudaGetSymbolAddress(&p, g_qt1);  float*  qt1  = (float*)p;
    cudaGetSymbolAddress(&p, g_qt2);  float*  qt2  = (float*)p;
    cudaGetSymbolAddress(&p, g_qk);   float*  qk   = (float*)p;
    cudaGetSymbolAddress(&p, g_hbar); float*  hbar = (float*)p;
    cudaGetSymbolAddress(&p, g_w1h);  __half* w1h  = (__half*)p;
    cudaGetSymbolAddress(&p, g_w2h);  __half* w2h  = (__half*)p;
    cudaGetSymbolAddress(&p, g_w3h);  __half* w3h  = (__half*)p;
    cudaGetSymbolAddress(&p, g_okwh); __half* okwh = (__half*)p;
    cudaGetSymbolAddress(&p, g_ovwh); __half* ovwh = (__half*)p;
    cudaGetSymbolAddress(&p, g_xlnh); __half* xlnh = (__half*)p;
    cudaGetSymbolAddress(&p, g_h1h);  __half* h1h  = (__half*)p;
    cudaGetSymbolAddress(&p, g_qt1h); __half* qt1h = (__half*)p;

    constexpr int S_64_128  = smem_g2(64, 128, 1, 32);
    constexpr int S_64_64   = smem_g2(64, 64, 1, 32);
    constexpr int S_128_64n = smem_g2(128, 64, 0, 32);
    constexpr int S_QKV     = (3*128*36 + 3*2304) * 4;

    cudaFuncSetAttribute(self_attn_kernel,   cudaFuncAttributeMaxDynamicSharedMemorySize, SATT_SMEM);
    cudaFuncSetAttribute(cross_score_kernel, cudaFuncAttributeMaxDynamicSharedMemorySize, SCORE_SMEM);
    cudaFuncSetAttribute(gemm2<1,64,128,32>, cudaFuncAttributeMaxDynamicSharedMemorySize, S_64_128);
    cudaFuncSetAttribute(gemm2<1,64,64,32>,  cudaFuncAttributeMaxDynamicSharedMemorySize, S_64_64);
    cudaFuncSetAttribute(gemm2<0,128,64,32>, cudaFuncAttributeMaxDynamicSharedMemorySize, S_128_64n);
    cudaFuncSetAttribute(gemm_qkv,           cudaFuncAttributeMaxDynamicSharedMemorySize, S_QKV);
    cudaFuncSetAttribute(gemm_ffn_h,         cudaFuncAttributeMaxDynamicSharedMemorySize, FFNH_SMEM);
    cudaFuncSetAttribute(gemm_w3_h,          cudaFuncAttributeMaxDynamicSharedMemorySize, W3H_SMEM);
    cudaFuncSetAttribute(gemm_okv_h,         cudaFuncAttributeMaxDynamicSharedMemorySize, OKVH_SMEM);

    float* qb = qkv;
    float* kb = qkv + M1*H;
    float* vb = qkv + 2*M1*H;

    const dim3 gHH  (H/128, M1/64, 1);        // 128
    const dim3 gQKV (H/64, M1/128, 3);        // 384
    const dim3 gFFN (FFN_D/64, M1/128, 1);    // 512
    const dim3 gQK  (H/64, M1/128, NHEADS);   // 2048
    const dim3 gVP  (1, M1/64, NHEADS);       // 256
    const dim3 gOKV (4096/128, M1/128, 2);    // 512
    const dim3 gW3  (H/128, M1/64, 2);        // 256, split-K=2

    // 0) weight fp32 -> fp16 conversions (data-independent, run first)
    convert_h<<<4096, 256>>>(w1,  w1h,  FFN_D*H/4);
    convert_h<<<4096, 256>>>(w2,  w2h,  FFN_D*H/4);
    convert_h<<<4096, 256>>>(w3,  w3h,  H*FFN_D/4);
    convert_h<<<4096, 256>>>(okw, okwh, LAYERS*H*H/4);
    convert_h<<<4096, 256>>>(ovw, ovwh, LAYERS*H*H/4);

    // 1) self-attention block
    ln_kernel<<<M1, 256>>>(qtok, ln1g, ln1b, xln);
    gemm_qkv<<<gQKV, 256, S_QKV>>>(xln, wqs, wks, wvs, qkv);
    self_attn_kernel<<<dim3(4, 64), 256, SATT_SMEM>>>(qb, kb, vb, ab);
    gemm2<1,64,128,32><<<gHH, 256, S_64_128>>>(ab, H, 0, wos, H, 0, qt1, H, 0, qtok, nullptr, H, 1);

    // 2) windowed cross-attention (factorized; qk intermediate in bf16)
    ln_kernel<<<M1, 256>>>(qt1, ln2g, ln2b, xln);
    gemm2<1,64,128,32><<<gHH, 256, S_64_128>>>(xln, H, 0, wqc, H, 0, qb, H, 0, nullptr, nullptr, H, 0);
    gemm2<0,128,64,32><<<gQK, 256, S_128_64n>>>(qb, H, 64, wkc, H, (long)64*H,
                                                qk, H, (long)M1*H/2, nullptr, nullptr, 64, 4);
    cross_score_kernel<<<M1, 512, SCORE_SMEM>>>((const __nv_bfloat16*)qk, hs, lnkvg, lnkvb, hbar);
    gemm2<1,64,64,32><<<gVP, 256, S_64_64>>>(hbar, H, (long)M1*H, wvc, H, (long)64*H,
                                             ab, H, 64, nullptr, nullptr, H, 0);
    gemm2<1,64,128,32><<<gHH, 256, S_64_128>>>(ab, H, 0, woc, H, 0, qt2, H, 0, qt1, nullptr, H, 1);

    // 3) SwiGLU FFN in fp16 (fused w1/w2 + silu; w3 via split-K=2 + reduce)
    ln_kernel_h<<<M1, 256>>>(qt2, lnfg, lnfb, xlnh);
    gemm_ffn_h<<<gFFN, 256, FFNH_SMEM>>>(xlnh, w1h, w2h, h1h);
    gemm_w3_h<<<gW3, 256, W3H_SMEM>>>(h1h, w3h, qk);
    reduce_w3<<<M1*H/1024, 256>>>(qk, qt2, qt1h, out);

    // 4) per-layer K/V output projections in fp16 (staged epilogue)
    gemm_okv_h<<<gOKV, 256, OKVH_SMEM>>>(qt1h, okwh, ovwh, out + (size_t)M1*H);
}

// round 15
// speedup vs baseline: 1.1491x; 1.0443x over previous
#include <cuda_runtime.h>
#include <cuda_bf16.h>
#include <cuda_fp16.h>
#include <cstdint>

#define H      1024
#define NHEADS 16
#define HDIM   64
#define NQ     256
#define BATCH  4
#define LAYERS 4
#define DOC    2048
#define KVLEN  8192
#define FFN_D  4096
#define M1     (BATCH*NQ)      /* 1024  */
#define MH     (BATCH*KVLEN)   /* 32768 */

// ---------------- device scratch ----------------
__device__ float  g_qkv [3*M1*H];
__device__ float  g_qb  [M1*H];
__device__ float  g_qt1 [M1*H];
__device__ float  g_qt2 [M1*H];
__device__ float  g_qk  [(size_t)NHEADS*M1*H];   // bf16 qk (low half); later w3 split-K float partials
__device__ __half g_hbarh[(size_t)NHEADS*M1*H];
__device__ __half g_abh [M1*H];
__device__ __half g_xlnh[M1*H];
__device__ __half g_h1h [(size_t)M1*FFN_D];
__device__ __half g_qt1h[M1*H];
__device__ __half g_w1h [(size_t)FFN_D*H];
__device__ __half g_w2h [(size_t)FFN_D*H];
__device__ __half g_w3h [(size_t)H*FFN_D];
__device__ __half g_okwh[(size_t)LAYERS*H*H];
__device__ __half g_ovwh[(size_t)LAYERS*H*H];
__device__ __half g_wqkvh[(size_t)3*H*H];
__device__ __half g_wosh[(size_t)H*H];
__device__ __half g_wqch[(size_t)H*H];
__device__ __half g_wvch[(size_t)H*H];
__device__ __half g_woch[(size_t)H*H];

// ---------------- helpers ----------------
__device__ __forceinline__ uint32_t f2tf32(float x) {
    uint32_t r;
    asm("cvt.rna.tf32.f32 %0, %1;" : "=r"(r) : "f"(x));
    return r;
}
__device__ __forceinline__ float rtf(float x) { return __uint_as_float(f2tf32(x)); }

__device__ __forceinline__ void mma_tf32(float c[4], const uint32_t a[4], const uint32_t b[2]) {
    asm volatile(
        "mma.sync.aligned.m16n8k8.row.col.f32.tf32.tf32.f32 "
        "{%0,%1,%2,%3}, {%4,%5,%6,%7}, {%8,%9}, {%0,%1,%2,%3};\n"
        : "+f"(c[0]), "+f"(c[1]), "+f"(c[2]), "+f"(c[3])
        : "r"(a[0]), "r"(a[1]), "r"(a[2]), "r"(a[3]), "r"(b[0]), "r"(b[1]));
}
__device__ __forceinline__ void mma_f16(float c[4], const uint32_t a[4], const uint32_t b[2]) {
    asm volatile(
        "mma.sync.aligned.m16n8k16.row.col.f32.f16.f16.f32 "
        "{%0,%1,%2,%3}, {%4,%5,%6,%7}, {%8,%9}, {%0,%1,%2,%3};\n"
        : "+f"(c[0]), "+f"(c[1]), "+f"(c[2]), "+f"(c[3])
        : "r"(a[0]), "r"(a[1]), "r"(a[2]), "r"(a[3]), "r"(b[0]), "r"(b[1]));
}
__device__ __forceinline__ void ldm4(uint32_t a[4], uint32_t addr) {
    asm volatile("ldmatrix.sync.aligned.m8n8.x4.shared.b16 {%0,%1,%2,%3}, [%4];\n"
                 : "=r"(a[0]), "=r"(a[1]), "=r"(a[2]), "=r"(a[3]) : "r"(addr));
}
__device__ __forceinline__ void cp16(float* s, const float* g) {
    uint32_t sa = (uint32_t)__cvta_generic_to_shared(s);
    asm volatile("cp.async.cg.shared.global [%0], [%1], 16;\n" :: "r"(sa), "l"(g));
}
__device__ __forceinline__ void cp16h(__half* s, const __half* g) {
    uint32_t sa = (uint32_t)__cvta_generic_to_shared(s);
    asm volatile("cp.async.cg.shared.global [%0], [%1], 16;\n" :: "r"(sa), "l"(g));
}
#define CP_COMMIT() asm volatile("cp.async.commit_group;\n")
#define CP_WAIT(n)  asm volatile("cp.async.wait_group %0;\n" :: "n"(n))

// ---------------- weight fp32 -> fp16 conversion ----------------
__global__ void convert_h(const float* __restrict__ s, __half* __restrict__ d, int n4)
{
    const int i = blockIdx.x * 256 + threadIdx.x;
    if (i < n4) {
        const float4 v = ((const float4*)s)[i];
        __half2* d2 = (__half2*)d;
        d2[2*i    ] = __floats2half2_rn(v.x, v.y);
        d2[2*i + 1] = __floats2half2_rn(v.z, v.w);
    }
}

// ---------------- LayerNorm with fp16 output ----------------
__global__ void ln_kernel_h(const float* __restrict__ x, const float* __restrict__ g,
                            const float* __restrict__ b, __half* __restrict__ y)
{
    __shared__ float red[16];
    const int row = blockIdx.x, tid = threadIdx.x;
    const float* xr = x + (size_t)row * H;
    float v[4]; float s = 0.f, s2 = 0.f;
#pragma unroll
    for (int i = 0; i < 4; i++) { v[i] = xr[tid + i*256]; s += v[i]; s2 += v[i]*v[i]; }
#pragma unroll
    for (int o = 16; o > 0; o >>= 1) { s += __shfl_xor_sync(~0u, s, o); s2 += __shfl_xor_sync(~0u, s2, o); }
    if ((tid & 31) == 0) { red[tid>>5] = s; red[8 + (tid>>5)] = s2; }
    __syncthreads();
    if (tid < 32) {
        s  = (tid < 8) ? red[tid]     : 0.f;
        s2 = (tid < 8) ? red[8 + tid] : 0.f;
#pragma unroll
        for (int o = 4; o > 0; o >>= 1) { s += __shfl_xor_sync(~0u, s, o); s2 += __shfl_xor_sync(~0u, s2, o); }
        if (tid == 0) { red[0] = s; red[1] = s2; }
    }
    __syncthreads();
    const float mu  = red[0] * (1.f / H);
    const float var = red[1] * (1.f / H) - mu * mu;
    const float rs  = rsqrtf(var + 1e-5f);
    __half* yr = y + (size_t)row * H;
#pragma unroll
    for (int i = 0; i < 4; i++) { int c = tid + i*256; yr[c] = __float2half_rn((v[i] - mu) * rs * g[c] + b[c]); }
}

// ================= tf32 GEMM (BT=0 only use: qk projection) =================
constexpr int smem_g2(int BM, int BN, int BT, int BK) {
    return (3*BM*(BK+4) + (BT ? 3*BN*(BK+4) : 3*32*(BN+8))) * 4;
}

template<int BT, int BM, int BN, int BK>
__global__ void __launch_bounds__(256) gemm2(
    const float* __restrict__ A, int lda, long Az,
    const float* __restrict__ B, int ldb, long Bz,
    float* __restrict__ C, int ldc, long Cz,
    const float* __restrict__ R, float* __restrict__ C2,
    int K, int epi)
{
    extern __shared__ float sm[];
    constexpr int RS  = BK + 4;
    constexpr int ASZ = BM * RS;
    constexpr int BSZ = BT ? BN * RS : 32*(BN+8);
    constexpr int MI = BM / 32;
    constexpr int NI = BN / 32;
    constexpr int KCN = BK / 8;
    constexpr int TPR = BK / 4;
    float* As = sm;
    float* Bs = sm + 3*ASZ;

    const int tid  = threadIdx.x;
    const int lane = tid & 31, warp = tid >> 5;
    const int wm = (warp & 1) * (BM/2);
    const int wn = (warp >> 1) * (BN/4);
    const int lr = lane >> 2, lc = lane & 3;
    const int g8 = lane >> 3, r8 = lane & 7;
    const int m0 = blockIdx.y * BM, n0 = blockIdx.x * BN;
    const float* Ab = A + (size_t)blockIdx.z * Az;
    const float* Bb = B + (size_t)blockIdx.z * Bz;
    float*       Cb = C + (size_t)blockIdx.z * Cz;

    const uint32_t As_u = (uint32_t)__cvta_generic_to_shared(As);
    const uint32_t aoff = ((wm + (g8 & 1) * 8 + r8) * RS + (g8 >> 1) * 4) * 4;

    float acc[MI][NI][4];
#pragma unroll
    for (int i = 0; i < MI; i++)
#pragma unroll
        for (int j = 0; j < NI; j++)
#pragma unroll
            for (int r = 0; r < 4; r++) acc[i][j][r] = 0.f;

    auto loadA = [&](int buf, int k0) {
        float* dst = As + buf * ASZ;
#pragma unroll
        for (int i = 0; i < BM*BK/1024; i++) {
            const int c = tid + i * 256;
            const int r = c / TPR, cc = (c % TPR) * 4;
            cp16(dst + r * RS + cc, Ab + (size_t)(m0 + r) * lda + k0 + cc);
        }
    };
    auto loadB = [&](int buf, int k0) {
        float* dst = Bs + buf * BSZ;
#pragma unroll
        for (int i = 0; i < BN/32; i++) {
            const int c = tid + i * 256;
            const int r = c / (BN/4), cc = (c % (BN/4)) * 4;
            cp16(dst + r * (BN+8) + cc, Bb + (size_t)(k0 + r) * ldb + n0 + cc);
        }
    };

    const int ntiles = K / BK;
    loadA(0, 0); loadB(0, 0); CP_COMMIT();
    if (ntiles > 1) { loadA(1, BK); loadB(1, BK); CP_COMMIT(); }

    for (int t = 0; t < ntiles; t++) {
        const int cur = t % 3;
        if (t < ntiles - 1) CP_WAIT(1); else CP_WAIT(0);
        __syncthreads();
        if (t + 2 < ntiles) {
            const int s = (t + 2) % 3;
            loadA(s, (t + 2) * BK);
            loadB(s, (t + 2) * BK);
            CP_COMMIT();
        }
        const uint32_t aB = As_u + cur * ASZ * 4;
        const float* Bsb = Bs + cur * BSZ;
#pragma unroll
        for (int kc = 0; kc < KCN; kc++) {
            const uint32_t kk4 = kc * 32;
            uint32_t af[MI][4], bf[NI][2];
#pragma unroll
            for (int mi = 0; mi < MI; mi++)
                ldm4(af[mi], aB + aoff + kk4 + mi * 16*RS*4);
            const int kk = kc * 8;
#pragma unroll
            for (int ni = 0; ni < NI; ni++) {
                const int nb = wn + ni * 8;
                bf[ni][0] = __float_as_uint(Bsb[(kk + lc    ) * (BN+8) + nb + lr]);
                bf[ni][1] = __float_as_uint(Bsb[(kk + lc + 4) * (BN+8) + nb + lr]);
            }
#pragma unroll
            for (int mi = 0; mi < MI; mi++)
#pragma unroll
                for (int ni = 0; ni < NI; ni++)
                    mma_tf32(acc[mi][ni], af[mi], bf[ni]);
        }
    }
    __syncthreads();

#pragma unroll
    for (int mi = 0; mi < MI; mi++)
#pragma unroll
        for (int ni = 0; ni < NI; ni++)
#pragma unroll
            for (int hh = 0; hh < 2; hh++) {
                const int row = m0 + wm + mi*16 + lr + hh*8;
                const int col = n0 + wn + ni*8  + lc*2;
                const float v0 = acc[mi][ni][hh*2+0];
                const float v1 = acc[mi][ni][hh*2+1];
                if (epi == 4) {
                    __nv_bfloat16* Ch = (__nv_bfloat16*)Cb;
                    *(__nv_bfloat162*)(Ch + (size_t)row * ldc + col) = __floats2bfloat162_rn(v0, v1);
                } else {
                    *(float2*)(Cb + (size_t)row * ldc + col) = make_float2(v0, v1);
                }
            }
    (void)R; (void)C2;
}

// ================= fp16 GEMM core (m16n8k16, 2-stage, RS=40 halfs, 2x4 warp grid) =================
// C = A@B^T, B stored [N,K] half. epi 0: store half; epi 1: C(f32) = R + acc; epi 2: store float.
constexpr int smem_gh(int BM, int BN) { return (2*BM*40 + 2*BN*40) * 2; }

template<int BM, int BN>
__global__ void __launch_bounds__(256) gemm2h(
    const __half* __restrict__ A, int lda, long Az,
    const __half* __restrict__ B, int ldb, long Bz,
    void* __restrict__ Cv, int ldc, long Cz,
    const float* __restrict__ R,
    int K, int epi)
{
    extern __shared__ __half smh[];
    constexpr int ASZ = BM * 40;
    constexpr int BSZ = BN * 40;
    constexpr int MI = BM / 32;
    constexpr int NI = BN / 32;
    __half* As = smh;
    __half* Bs = smh + 2*ASZ;

    const int tid  = threadIdx.x;
    const int lane = tid & 31, warp = tid >> 5;
    const int wm = (warp & 1) * (BM/2);
    const int wn = (warp >> 1) * (BN/4);
    const int lr = lane >> 2, lc = lane & 3;
    const int g8 = lane >> 3, r8 = lane & 7;
    const int m0 = blockIdx.y * BM, n0 = blockIdx.x * BN;
    const __half* Ab = A + (size_t)blockIdx.z * Az;
    const __half* Bb = B + (size_t)blockIdx.z * Bz;

    const uint32_t As_u = (uint32_t)__cvta_generic_to_shared(As);
    const uint32_t Bs_u = (uint32_t)__cvta_generic_to_shared(Bs);
    const uint32_t aoff = ((wm + (g8 & 1) * 8 + r8) * 40 + (g8 >> 1) * 8) * 2;
    const uint32_t boff = ((wn + (g8 >> 1) * 8 + r8) * 40 + (g8 & 1) * 8) * 2;

    float acc[MI][NI][4];
#pragma unroll
    for (int i = 0; i < MI; i++)
#pragma unroll
        for (int j = 0; j < NI; j++)
#pragma unroll
            for (int r = 0; r < 4; r++) acc[i][j][r] = 0.f;

    auto loadA = [&](int buf, int k0) {
        __half* dst = As + buf * ASZ;
#pragma unroll
        for (int i = 0; i < BM/64; i++) {
            const int c = tid + i * 256;
            const int r = c >> 2, c16 = c & 3;
            cp16h(dst + r * 40 + c16 * 8, Ab + (size_t)(m0 + r) * lda + k0 + c16 * 8);
        }
    };
    auto loadB = [&](int buf, int k0) {
        __half* dst = Bs + buf * BSZ;
#pragma unroll
        for (int i = 0; i < BN/64; i++) {
            const int c = tid + i * 256;
            const int r = c >> 2, c16 = c & 3;
            cp16h(dst + r * 40 + c16 * 8, Bb + (size_t)(n0 + r) * ldb + k0 + c16 * 8);
        }
    };

    const int ntiles = K >> 5;
    loadA(0, 0); loadB(0, 0); CP_COMMIT();
    for (int t = 0; t < ntiles; t++) {
        const int cur = t & 1;
        if (t + 1 < ntiles) {
            loadA(cur ^ 1, (t + 1) << 5);
            loadB(cur ^ 1, (t + 1) << 5);
            CP_COMMIT();
            CP_WAIT(1);
        } else {
            CP_WAIT(0);
        }
        __syncthreads();
        const uint32_t aB = As_u + cur * ASZ * 2;
        const uint32_t bB = Bs_u + cur * BSZ * 2;
#pragma unroll
        for (int kc = 0; kc < 2; kc++) {
            const uint32_t kk = kc * 32;
            uint32_t af[MI][4], bf[NI][2], bt[4];
#pragma unroll
            for (int mi = 0; mi < MI; mi++)
                ldm4(af[mi], aB + aoff + kk + mi * 16*40*2);
#pragma unroll
            for (int p = 0; p < NI/2; p++) {
                ldm4(bt, bB + boff + kk + p * 16*40*2);
                bf[2*p][0]=bt[0]; bf[2*p][1]=bt[1]; bf[2*p+1][0]=bt[2]; bf[2*p+1][1]=bt[3];
            }
#pragma unroll
            for (int mi = 0; mi < MI; mi++)
#pragma unroll
                for (int ni = 0; ni < NI; ni++)
                    mma_f16(acc[mi][ni], af[mi], bf[ni]);
        }
        __syncthreads();
    }

#pragma unroll
    for (int mi = 0; mi < MI; mi++)
#pragma unroll
        for (int ni = 0; ni < NI; ni++)
#pragma unroll
            for (int hh = 0; hh < 2; hh++) {
                const int row = m0 + wm + mi*16 + lr + hh*8;
                const int col = n0 + wn + ni*8  + lc*2;
                const float v0 = acc[mi][ni][hh*2+0];
                const float v1 = acc[mi][ni][hh*2+1];
                if (epi == 0) {
                    __half* Ch = (__half*)Cv + (size_t)blockIdx.z * Cz;
                    *(__half2*)(Ch + (size_t)row * ldc + col) = __floats2half2_rn(v0, v1);
                } else if (epi == 1) {
                    float* Cf = (float*)Cv + (size_t)blockIdx.z * Cz;
                    const size_t o = (size_t)row * ldc + col;
                    *(float2*)(Cf + o) = make_float2(R[o] + v0, R[o+1] + v1);
                } else {
                    float* Cf = (float*)Cv + (size_t)blockIdx.z * Cz;
                    *(float2*)(Cf + (size_t)row * ldc + col) = make_float2(v0, v1);
                }
            }
}

// ---- fused FFN fp16 (validated): C = silu(A@W1^T) * (A@W2^T), half output ----
#define FFNH_SMEM ((2*128*40 + 2*64*40 + 2*64*40) * 2)
__global__ void __launch_bounds__(256) gemm_ffn_h(
    const __half* __restrict__ A, const __half* __restrict__ W1, const __half* __restrict__ W2,
    __half* __restrict__ C)
{
    extern __shared__ __half smh[];
    __half* As  = smh;
    __half* Bs1 = smh + 2*5120;
    __half* Bs2 = Bs1 + 2*2560;

    const int tid  = threadIdx.x;
    const int lane = tid & 31, warp = tid >> 5;
    const int wm = (warp & 3) * 32, wn = (warp >> 2) * 32;
    const int lr = lane >> 2, lc = lane & 3;
    const int g8 = lane >> 3, r8 = lane & 7;
    const int m0 = blockIdx.y * 128, n0 = blockIdx.x * 64;

    const uint32_t As_u  = (uint32_t)__cvta_generic_to_shared(As);
    const uint32_t Bs1_u = (uint32_t)__cvta_generic_to_shared(Bs1);
    const uint32_t Bs2_u = (uint32_t)__cvta_generic_to_shared(Bs2);
    const uint32_t aoff = ((wm + (g8 & 1) * 8 + r8) * 40 + (g8 >> 1) * 8) * 2;
    const uint32_t boff = ((wn + (g8 >> 1) * 8 + r8) * 40 + (g8 & 1) * 8) * 2;

    float a1[2][4][4], a2[2][4][4];
#pragma unroll
    for (int i = 0; i < 2; i++)
#pragma unroll
        for (int j = 0; j < 4; j++)
#pragma unroll
            for (int r = 0; r < 4; r++) { a1[i][j][r] = 0.f; a2[i][j][r] = 0.f; }

    auto loadA = [&](int buf, int k0) {
        __half* dst = As + buf * 5120;
#pragma unroll
        for (int i = 0; i < 2; i++) {
            const int c = tid + i * 256;
            const int r = c >> 2, c16 = c & 3;
            cp16h(dst + r * 40 + c16 * 8, A + (size_t)(m0 + r) * H + k0 + c16 * 8);
        }
    };
    auto loadB = [&](int buf, int k0) {
        const int r = tid >> 2, c16 = tid & 3;
        cp16h(Bs1 + buf * 2560 + r * 40 + c16 * 8, W1 + (size_t)(n0 + r) * H + k0 + c16 * 8);
        cp16h(Bs2 + buf * 2560 + r * 40 + c16 * 8, W2 + (size_t)(n0 + r) * H + k0 + c16 * 8);
    };

    loadA(0, 0); loadB(0, 0); CP_COMMIT();
    for (int t = 0; t < 32; t++) {
        const int cur = t & 1;
        if (t + 1 < 32) {
            loadA(cur ^ 1, (t + 1) << 5);
            loadB(cur ^ 1, (t + 1) << 5);
            CP_COMMIT();
            CP_WAIT(1);
        } else {
            CP_WAIT(0);
        }
        __syncthreads();
        const uint32_t aB  = As_u  + cur * 5120 * 2;
        const uint32_t b1B = Bs1_u + cur * 2560 * 2;
        const uint32_t b2B = Bs2_u + cur * 2560 * 2;
#pragma unroll
        for (int kc = 0; kc < 2; kc++) {
            const uint32_t kk = kc * 32;
            uint32_t af[2][4], b1f[4][2], b2f[4][2], bt[4];
            ldm4(af[0], aB + aoff + kk);
            ldm4(af[1], aB + aoff + kk + 16*40*2);
#pragma unroll
            for (int p = 0; p < 2; p++) {
                ldm4(bt, b1B + boff + kk + p * 16*40*2);
                b1f[2*p][0]=bt[0]; b1f[2*p][1]=bt[1]; b1f[2*p+1][0]=bt[2]; b1f[2*p+1][1]=bt[3];
                ldm4(bt, b2B + boff + kk + p * 16*40*2);
                b2f[2*p][0]=bt[0]; b2f[2*p][1]=bt[1]; b2f[2*p+1][0]=bt[2]; b2f[2*p+1][1]=bt[3];
            }
#pragma unroll
            for (int mi = 0; mi < 2; mi++)
#pragma unroll
                for (int ni = 0; ni < 4; ni++) {
                    mma_f16(a1[mi][ni], af[mi], b1f[ni]);
                    mma_f16(a2[mi][ni], af[mi], b2f[ni]);
                }
        }
        __syncthreads();
    }
#pragma unroll
    for (int mi = 0; mi < 2; mi++)
#pragma unroll
        for (int ni = 0; ni < 4; ni++)
#pragma unroll
            for (int hh = 0; hh < 2; hh++) {
                const int row = m0 + wm + mi*16 + lr + hh*8;
                const int col = n0 + wn + ni*8  + lc*2;
                const float x0 = a1[mi][ni][hh*2],  x1 = a1[mi][ni][hh*2+1];
                const float g0 = x0 / (1.f + __expf(-x0));
                const float g1 = x1 / (1.f + __expf(-x1));
                *(__half2*)(C + (size_t)row * FFN_D + col) =
                    __floats2half2_rn(g0 * a2[mi][ni][hh*2], g1 * a2[mi][ni][hh*2+1]);
            }
}

// ---- w3 fp16 (BM64/BN128, split-K via z, float partials; validated) ----
#define W3H_SMEM ((2*64*40 + 2*128*40) * 2)
__global__ void __launch_bounds__(256) gemm_w3_h(
    const __half* __restrict__ A, const __half* __restrict__ B, float* __restrict__ P)
{
    extern __shared__ __half smh[];
    __half* As = smh;
    __half* Bs = smh + 2*2560;

    const int tid  = threadIdx.x;
    const int lane = tid & 31, warp = tid >> 5;
    const int wm = (warp & 1) * 32, wn = (warp >> 1) * 32;
    const int lr = lane >> 2, lc = lane & 3;
    const int g8 = lane >> 3, r8 = lane & 7;
    const int m0 = blockIdx.y * 64, n0 = blockIdx.x * 128;
    const int z  = blockIdx.z;
    const __half* Ab = A + z * 2048;
    const __half* Bb = B + z * 2048;
    float* Pb = P + (size_t)z * M1 * H;

    const uint32_t As_u = (uint32_t)__cvta_generic_to_shared(As);
    const uint32_t Bs_u = (uint32_t)__cvta_generic_to_shared(Bs);
    const uint32_t aoff = ((wm + (g8 & 1) * 8 + r8) * 40 + (g8 >> 1) * 8) * 2;
    const uint32_t boff = ((wn + (g8 >> 1) * 8 + r8) * 40 + (g8 & 1) * 8) * 2;

    float acc[2][4][4];
#pragma unroll
    for (int i = 0; i < 2; i++)
#pragma unroll
        for (int j = 0; j < 4; j++)
#pragma unroll
            for (int r = 0; r < 4; r++) acc[i][j][r] = 0.f;

    auto loadA = [&](int buf, int k0) {
        const int r = tid >> 2, c16 = tid & 3;
        cp16h(As + buf * 2560 + r * 40 + c16 * 8, Ab + (size_t)(m0 + r) * FFN_D + k0 + c16 * 8);
    };
    auto loadB = [&](int buf, int k0) {
        __half* dst = Bs + buf * 5120;
#pragma unroll
        for (int i = 0; i < 2; i++) {
            const int c = tid + i * 256;
            const int r = c >> 2, c16 = c & 3;
            cp16h(dst + r * 40 + c16 * 8, Bb + (size_t)(n0 + r) * FFN_D + k0 + c16 * 8);
        }
    };

    loadA(0, 0); loadB(0, 0); CP_COMMIT();
    for (int t = 0; t < 64; t++) {
        const int cur = t & 1;
        if (t + 1 < 64) {
            loadA(cur ^ 1, (t + 1) << 5);
            loadB(cur ^ 1, (t + 1) << 5);
            CP_COMMIT();
            CP_WAIT(1);
        } else {
            CP_WAIT(0);
        }
        __syncthreads();
        const uint32_t aB = As_u + cur * 2560 * 2;
        const uint32_t bB = Bs_u + cur * 5120 * 2;
#pragma unroll
        for (int kc = 0; kc < 2; kc++) {
            const uint32_t kk = kc * 32;
            uint32_t af[2][4], bf[4][2], bt[4];
            ldm4(af[0], aB + aoff + kk);
            ldm4(af[1], aB + aoff + kk + 16*40*2);
#pragma unroll
            for (int p = 0; p < 2; p++) {
                ldm4(bt, bB + boff + kk + p * 16*40*2);
                bf[2*p][0]=bt[0]; bf[2*p][1]=bt[1]; bf[2*p+1][0]=bt[2]; bf[2*p+1][1]=bt[3];
            }
#pragma unroll
            for (int mi = 0; mi < 2; mi++)
#pragma unroll
                for (int ni = 0; ni < 4; ni++)
                    mma_f16(acc[mi][ni], af[mi], bf[ni]);
        }
        __syncthreads();
    }
#pragma unroll
    for (int mi = 0; mi < 2; mi++)
#pragma unroll
        for (int ni = 0; ni < 4; ni++)
#pragma unroll
            for (int hh = 0; hh < 2; hh++) {
                const int row = m0 + wm + mi*16 + lr + hh*8;
                const int col = n0 + wn + ni*8  + lc*2;
                *(float2*)(Pb + (size_t)row * H + col) =
                    make_float2(acc[mi][ni][hh*2], acc[mi][ni][hh*2+1]);
            }
}

// ---- okv fp16 (BM128/BN128), smem-staged coalesced epilogue (validated) ----
#define OKVH_SMEM (132*128*4)
__global__ void __launch_bounds__(256) gemm_okv_h(
    const __half* __restrict__ A,
    const __half* __restrict__ BK_, const __half* __restrict__ BV_,
    float* __restrict__ OutBase)
{
    extern __shared__ char smraw[];
    __half* As = (__half*)smraw;
    __half* Bs = As + 2*5120;
    float* smf = (float*)smraw;
    const int z = blockIdx.z;
    const __half* B = z ? BV_ : BK_;
    float* Ob = OutBase + (size_t)z * 4194304;

    const int tid  = threadIdx.x;
    const int lane = tid & 31, warp = tid >> 5;
    const int wm = (warp & 1) * 64, wn = (warp >> 1) * 32;
    const int lr = lane >> 2, lc = lane & 3;
    const int g8 = lane >> 3, r8 = lane & 7;
    const int m0 = blockIdx.y * 128, n0 = blockIdx.x * 128;

    const uint32_t As_u = (uint32_t)__cvta_generic_to_shared(As);
    const uint32_t Bs_u = (uint32_t)__cvta_generic_to_shared(Bs);
    const uint32_t aoff = ((wm + (g8 & 1) * 8 + r8) * 40 + (g8 >> 1) * 8) * 2;
    const uint32_t boff = ((wn + (g8 >> 1) * 8 + r8) * 40 + (g8 & 1) * 8) * 2;

    float acc[4][4][4];
#pragma unroll
    for (int i = 0; i < 4; i++)
#pragma unroll
        for (int j = 0; j < 4; j++)
#pragma unroll
            for (int r = 0; r < 4; r++) acc[i][j][r] = 0.f;

    auto loadT = [&](int buf, int k0) {
        __half* dA = As + buf * 5120;
        __half* dB = Bs + buf * 5120;
#pragma unroll
        for (int i = 0; i < 2; i++) {
            const int c = tid + i * 256;
            const int r = c >> 2, c16 = c & 3;
            cp16h(dA + r * 40 + c16 * 8, A + (size_t)(m0 + r) * H + k0 + c16 * 8);
            cp16h(dB + r * 40 + c16 * 8, B + (size_t)(n0 + r) * H + k0 + c16 * 8);
        }
    };

    loadT(0, 0); CP_COMMIT();
    for (int t = 0; t < 32; t++) {
        const int cur = t & 1;
        if (t + 1 < 32) {
            loadT(cur ^ 1, (t + 1) << 5);
            CP_COMMIT();
            CP_WAIT(1);
        } else {
            CP_WAIT(0);
        }
        __syncthreads();
        const uint32_t aB = As_u + cur * 5120 * 2;
        const uint32_t bB = Bs_u + cur * 5120 * 2;
#pragma unroll
        for (int kc = 0; kc < 2; kc++) {
            const uint32_t kk = kc * 32;
            uint32_t af[4][4], bf[4][2], bt[4];
#pragma unroll
            for (int mi = 0; mi < 4; mi++)
                ldm4(af[mi], aB + aoff + kk + mi * 16*40*2);
#pragma unroll
            for (int p = 0; p < 2; p++) {
                ldm4(bt, bB + boff + kk + p * 16*40*2);
                bf[2*p][0]=bt[0]; bf[2*p][1]=bt[1]; bf[2*p+1][0]=bt[2]; bf[2*p+1][1]=bt[3];
            }
#pragma unroll
            for (int mi = 0; mi < 4; mi++)
#pragma unroll
                for (int ni = 0; ni < 4; ni++)
                    mma_f16(acc[mi][ni], af[mi], bf[ni]);
        }
        __syncthreads();
    }

#pragma unroll
    for (int mi = 0; mi < 4; mi++)
#pragma unroll
        for (int ni = 0; ni < 4; ni++)
#pragma unroll
            for (int hh = 0; hh < 2; hh++) {
                const int rr = wm + mi*16 + lr + hh*8;
                const int cc = wn + ni*8  + lc*2;
                smf[rr*132 + cc    ] = acc[mi][ni][hh*2+0];
                smf[rr*132 + cc + 1] = acc[mi][ni][hh*2+1];
            }
    __syncthreads();
    const int l = n0 >> 10, kvh = (n0 & 1023) >> 7;
    const int bb = m0 >> 8, q0 = m0 & 255;
    float* ob = Ob + ((((size_t)l * BATCH + bb) * 8 + kvh) * NQ + q0) * 128;
#pragma unroll
    for (int i = 0; i < 16; i++) {
        const int idx = tid + i * 256;
        const int q = idx >> 5, c4 = (idx & 31) * 4;
        *(float4*)(ob + q*128 + c4) = *(const float4*)(smf + q*132 + c4);
    }
}

// ---- split-K(2) reduce for w3: out(float, raw) + qt1h(half, feeds okv) ----
__global__ void reduce_w3(const float* __restrict__ P, const float* __restrict__ R,
                          __half* __restrict__ Ch, float* __restrict__ C2)
{
    const int i = blockIdx.x * 256 + threadIdx.x;
    const float4 a = ((const float4*)P)[i];
    const float4 b = ((const float4*)(P + M1*H))[i];
    const float4 r = ((const float4*)R)[i];
    float4 o;
    o.x = r.x + a.x + b.x;
    o.y = r.y + a.y + b.y;
    o.z = r.z + a.z + b.z;
    o.w = r.w + a.w + b.w;
    ((float4*)C2)[i] = o;
    __half2* ch2 = (__half2*)Ch;
    ch2[2*i    ] = __floats2half2_rn(o.x, o.y);
    ch2[2*i + 1] = __floats2half2_rn(o.z, o.w);
}

// ---------------- dense self-attention (fp32 in, half out) ----------------
#define SATT_SMEM ((2*64*65 + 64*257) * (int)sizeof(float))
__global__ void self_attn_kernel(const float* __restrict__ Q, const float* __restrict__ K,
                                 const float* __restrict__ V, __half* __restrict__ O)
{
    extern __shared__ float sm[];
    float* Qs = sm;
    float* Ks = sm + 64*65;
    float* S  = sm + 2*64*65;
    const int bh = blockIdx.y;
    const int b = bh >> 4, h = bh & 15;
    const int q0 = blockIdx.x * 64;
    const int tid = threadIdx.x;
    const size_t base = ((size_t)b * NQ) * H + h * HDIM;

    for (int idx = tid; idx < 64*64; idx += 256) {
        const int r = idx >> 6, d = idx & 63;
        Qs[r*65 + d] = Q[base + (size_t)(q0 + r) * H + d] * 0.125f;
    }
    const int q = tid >> 2, g4 = tid & 3;

    for (int t = 0; t < 4; t++) {
        __syncthreads();
        for (int idx = tid; idx < 64*64; idx += 256) {
            const int r = idx >> 6, d = idx & 63;
            Ks[r*65 + d] = K[base + (size_t)(t*64 + r) * H + d];
        }
        __syncthreads();
#pragma unroll
        for (int jj = 0; jj < 16; jj++) {
            const int j = g4 * 16 + jj;
            float s = 0.f;
#pragma unroll
            for (int d = 0; d < 64; d++) s += Qs[q*65 + d] * Ks[j*65 + d];
            S[q*257 + t*64 + j] = s;
        }
    }
    __syncthreads();

    float mx = -1e30f;
    for (int i = g4; i < 256; i += 4) mx = fmaxf(mx, S[q*257 + i]);
    mx = fmaxf(mx, __shfl_xor_sync(~0u, mx, 1));
    mx = fmaxf(mx, __shfl_xor_sync(~0u, mx, 2));
    float sum = 0.f;
    for (int i = g4; i < 256; i += 4) { const float e = __expf(S[q*257 + i] - mx); S[q*257 + i] = e; sum += e; }
    sum += __shfl_xor_sync(~0u, sum, 1);
    sum += __shfl_xor_sync(~0u, sum, 2);
    const float inv = 1.f / sum;

    float acc[16];
#pragma unroll
    for (int i = 0; i < 16; i++) acc[i] = 0.f;

    for (int t = 0; t < 4; t++) {
        __syncthreads();
        for (int idx = tid; idx < 64*64; idx += 256) {
            const int r = idx >> 6, d = idx & 63;
            Ks[r*65 + d] = V[base + (size_t)(t*64 + r) * H + d];
        }
        __syncthreads();
        for (int j = 0; j < 64; j++) {
            const float p = S[q*257 + t*64 + j];
#pragma unroll
            for (int i = 0; i < 16; i++) acc[i] += p * Ks[j*65 + g4*16 + i];
        }
    }
#pragma unroll
    for (int i = 0; i < 16; i++)
        O[base + (size_t)(q0 + q) * H + g4*16 + i] = __float2half_rn(acc[i] * inv);
}

// ---------------- fused windowed cross-attention core (bf16 staging; half hbar out) ----------------
#define SCORE_SMEM (36*1024*2 + 2*1024*4)
__global__ void __launch_bounds__(512) cross_score_kernel(
    const __nv_bfloat16* __restrict__ qk, const float* __restrict__ hs,
    const float* __restrict__ g, const float* __restrict__ b,
    __half* __restrict__ hbar)
{
    extern __shared__ char smraw[];
    __nv_bfloat16* srows = (__nv_bfloat16*)smraw;        // [36][1024] bf16
    float* sg = (float*)(smraw + 36*1024*2);
    float* sb = sg + 1024;
    __shared__ float sc[16*40];
    __shared__ float smu[36], srs[36];
    __shared__ int spos[36];

    const int row = blockIdx.x;      // b*256 + q
    const int bb = row >> 8, q = row & 255;
    const int tid = threadIdx.x;
    const int base = q * 8;
    const int nj = (base + 9 <= DOC) ? 9 : (DOC - base);
    const int nkv = LAYERS * nj;

    for (int i = tid; i < 1024; i += 512) { sg[i] = g[i]; sb[i] = b[i]; }
    if (tid < nkv) { const int l = tid / nj, jj = tid - l * nj; spos[tid] = l * DOC + base + jj; }
    __syncthreads();

    for (int idx = tid; idx < nkv * 256; idx += 512) {
        const int j = idx >> 8, c4 = (idx & 255) << 2;
        const int gr = bb * KVLEN + spos[j];
        const float4 v = *(const float4*)(hs + (size_t)gr * H + c4);
        __nv_bfloat162* d = (__nv_bfloat162*)(srows + (j << 10) + c4);
        d[0] = __floats2bfloat162_rn(v.x, v.y);
        d[1] = __floats2bfloat162_rn(v.z, v.w);
    }
    __syncthreads();

    const int w = tid >> 5, lane = tid & 31;
    for (int j = w; j < nkv; j += 16) {
        const __nv_bfloat162* r2 = (const __nv_bfloat162*)(srows + (j << 10));
        float s = 0.f, s2 = 0.f;
#pragma unroll
        for (int i = 0; i < 16; i++) {
            const float2 v = __bfloat1622float2(r2[lane + 32*i]);
            s += v.x + v.y; s2 += v.x*v.x + v.y*v.y;
        }
#pragma unroll
        for (int o = 16; o > 0; o >>= 1) { s += __shfl_xor_sync(~0u, s, o); s2 += __shfl_xor_sync(~0u, s2, o); }
        if (lane == 0) {
            const float mu = s * (1.f / H);
            smu[j] = mu;
            srs[j] = rsqrtf(s2 * (1.f / H) - mu * mu + 1e-5f);
        }
    }
    __syncthreads();

    for (int idx = tid; idx < nkv * 512; idx += 512) {
        const int j = idx >> 9, p = idx & 511;
        const float mu = smu[j], rs = srs[j];
        __nv_bfloat162* d = (__nv_bfloat162*)(srows + (j << 10)) + p;
        float2 v = __bfloat1622float2(*d);
        v.x = (v.x - mu) * rs * sg[2*p  ] + sb[2*p  ];
        v.y = (v.y - mu) * rs * sg[2*p+1] + sb[2*p+1];
        *d = __floats2bfloat162_rn(v.x, v.y);
    }
    __syncthreads();

    float2 qv[16];
    const __nv_bfloat162* qrow2 = (const __nv_bfloat162*)(qk + ((size_t)w * M1 + row) * H);
#pragma unroll
    for (int i = 0; i < 16; i++) qv[i] = __bfloat1622float2(qrow2[lane + 32*i]);
    for (int j = 0; j < nkv; j++) {
        const __nv_bfloat162* r2 = (const __nv_bfloat162*)(srows + (j << 10));
        float s = 0.f;
#pragma unroll
        for (int i = 0; i < 16; i++) {
            const float2 v = __bfloat1622float2(r2[lane + 32*i]);
            s += qv[i].x * v.x + qv[i].y * v.y;
        }
#pragma unroll
        for (int o = 16; o > 0; o >>= 1) s += __shfl_xor_sync(~0u, s, o);
        if (lane == 0) sc[w*40 + j] = s * 0.125f;
    }
    __syncthreads();

    {
        float v0 = (lane      < nkv) ? sc[w*40 + lane     ] : -1e30f;
        float v1 = (lane + 32 < nkv) ? sc[w*40 + lane + 32] : -1e30f;
        float m = fmaxf(v0, v1);
#pragma unroll
        for (int o = 16; o > 0; o >>= 1) m = fmaxf(m, __shfl_xor_sync(~0u, m, o));
        float e0 = (lane      < nkv) ? __expf(v0 - m) : 0.f;
        float e1 = (lane + 32 < nkv) ? __expf(v1 - m) : 0.f;
        float su = e0 + e1;
#pragma unroll
        for (int o = 16; o > 0; o >>= 1) su += __shfl_xor_sync(~0u, su, o);
        const float inv = 1.f / su;
        if (lane      < nkv) sc[w*40 + lane     ] = e0 * inv;
        if (lane + 32 < nkv) sc[w*40 + lane + 32] = e1 * inv;
    }
    __syncthreads();

    float acc[16][2];
#pragma unroll
    for (int h = 0; h < 16; h++) { acc[h][0] = 0.f; acc[h][1] = 0.f; }
    for (int j = 0; j < nkv; j++) {
        const float2 v = __bfloat1622float2(((const __nv_bfloat162*)(srows + (j << 10)))[tid]);
#pragma unroll
        for (int h = 0; h < 16; h++) {
            const float p = sc[h*40 + j];
            acc[h][0] += p * v.x;
            acc[h][1] += p * v.y;
        }
    }
    const int c0 = tid * 2;
#pragma unroll
    for (int h = 0; h < 16; h++)
        *(__half2*)(hbar + ((size_t)h * M1 + row) * H + c0) =
            __floats2half2_rn(acc[h][0], acc[h][1]);
}

// ---------------- launch ----------------
extern "C" void kernel_launch(void* const* d_in, const int* in_sizes, int n_in,
                              void* d_out_, int out_size)
{
    (void)in_sizes; (void)n_in; (void)out_size;
    const float* qtok = (const float*)d_in[0];
    const float* hs   = (const float*)d_in[1];
    const float* ln1g = (const float*)d_in[2];
    const float* ln1b = (const float*)d_in[3];
    const float* ln2g = (const float*)d_in[4];
    const float* ln2b = (const float*)d_in[5];
    const float* lnkvg= (const float*)d_in[6];
    const float* lnkvb= (const float*)d_in[7];
    const float* lnfg = (const float*)d_in[8];
    const float* lnfb = (const float*)d_in[9];
    const float* wqs  = (const float*)d_in[10];
    const float* wks  = (const float*)d_in[11];
    const float* wvs  = (const float*)d_in[12];
    const float* wos  = (const float*)d_in[13];
    const float* wqc  = (const float*)d_in[14];
    const float* wkc  = (const float*)d_in[15];
    const float* wvc  = (const float*)d_in[16];
    const float* woc  = (const float*)d_in[17];
    const float* w1   = (const float*)d_in[18];
    const float* w2   = (const float*)d_in[19];
    const float* w3   = (const float*)d_in[20];
    const float* okw  = (const float*)d_in[21];
    const float* ovw  = (const float*)d_in[22];
    float* out = (float*)d_out_;

    void* p;
    cudaGetSymbolAddress(&p, g_qkv);   float*  qkv  = (float*)p;
    cudaGetSymbolAddress(&p, g_qb);    float*  qb   = (float*)p;
    cudaGetSymbolAddress(&p, g_qt1);   float*  qt1  = (float*)p;
    cudaGetSymbolAddress(&p, g_qt2);   float*  qt2  = (float*)p;
    cudaGetSymbolAddress(&p, g_qk);    float*  qk   = (float*)p;
    cudaGetSymbolAddress(&p, g_hbarh); __half* hbarh= (__half*)p;
    cudaGetSymbolAddress(&p, g_abh);   __half* abh  = (__half*)p;
    cudaGetSymbolAddress(&p, g_xlnh);  __half* xlnh = (__half*)p;
    cudaGetSymbolAddress(&p, g_h1h);   __half* h1h  = (__half*)p;
    cudaGetSymbolAddress(&p, g_qt1h);  __half* qt1h = (__half*)p;
    cudaGetSymbolAddress(&p, g_w1h);   __half* w1h  = (__half*)p;
    cudaGetSymbolAddress(&p, g_w2h);   __half* w2h  = (__half*)p;
    cudaGetSymbolAddress(&p, g_w3h);   __half* w3h  = (__half*)p;
    cudaGetSymbolAddress(&p, g_okwh);  __half* okwh = (__half*)p;
    cudaGetSymbolAddress(&p, g_ovwh);  __half* ovwh = (__half*)p;
    cudaGetSymbolAddress(&p, g_wqkvh); __half* wqkvh= (__half*)p;
    cudaGetSymbolAddress(&p, g_wosh);  __half* wosh = (__half*)p;
    cudaGetSymbolAddress(&p, g_wqch);  __half* wqch = (__half*)p;
    cudaGetSymbolAddress(&p, g_wvch);  __half* wvch = (__half*)p;
    cudaGetSymbolAddress(&p, g_woch);  __half* woch = (__half*)p;

    constexpr int S_128_64n = smem_g2(128, 64, 0, 32);
    constexpr int SH_128_64 = smem_gh(128, 64);
    constexpr int SH_64_128 = smem_gh(64, 128);
    constexpr int SH_64_64  = smem_gh(64, 64);

    cudaFuncSetAttribute(self_attn_kernel,   cudaFuncAttributeMaxDynamicSharedMemorySize, SATT_SMEM);
    cudaFuncSetAttribute(cross_score_kernel, cudaFuncAttributeMaxDynamicSharedMemorySize, SCORE_SMEM);
    cudaFuncSetAttribute(gemm2<0,128,64,32>, cudaFuncAttributeMaxDynamicSharedMemorySize, S_128_64n);
    cudaFuncSetAttribute(gemm2h<128,64>,     cudaFuncAttributeMaxDynamicSharedMemorySize, SH_128_64);
    cudaFuncSetAttribute(gemm2h<64,128>,     cudaFuncAttributeMaxDynamicSharedMemorySize, SH_64_128);
    cudaFuncSetAttribute(gemm2h<64,64>,      cudaFuncAttributeMaxDynamicSharedMemorySize, SH_64_64);
    cudaFuncSetAttribute(gemm_ffn_h,         cudaFuncAttributeMaxDynamicSharedMemorySize, FFNH_SMEM);
    cudaFuncSetAttribute(gemm_w3_h,          cudaFuncAttributeMaxDynamicSharedMemorySize, W3H_SMEM);
    cudaFuncSetAttribute(gemm_okv_h,         cudaFuncAttributeMaxDynamicSharedMemorySize, OKVH_SMEM);

    float* kb = qkv + M1*H;
    float* vb = qkv + 2*M1*H;

    const dim3 gQKV (H/64, M1/128, 3);        // 16 x 8 x 3 = 384
    const dim3 gHH  (H/128, M1/64, 1);        // 8 x 16 = 128
    const dim3 gFFN (FFN_D/64, M1/128, 1);    // 512
    const dim3 gQK  (H/64, M1/128, NHEADS);   // 2048
    const dim3 gVP  (1, M1/64, NHEADS);       // 256
    const dim3 gOKV (4096/128, M1/128, 2);    // 512
    const dim3 gW3  (H/128, M1/64, 2);        // 256

    // 0) weight fp32 -> fp16 conversions (data-independent)
    convert_h<<<4096, 256>>>(w1,  w1h,  FFN_D*H/4);
    convert_h<<<4096, 256>>>(w2,  w2h,  FFN_D*H/4);
    convert_h<<<4096, 256>>>(w3,  w3h,  H*FFN_D/4);
    convert_h<<<4096, 256>>>(okw, okwh, LAYERS*H*H/4);
    convert_h<<<4096, 256>>>(ovw, ovwh, LAYERS*H*H/4);
    convert_h<<<1024, 256>>>(wqs, wqkvh,           H*H/4);
    convert_h<<<1024, 256>>>(wks, wqkvh +   H*H,   H*H/4);
    convert_h<<<1024, 256>>>(wvs, wqkvh + 2*H*H,   H*H/4);
    convert_h<<<1024, 256>>>(wos, wosh, H*H/4);
    convert_h<<<1024, 256>>>(wqc, wqch, H*H/4);
    convert_h<<<1024, 256>>>(wvc, wvch, H*H/4);
    convert_h<<<1024, 256>>>(woc, woch, H*H/4);

    // 1) self-attention block (fp16 GEMMs)
    ln_kernel_h<<<M1, 256>>>(qtok, ln1g, ln1b, xlnh);
    gemm2h<128,64><<<gQKV, 256, SH_128_64>>>(xlnh, H, 0, wqkvh, H, (long)H*H,
                                             qkv, H, (long)M1*H, nullptr, H, 2);
    self_attn_kernel<<<dim3(4, 64), 256, SATT_SMEM>>>(qkv, kb, vb, abh);
    gemm2h<64,128><<<gHH, 256, SH_64_128>>>(abh, H, 0, wosh, H, 0,
                                            qt1, H, 0, qtok, H, 1);

    // 2) windowed cross-attention (factorized)
    ln_kernel_h<<<M1, 256>>>(qt1, ln2g, ln2b, xlnh);
    gemm2h<64,128><<<gHH, 256, SH_64_128>>>(xlnh, H, 0, wqch, H, 0,
                                            qb, H, 0, nullptr, H, 2);
    gemm2<0,128,64,32><<<gQK, 256, S_128_64n>>>(qb, H, 64, wkc, H, (long)64*H,
                                                qk, H, (long)M1*H/2, nullptr, nullptr, 64, 4);
    cross_score_kernel<<<M1, 512, SCORE_SMEM>>>((const __nv_bfloat16*)qk, hs, lnkvg, lnkvb, hbarh);
    gemm2h<64,64><<<gVP, 256, SH_64_64>>>(hbarh, H, (long)M1*H, wvch, H, (long)64*H,
                                          abh, H, 64, nullptr, H, 0);
    gemm2h<64,128><<<gHH, 256, SH_64_128>>>(abh, H, 0, woch, H, 0,
                                            qt2, H, 0, qt1, H, 1);

    // 3) SwiGLU FFN in fp16 (fused w1/w2 + silu; w3 via split-K=2 + reduce)
    ln_kernel_h<<<M1, 256>>>(qt2, lnfg, lnfb, xlnh);
    gemm_ffn_h<<<gFFN, 256, FFNH_SMEM>>>(xlnh, w1h, w2h, h1h);
    gemm_w3_h<<<gW3, 256, W3H_SMEM>>>(h1h, w3h, qk);
    reduce_w3<<<M1*H/1024, 256>>>(qk, qt2, qt1h, out);

    // 4) per-layer K/V output projections in fp16 (staged epilogue)
    gemm_okv_h<<<gOKV, 256, OKVH_SMEM>>>(qt1h, okwh, ovwh, out + (size_t)M1*H);
}

// round 16
// speedup vs baseline: 1.5648x; 1.3617x over previous
#include <cuda_runtime.h>
#include <cuda_bf16.h>
#include <cuda_fp16.h>
#include <cstdint>

#define H      1024
#define NHEADS 16
#define HDIM   64
#define NQ     256
#define BATCH  4
#define LAYERS 4
#define DOC    2048
#define KVLEN  8192
#define FFN_D  4096
#define M1     (BATCH*NQ)      /* 1024  */
#define MH     (BATCH*KVLEN)   /* 32768 */

// ---------------- device scratch ----------------
__device__ float  g_qb  [M1*H];
__device__ float  g_qt1 [M1*H];
__device__ float  g_qt2 [M1*H];
__device__ float  g_qk  [(size_t)NHEADS*M1*H];   // bf16 qk (low half); later w3 split-K float partials
__device__ __half g_qkvh[(size_t)3*M1*H];
__device__ __half g_hbarh[(size_t)NHEADS*M1*H];
__device__ __half g_abh [M1*H];
__device__ __half g_xlnh[M1*H];
__device__ __half g_h1h [(size_t)M1*FFN_D];
__device__ __half g_qt1h[M1*H];
__device__ __half g_w1h [(size_t)FFN_D*H];
__device__ __half g_w2h [(size_t)FFN_D*H];
__device__ __half g_w3h [(size_t)H*FFN_D];
__device__ __half g_okwh[(size_t)LAYERS*H*H];
__device__ __half g_ovwh[(size_t)LAYERS*H*H];
__device__ __half g_wqkvh[(size_t)3*H*H];
__device__ __half g_wosh[(size_t)H*H];
__device__ __half g_wqch[(size_t)H*H];
__device__ __half g_wvch[(size_t)H*H];
__device__ __half g_woch[(size_t)H*H];

// ---------------- helpers ----------------
__device__ __forceinline__ uint32_t f2tf32(float x) {
    uint32_t r;
    asm("cvt.rna.tf32.f32 %0, %1;" : "=r"(r) : "f"(x));
    return r;
}
__device__ __forceinline__ float rtf(float x) { return __uint_as_float(f2tf32(x)); }

__device__ __forceinline__ void mma_tf32(float c[4], const uint32_t a[4], const uint32_t b[2]) {
    asm volatile(
        "mma.sync.aligned.m16n8k8.row.col.f32.tf32.tf32.f32 "
        "{%0,%1,%2,%3}, {%4,%5,%6,%7}, {%8,%9}, {%0,%1,%2,%3};\n"
        : "+f"(c[0]), "+f"(c[1]), "+f"(c[2]), "+f"(c[3])
        : "r"(a[0]), "r"(a[1]), "r"(a[2]), "r"(a[3]), "r"(b[0]), "r"(b[1]));
}
__device__ __forceinline__ void mma_f16(float c[4], const uint32_t a[4], const uint32_t b[2]) {
    asm volatile(
        "mma.sync.aligned.m16n8k16.row.col.f32.f16.f16.f32 "
        "{%0,%1,%2,%3}, {%4,%5,%6,%7}, {%8,%9}, {%0,%1,%2,%3};\n"
        : "+f"(c[0]), "+f"(c[1]), "+f"(c[2]), "+f"(c[3])
        : "r"(a[0]), "r"(a[1]), "r"(a[2]), "r"(a[3]), "r"(b[0]), "r"(b[1]));
}
__device__ __forceinline__ void ldm4(uint32_t a[4], uint32_t addr) {
    asm volatile("ldmatrix.sync.aligned.m8n8.x4.shared.b16 {%0,%1,%2,%3}, [%4];\n"
                 : "=r"(a[0]), "=r"(a[1]), "=r"(a[2]), "=r"(a[3]) : "r"(addr));
}
__device__ __forceinline__ void cp16(float* s, const float* g) {
    uint32_t sa = (uint32_t)__cvta_generic_to_shared(s);
    asm volatile("cp.async.cg.shared.global [%0], [%1], 16;\n" :: "r"(sa), "l"(g));
}
__device__ __forceinline__ void cp16h(__half* s, const __half* g) {
    uint32_t sa = (uint32_t)__cvta_generic_to_shared(s);
    asm volatile("cp.async.cg.shared.global [%0], [%1], 16;\n" :: "r"(sa), "l"(g));
}
__device__ __forceinline__ uint32_t pack_h2(float a, float b) {
    __half2 h = __floats2half2_rn(a, b);
    return *(uint32_t*)&h;
}
#define CP_COMMIT() asm volatile("cp.async.commit_group;\n")
#define CP_WAIT(n)  asm volatile("cp.async.wait_group %0;\n" :: "n"(n))

// ---------------- single mega weight fp32 -> fp16 conversion ----------------
__global__ void convert_all(
    const float* s0, const float* s1, const float* s2, const float* s3,
    const float* s4, const float* s5, const float* s6, const float* s7,
    const float* s8, const float* s9, const float* s10, const float* s11,
    __half* d0, __half* d1, __half* d2, __half* d3, __half* d4, __half* d5,
    __half* d6, __half* d7, __half* d8, __half* d9, __half* d10, __half* d11)
{
    const int seg = blockIdx.y;
    const float* s; __half* d; int n4;
    switch (seg) {
        case 0:  s = s0;  d = d0;  n4 = 1048576; break;   // w1
        case 1:  s = s1;  d = d1;  n4 = 1048576; break;   // w2
        case 2:  s = s2;  d = d2;  n4 = 1048576; break;   // w3
        case 3:  s = s3;  d = d3;  n4 = 1048576; break;   // okw
        case 4:  s = s4;  d = d4;  n4 = 1048576; break;   // ovw
        case 5:  s = s5;  d = d5;  n4 = 262144;  break;   // wqs
        case 6:  s = s6;  d = d6;  n4 = 262144;  break;   // wks
        case 7:  s = s7;  d = d7;  n4 = 262144;  break;   // wvs
        case 8:  s = s8;  d = d8;  n4 = 262144;  break;   // wos
        case 9:  s = s9;  d = d9;  n4 = 262144;  break;   // wqc
        case 10: s = s10; d = d10; n4 = 262144;  break;   // wvc
        default: s = s11; d = d11; n4 = 262144;  break;   // woc
    }
    for (int i = blockIdx.x * 256 + threadIdx.x; i < n4; i += gridDim.x * 256) {
        const float4 v = ((const float4*)s)[i];
        __half2* d2p = (__half2*)d;
        d2p[2*i    ] = __floats2half2_rn(v.x, v.y);
        d2p[2*i + 1] = __floats2half2_rn(v.z, v.w);
    }
}

// ---------------- LayerNorm with fp16 output ----------------
__global__ void ln_kernel_h(const float* __restrict__ x, const float* __restrict__ g,
                            const float* __restrict__ b, __half* __restrict__ y)
{
    __shared__ float red[16];
    const int row = blockIdx.x, tid = threadIdx.x;
    const float* xr = x + (size_t)row * H;
    float v[4]; float s = 0.f, s2 = 0.f;
#pragma unroll
    for (int i = 0; i < 4; i++) { v[i] = xr[tid + i*256]; s += v[i]; s2 += v[i]*v[i]; }
#pragma unroll
    for (int o = 16; o > 0; o >>= 1) { s += __shfl_xor_sync(~0u, s, o); s2 += __shfl_xor_sync(~0u, s2, o); }
    if ((tid & 31) == 0) { red[tid>>5] = s; red[8 + (tid>>5)] = s2; }
    __syncthreads();
    if (tid < 32) {
        s  = (tid < 8) ? red[tid]     : 0.f;
        s2 = (tid < 8) ? red[8 + tid] : 0.f;
#pragma unroll
        for (int o = 4; o > 0; o >>= 1) { s += __shfl_xor_sync(~0u, s, o); s2 += __shfl_xor_sync(~0u, s2, o); }
        if (tid == 0) { red[0] = s; red[1] = s2; }
    }
    __syncthreads();
    const float mu  = red[0] * (1.f / H);
    const float var = red[1] * (1.f / H) - mu * mu;
    const float rs  = rsqrtf(var + 1e-5f);
    __half* yr = y + (size_t)row * H;
#pragma unroll
    for (int i = 0; i < 4; i++) { int c = tid + i*256; yr[c] = __float2half_rn((v[i] - mu) * rs * g[c] + b[c]); }
}

// ================= tf32 GEMM (BT=0 only use: qk projection) =================
constexpr int smem_g2(int BM, int BN, int BT, int BK) {
    return (3*BM*(BK+4) + (BT ? 3*BN*(BK+4) : 3*32*(BN+8))) * 4;
}

template<int BT, int BM, int BN, int BK>
__global__ void __launch_bounds__(256) gemm2(
    const float* __restrict__ A, int lda, long Az,
    const float* __restrict__ B, int ldb, long Bz,
    float* __restrict__ C, int ldc, long Cz,
    const float* __restrict__ R, float* __restrict__ C2,
    int K, int epi)
{
    extern __shared__ float sm[];
    constexpr int RS  = BK + 4;
    constexpr int ASZ = BM * RS;
    constexpr int BSZ = BT ? BN * RS : 32*(BN+8);
    constexpr int MI = BM / 32;
    constexpr int NI = BN / 32;
    constexpr int KCN = BK / 8;
    constexpr int TPR = BK / 4;
    float* As = sm;
    float* Bs = sm + 3*ASZ;

    const int tid  = threadIdx.x;
    const int lane = tid & 31, warp = tid >> 5;
    const int wm = (warp & 1) * (BM/2);
    const int wn = (warp >> 1) * (BN/4);
    const int lr = lane >> 2, lc = lane & 3;
    const int g8 = lane >> 3, r8 = lane & 7;
    const int m0 = blockIdx.y * BM, n0 = blockIdx.x * BN;
    const float* Ab = A + (size_t)blockIdx.z * Az;
    const float* Bb = B + (size_t)blockIdx.z * Bz;
    float*       Cb = C + (size_t)blockIdx.z * Cz;

    const uint32_t As_u = (uint32_t)__cvta_generic_to_shared(As);
    const uint32_t aoff = ((wm + (g8 & 1) * 8 + r8) * RS + (g8 >> 1) * 4) * 4;

    float acc[MI][NI][4];
#pragma unroll
    for (int i = 0; i < MI; i++)
#pragma unroll
        for (int j = 0; j < NI; j++)
#pragma unroll
            for (int r = 0; r < 4; r++) acc[i][j][r] = 0.f;

    auto loadA = [&](int buf, int k0) {
        float* dst = As + buf * ASZ;
#pragma unroll
        for (int i = 0; i < BM*BK/1024; i++) {
            const int c = tid + i * 256;
            const int r = c / TPR, cc = (c % TPR) * 4;
            cp16(dst + r * RS + cc, Ab + (size_t)(m0 + r) * lda + k0 + cc);
        }
    };
    auto loadB = [&](int buf, int k0) {
        float* dst = Bs + buf * BSZ;
#pragma unroll
        for (int i = 0; i < BN/32; i++) {
            const int c = tid + i * 256;
            const int r = c / (BN/4), cc = (c % (BN/4)) * 4;
            cp16(dst + r * (BN+8) + cc, Bb + (size_t)(k0 + r) * ldb + n0 + cc);
        }
    };

    const int ntiles = K / BK;
    loadA(0, 0); loadB(0, 0); CP_COMMIT();
    if (ntiles > 1) { loadA(1, BK); loadB(1, BK); CP_COMMIT(); }

    for (int t = 0; t < ntiles; t++) {
        const int cur = t % 3;
        if (t < ntiles - 1) CP_WAIT(1); else CP_WAIT(0);
        __syncthreads();
        if (t + 2 < ntiles) {
            const int s = (t + 2) % 3;
            loadA(s, (t + 2) * BK);
            loadB(s, (t + 2) * BK);
            CP_COMMIT();
        }
        const uint32_t aB = As_u + cur * ASZ * 4;
        const float* Bsb = Bs + cur * BSZ;
#pragma unroll
        for (int kc = 0; kc < KCN; kc++) {
            const uint32_t kk4 = kc * 32;
            uint32_t af[MI][4], bf[NI][2];
#pragma unroll
            for (int mi = 0; mi < MI; mi++)
                ldm4(af[mi], aB + aoff + kk4 + mi * 16*RS*4);
            const int kk = kc * 8;
#pragma unroll
            for (int ni = 0; ni < NI; ni++) {
                const int nb = wn + ni * 8;
                bf[ni][0] = __float_as_uint(Bsb[(kk + lc    ) * (BN+8) + nb + lr]);
                bf[ni][1] = __float_as_uint(Bsb[(kk + lc + 4) * (BN+8) + nb + lr]);
            }
#pragma unroll
            for (int mi = 0; mi < MI; mi++)
#pragma unroll
                for (int ni = 0; ni < NI; ni++)
                    mma_tf32(acc[mi][ni], af[mi], bf[ni]);
        }
    }
    __syncthreads();

#pragma unroll
    for (int mi = 0; mi < MI; mi++)
#pragma unroll
        for (int ni = 0; ni < NI; ni++)
#pragma unroll
            for (int hh = 0; hh < 2; hh++) {
                const int row = m0 + wm + mi*16 + lr + hh*8;
                const int col = n0 + wn + ni*8  + lc*2;
                const float v0 = acc[mi][ni][hh*2+0];
                const float v1 = acc[mi][ni][hh*2+1];
                if (epi == 4) {
                    __nv_bfloat16* Ch = (__nv_bfloat16*)Cb;
                    *(__nv_bfloat162*)(Ch + (size_t)row * ldc + col) = __floats2bfloat162_rn(v0, v1);
                } else {
                    *(float2*)(Cb + (size_t)row * ldc + col) = make_float2(v0, v1);
                }
            }
    (void)R; (void)C2;
}

// ================= fp16 GEMM core (m16n8k16, 2-stage, RS=40 halfs, 2x4 warp grid) =================
constexpr int smem_gh(int BM, int BN) { return (2*BM*40 + 2*BN*40) * 2; }

template<int BM, int BN>
__global__ void __launch_bounds__(256) gemm2h(
    const __half* __restrict__ A, int lda, long Az,
    const __half* __restrict__ B, int ldb, long Bz,
    void* __restrict__ Cv, int ldc, long Cz,
    const float* __restrict__ R,
    int K, int epi)
{
    extern __shared__ __half smh[];
    constexpr int ASZ = BM * 40;
    constexpr int BSZ = BN * 40;
    constexpr int MI = BM / 32;
    constexpr int NI = BN / 32;
    __half* As = smh;
    __half* Bs = smh + 2*ASZ;

    const int tid  = threadIdx.x;
    const int lane = tid & 31, warp = tid >> 5;
    const int wm = (warp & 1) * (BM/2);
    const int wn = (warp >> 1) * (BN/4);
    const int lr = lane >> 2, lc = lane & 3;
    const int g8 = lane >> 3, r8 = lane & 7;
    const int m0 = blockIdx.y * BM, n0 = blockIdx.x * BN;
    const __half* Ab = A + (size_t)blockIdx.z * Az;
    const __half* Bb = B + (size_t)blockIdx.z * Bz;

    const uint32_t As_u = (uint32_t)__cvta_generic_to_shared(As);
    const uint32_t Bs_u = (uint32_t)__cvta_generic_to_shared(Bs);
    const uint32_t aoff = ((wm + (g8 & 1) * 8 + r8) * 40 + (g8 >> 1) * 8) * 2;
    const uint32_t boff = ((wn + (g8 >> 1) * 8 + r8) * 40 + (g8 & 1) * 8) * 2;

    float acc[MI][NI][4];
#pragma unroll
    for (int i = 0; i < MI; i++)
#pragma unroll
        for (int j = 0; j < NI; j++)
#pragma unroll
            for (int r = 0; r < 4; r++) acc[i][j][r] = 0.f;

    auto loadA = [&](int buf, int k0) {
        __half* dst = As + buf * ASZ;
#pragma unroll
        for (int i = 0; i < BM/64; i++) {
            const int c = tid + i * 256;
            const int r = c >> 2, c16 = c & 3;
            cp16h(dst + r * 40 + c16 * 8, Ab + (size_t)(m0 + r) * lda + k0 + c16 * 8);
        }
    };
    auto loadB = [&](int buf, int k0) {
        __half* dst = Bs + buf * BSZ;
#pragma unroll
        for (int i = 0; i < BN/64; i++) {
            const int c = tid + i * 256;
            const int r = c >> 2, c16 = c & 3;
            cp16h(dst + r * 40 + c16 * 8, Bb + (size_t)(n0 + r) * ldb + k0 + c16 * 8);
        }
    };

    const int ntiles = K >> 5;
    loadA(0, 0); loadB(0, 0); CP_COMMIT();
    for (int t = 0; t < ntiles; t++) {
        const int cur = t & 1;
        if (t + 1 < ntiles) {
            loadA(cur ^ 1, (t + 1) << 5);
            loadB(cur ^ 1, (t + 1) << 5);
            CP_COMMIT();
            CP_WAIT(1);
        } else {
            CP_WAIT(0);
        }
        __syncthreads();
        const uint32_t aB = As_u + cur * ASZ * 2;
        const uint32_t bB = Bs_u + cur * BSZ * 2;
#pragma unroll
        for (int kc = 0; kc < 2; kc++) {
            const uint32_t kk = kc * 32;
            uint32_t af[MI][4], bf[NI][2], bt[4];
#pragma unroll
            for (int mi = 0; mi < MI; mi++)
                ldm4(af[mi], aB + aoff + kk + mi * 16*40*2);
#pragma unroll
            for (int p = 0; p < NI/2; p++) {
                ldm4(bt, bB + boff + kk + p * 16*40*2);
                bf[2*p][0]=bt[0]; bf[2*p][1]=bt[1]; bf[2*p+1][0]=bt[2]; bf[2*p+1][1]=bt[3];
            }
#pragma unroll
            for (int mi = 0; mi < MI; mi++)
#pragma unroll
                for (int ni = 0; ni < NI; ni++)
                    mma_f16(acc[mi][ni], af[mi], bf[ni]);
        }
        __syncthreads();
    }

#pragma unroll
    for (int mi = 0; mi < MI; mi++)
#pragma unroll
        for (int ni = 0; ni < NI; ni++)
#pragma unroll
            for (int hh = 0; hh < 2; hh++) {
                const int row = m0 + wm + mi*16 + lr + hh*8;
                const int col = n0 + wn + ni*8  + lc*2;
                const float v0 = acc[mi][ni][hh*2+0];
                const float v1 = acc[mi][ni][hh*2+1];
                if (epi == 0) {
                    __half* Ch = (__half*)Cv + (size_t)blockIdx.z * Cz;
                    *(__half2*)(Ch + (size_t)row * ldc + col) = __floats2half2_rn(v0, v1);
                } else if (epi == 1) {
                    float* Cf = (float*)Cv + (size_t)blockIdx.z * Cz;
                    const size_t o = (size_t)row * ldc + col;
                    *(float2*)(Cf + o) = make_float2(R[o] + v0, R[o+1] + v1);
                } else {
                    float* Cf = (float*)Cv + (size_t)blockIdx.z * Cz;
                    *(float2*)(Cf + (size_t)row * ldc + col) = make_float2(v0, v1);
                }
            }
}

// ---- fused FFN fp16 (validated) ----
#define FFNH_SMEM ((2*128*40 + 2*64*40 + 2*64*40) * 2)
__global__ void __launch_bounds__(256) gemm_ffn_h(
    const __half* __restrict__ A, const __half* __restrict__ W1, const __half* __restrict__ W2,
    __half* __restrict__ C)
{
    extern __shared__ __half smh[];
    __half* As  = smh;
    __half* Bs1 = smh + 2*5120;
    __half* Bs2 = Bs1 + 2*2560;

    const int tid  = threadIdx.x;
    const int lane = tid & 31, warp = tid >> 5;
    const int wm = (warp & 3) * 32, wn = (warp >> 2) * 32;
    const int lr = lane >> 2, lc = lane & 3;
    const int g8 = lane >> 3, r8 = lane & 7;
    const int m0 = blockIdx.y * 128, n0 = blockIdx.x * 64;

    const uint32_t As_u  = (uint32_t)__cvta_generic_to_shared(As);
    const uint32_t Bs1_u = (uint32_t)__cvta_generic_to_shared(Bs1);
    const uint32_t Bs2_u = (uint32_t)__cvta_generic_to_shared(Bs2);
    const uint32_t aoff = ((wm + (g8 & 1) * 8 + r8) * 40 + (g8 >> 1) * 8) * 2;
    const uint32_t boff = ((wn + (g8 >> 1) * 8 + r8) * 40 + (g8 & 1) * 8) * 2;

    float a1[2][4][4], a2[2][4][4];
#pragma unroll
    for (int i = 0; i < 2; i++)
#pragma unroll
        for (int j = 0; j < 4; j++)
#pragma unroll
            for (int r = 0; r < 4; r++) { a1[i][j][r] = 0.f; a2[i][j][r] = 0.f; }

    auto loadA = [&](int buf, int k0) {
        __half* dst = As + buf * 5120;
#pragma unroll
        for (int i = 0; i < 2; i++) {
            const int c = tid + i * 256;
            const int r = c >> 2, c16 = c & 3;
            cp16h(dst + r * 40 + c16 * 8, A + (size_t)(m0 + r) * H + k0 + c16 * 8);
        }
    };
    auto loadB = [&](int buf, int k0) {
        const int r = tid >> 2, c16 = tid & 3;
        cp16h(Bs1 + buf * 2560 + r * 40 + c16 * 8, W1 + (size_t)(n0 + r) * H + k0 + c16 * 8);
        cp16h(Bs2 + buf * 2560 + r * 40 + c16 * 8, W2 + (size_t)(n0 + r) * H + k0 + c16 * 8);
    };

    loadA(0, 0); loadB(0, 0); CP_COMMIT();
    for (int t = 0; t < 32; t++) {
        const int cur = t & 1;
        if (t + 1 < 32) {
            loadA(cur ^ 1, (t + 1) << 5);
            loadB(cur ^ 1, (t + 1) << 5);
            CP_COMMIT();
            CP_WAIT(1);
        } else {
            CP_WAIT(0);
        }
        __syncthreads();
        const uint32_t aB  = As_u  + cur * 5120 * 2;
        const uint32_t b1B = Bs1_u + cur * 2560 * 2;
        const uint32_t b2B = Bs2_u + cur * 2560 * 2;
#pragma unroll
        for (int kc = 0; kc < 2; kc++) {
            const uint32_t kk = kc * 32;
            uint32_t af[2][4], b1f[4][2], b2f[4][2], bt[4];
            ldm4(af[0], aB + aoff + kk);
            ldm4(af[1], aB + aoff + kk + 16*40*2);
#pragma unroll
            for (int p = 0; p < 2; p++) {
                ldm4(bt, b1B + boff + kk + p * 16*40*2);
                b1f[2*p][0]=bt[0]; b1f[2*p][1]=bt[1]; b1f[2*p+1][0]=bt[2]; b1f[2*p+1][1]=bt[3];
                ldm4(bt, b2B + boff + kk + p * 16*40*2);
                b2f[2*p][0]=bt[0]; b2f[2*p][1]=bt[1]; b2f[2*p+1][0]=bt[2]; b2f[2*p+1][1]=bt[3];
            }
#pragma unroll
            for (int mi = 0; mi < 2; mi++)
#pragma unroll
                for (int ni = 0; ni < 4; ni++) {
                    mma_f16(a1[mi][ni], af[mi], b1f[ni]);
                    mma_f16(a2[mi][ni], af[mi], b2f[ni]);
                }
        }
        __syncthreads();
    }
#pragma unroll
    for (int mi = 0; mi < 2; mi++)
#pragma unroll
        for (int ni = 0; ni < 4; ni++)
#pragma unroll
            for (int hh = 0; hh < 2; hh++) {
                const int row = m0 + wm + mi*16 + lr + hh*8;
                const int col = n0 + wn + ni*8  + lc*2;
                const float x0 = a1[mi][ni][hh*2],  x1 = a1[mi][ni][hh*2+1];
                const float g0 = x0 / (1.f + __expf(-x0));
                const float g1 = x1 / (1.f + __expf(-x1));
                *(__half2*)(C + (size_t)row * FFN_D + col) =
                    __floats2half2_rn(g0 * a2[mi][ni][hh*2], g1 * a2[mi][ni][hh*2+1]);
            }
}

// ---- w3 fp16 (BM64/BN128, split-K via z, float partials; validated) ----
#define W3H_SMEM ((2*64*40 + 2*128*40) * 2)
__global__ void __launch_bounds__(256) gemm_w3_h(
    const __half* __restrict__ A, const __half* __restrict__ B, float* __restrict__ P)
{
    extern __shared__ __half smh[];
    __half* As = smh;
    __half* Bs = smh + 2*2560;

    const int tid  = threadIdx.x;
    const int lane = tid & 31, warp = tid >> 5;
    const int wm = (warp & 1) * 32, wn = (warp >> 1) * 32;
    const int lr = lane >> 2, lc = lane & 3;
    const int g8 = lane >> 3, r8 = lane & 7;
    const int m0 = blockIdx.y * 64, n0 = blockIdx.x * 128;
    const int z  = blockIdx.z;
    const __half* Ab = A + z * 2048;
    const __half* Bb = B + z * 2048;
    float* Pb = P + (size_t)z * M1 * H;

    const uint32_t As_u = (uint32_t)__cvta_generic_to_shared(As);
    const uint32_t Bs_u = (uint32_t)__cvta_generic_to_shared(Bs);
    const uint32_t aoff = ((wm + (g8 & 1) * 8 + r8) * 40 + (g8 >> 1) * 8) * 2;
    const uint32_t boff = ((wn + (g8 >> 1) * 8 + r8) * 40 + (g8 & 1) * 8) * 2;

    float acc[2][4][4];
#pragma unroll
    for (int i = 0; i < 2; i++)
#pragma unroll
        for (int j = 0; j < 4; j++)
#pragma unroll
            for (int r = 0; r < 4; r++) acc[i][j][r] = 0.f;

    auto loadA = [&](int buf, int k0) {
        const int r = tid >> 2, c16 = tid & 3;
        cp16h(As + buf * 2560 + r * 40 + c16 * 8, Ab + (size_t)(m0 + r) * FFN_D + k0 + c16 * 8);
    };
    auto loadB = [&](int buf, int k0) {
        __half* dst = Bs + buf * 5120;
#pragma unroll
        for (int i = 0; i < 2; i++) {
            const int c = tid + i * 256;
            const int r = c >> 2, c16 = c & 3;
            cp16h(dst + r * 40 + c16 * 8, Bb + (size_t)(n0 + r) * FFN_D + k0 + c16 * 8);
        }
    };

    loadA(0, 0); loadB(0, 0); CP_COMMIT();
    for (int t = 0; t < 64; t++) {
        const int cur = t & 1;
        if (t + 1 < 64) {
            loadA(cur ^ 1, (t + 1) << 5);
            loadB(cur ^ 1, (t + 1) << 5);
            CP_COMMIT();
            CP_WAIT(1);
        } else {
            CP_WAIT(0);
        }
        __syncthreads();
        const uint32_t aB = As_u + cur * 2560 * 2;
        const uint32_t bB = Bs_u + cur * 5120 * 2;
#pragma unroll
        for (int kc = 0; kc < 2; kc++) {
            const uint32_t kk = kc * 32;
            uint32_t af[2][4], bf[4][2], bt[4];
            ldm4(af[0], aB + aoff + kk);
            ldm4(af[1], aB + aoff + kk + 16*40*2);
#pragma unroll
            for (int p = 0; p < 2; p++) {
                ldm4(bt, bB + boff + kk + p * 16*40*2);
                bf[2*p][0]=bt[0]; bf[2*p][1]=bt[1]; bf[2*p+1][0]=bt[2]; bf[2*p+1][1]=bt[3];
            }
#pragma unroll
            for (int mi = 0; mi < 2; mi++)
#pragma unroll
                for (int ni = 0; ni < 4; ni++)
                    mma_f16(acc[mi][ni], af[mi], bf[ni]);
        }
        __syncthreads();
    }
#pragma unroll
    for (int mi = 0; mi < 2; mi++)
#pragma unroll
        for (int ni = 0; ni < 4; ni++)
#pragma unroll
            for (int hh = 0; hh < 2; hh++) {
                const int row = m0 + wm + mi*16 + lr + hh*8;
                const int col = n0 + wn + ni*8  + lc*2;
                *(float2*)(Pb + (size_t)row * H + col) =
                    make_float2(acc[mi][ni][hh*2], acc[mi][ni][hh*2+1]);
            }
}

// ---- okv fp16 (BM128/BN128), smem-staged coalesced epilogue (validated) ----
#define OKVH_SMEM (132*128*4)
__global__ void __launch_bounds__(256) gemm_okv_h(
    const __half* __restrict__ A,
    const __half* __restrict__ BK_, const __half* __restrict__ BV_,
    float* __restrict__ OutBase)
{
    extern __shared__ char smraw[];
    __half* As = (__half*)smraw;
    __half* Bs = As + 2*5120;
    float* smf = (float*)smraw;
    const int z = blockIdx.z;
    const __half* B = z ? BV_ : BK_;
    float* Ob = OutBase + (size_t)z * 4194304;

    const int tid  = threadIdx.x;
    const int lane = tid & 31, warp = tid >> 5;
    const int wm = (warp & 1) * 64, wn = (warp >> 1) * 32;
    const int lr = lane >> 2, lc = lane & 3;
    const int g8 = lane >> 3, r8 = lane & 7;
    const int m0 = blockIdx.y * 128, n0 = blockIdx.x * 128;

    const uint32_t As_u = (uint32_t)__cvta_generic_to_shared(As);
    const uint32_t Bs_u = (uint32_t)__cvta_generic_to_shared(Bs);
    const uint32_t aoff = ((wm + (g8 & 1) * 8 + r8) * 40 + (g8 >> 1) * 8) * 2;
    const uint32_t boff = ((wn + (g8 >> 1) * 8 + r8) * 40 + (g8 & 1) * 8) * 2;

    float acc[4][4][4];
#pragma unroll
    for (int i = 0; i < 4; i++)
#pragma unroll
        for (int j = 0; j < 4; j++)
#pragma unroll
            for (int r = 0; r < 4; r++) acc[i][j][r] = 0.f;

    auto loadT = [&](int buf, int k0) {
        __half* dA = As + buf * 5120;
        __half* dB = Bs + buf * 5120;
#pragma unroll
        for (int i = 0; i < 2; i++) {
            const int c = tid + i * 256;
            const int r = c >> 2, c16 = c & 3;
            cp16h(dA + r * 40 + c16 * 8, A + (size_t)(m0 + r) * H + k0 + c16 * 8);
            cp16h(dB + r * 40 + c16 * 8, B + (size_t)(n0 + r) * H + k0 + c16 * 8);
        }
    };

    loadT(0, 0); CP_COMMIT();
    for (int t = 0; t < 32; t++) {
        const int cur = t & 1;
        if (t + 1 < 32) {
            loadT(cur ^ 1, (t + 1) << 5);
            CP_COMMIT();
            CP_WAIT(1);
        } else {
            CP_WAIT(0);
        }
        __syncthreads();
        const uint32_t aB = As_u + cur * 5120 * 2;
        const uint32_t bB = Bs_u + cur * 5120 * 2;
#pragma unroll
        for (int kc = 0; kc < 2; kc++) {
            const uint32_t kk = kc * 32;
            uint32_t af[4][4], bf[4][2], bt[4];
#pragma unroll
            for (int mi = 0; mi < 4; mi++)
                ldm4(af[mi], aB + aoff + kk + mi * 16*40*2);
#pragma unroll
            for (int p = 0; p < 2; p++) {
                ldm4(bt, bB + boff + kk + p * 16*40*2);
                bf[2*p][0]=bt[0]; bf[2*p][1]=bt[1]; bf[2*p+1][0]=bt[2]; bf[2*p+1][1]=bt[3];
            }
#pragma unroll
            for (int mi = 0; mi < 4; mi++)
#pragma unroll
                for (int ni = 0; ni < 4; ni++)
                    mma_f16(acc[mi][ni], af[mi], bf[ni]);
        }
        __syncthreads();
    }

#pragma unroll
    for (int mi = 0; mi < 4; mi++)
#pragma unroll
        for (int ni = 0; ni < 4; ni++)
#pragma unroll
            for (int hh = 0; hh < 2; hh++) {
                const int rr = wm + mi*16 + lr + hh*8;
                const int cc = wn + ni*8  + lc*2;
                smf[rr*132 + cc    ] = acc[mi][ni][hh*2+0];
                smf[rr*132 + cc + 1] = acc[mi][ni][hh*2+1];
            }
    __syncthreads();
    const int l = n0 >> 10, kvh = (n0 & 1023) >> 7;
    const int bb = m0 >> 8, q0 = m0 & 255;
    float* ob = Ob + ((((size_t)l * BATCH + bb) * 8 + kvh) * NQ + q0) * 128;
#pragma unroll
    for (int i = 0; i < 16; i++) {
        const int idx = tid + i * 256;
        const int q = idx >> 5, c4 = (idx & 31) * 4;
        *(float4*)(ob + q*128 + c4) = *(const float4*)(smf + q*132 + c4);
    }
}

// ---- split-K(2) reduce for w3 ----
__global__ void reduce_w3(const float* __restrict__ P, const float* __restrict__ R,
                          __half* __restrict__ Ch, float* __restrict__ C2)
{
    const int i = blockIdx.x * 256 + threadIdx.x;
    const float4 a = ((const float4*)P)[i];
    const float4 b = ((const float4*)(P + M1*H))[i];
    const float4 r = ((const float4*)R)[i];
    float4 o;
    o.x = r.x + a.x + b.x;
    o.y = r.y + a.y + b.y;
    o.z = r.z + a.z + b.z;
    o.w = r.w + a.w + b.w;
    ((float4*)C2)[i] = o;
    __half2* ch2 = (__half2*)Ch;
    ch2[2*i    ] = __floats2half2_rn(o.x, o.y);
    ch2[2*i + 1] = __floats2half2_rn(o.z, o.w);
}

// ---------------- tensor-core self-attention (fp16, one block per (b,h,q64)) ----------------
// S = Q@K^T (m64 x n256 x k64), softmax, O = P@V (m64 x n64 x k256).
#define SATTH_SMEM (9216 + 36864 + 33792 + 18432 + 1024)
__global__ void __launch_bounds__(256) self_attn_h(
    const __half* __restrict__ QKV, __half* __restrict__ O)
{
    extern __shared__ char smraw[];
    __half* Qs = (__half*)smraw;                              // [64][72]
    __half* Ks = (__half*)(smraw + 9216);                     // [256][72]
    __half* Vt = (__half*)(smraw + 9216 + 36864);             // [64][264] (V transposed: d-major)
    float*  Of = (float*)(smraw + 9216 + 36864 + 33792);      // [64][72]
    float*  rstat = (float*)(smraw + 9216 + 36864 + 33792 + 18432); // [2 stats][2 wn][64]

    const int tid = threadIdx.x, lane = tid & 31, warp = tid >> 5;
    const int wm = warp & 3, wn = warp >> 2;          // 4 m-groups x 2 n-groups
    const int lr = lane >> 2, lc = lane & 3;
    const int g8 = lane >> 3, r8 = lane & 7;
    const int bh = blockIdx.y;
    const int b = bh >> 4, h = bh & 15;
    const int q0 = blockIdx.x * 64;
    const size_t base = ((size_t)b * NQ) * H + h * HDIM;
    const __half* Qg = QKV + base;
    const __half* Kg = QKV + (size_t)M1 * H + base;
    const __half* Vg = QKV + 2 * (size_t)M1 * H + base;

    // stage Q (64x64) and K (256x64), rows padded to 72 halfs
    for (int i = tid; i < 512; i += 256) {
        const int r = i >> 3, c = (i & 7) * 8;
        cp16h(Qs + r * 72 + c, Qg + (size_t)(q0 + r) * H + c);
    }
    for (int i = tid; i < 2048; i += 256) {
        const int r = i >> 3, c = (i & 7) * 8;
        cp16h(Ks + r * 72 + c, Kg + (size_t)r * H + c);
    }
    CP_COMMIT(); CP_WAIT(0);
    __syncthreads();
    // stage V transposed: Vt[d][kv], coalesced global reads
    for (int i = tid; i < 8192; i += 256) {
        const int j = i & 31, kv = i >> 5;            // j = d-pair
        const __half2 v = *(const __half2*)(Vg + (size_t)kv * H + 2 * j);
        Vt[(2*j    ) * 264 + kv] = __low2half(v);
        Vt[(2*j + 1) * 264 + kv] = __high2half(v);
    }
    __syncthreads();

    const uint32_t Qs_u = (uint32_t)__cvta_generic_to_shared(Qs);
    const uint32_t Ks_u = (uint32_t)__cvta_generic_to_shared(Ks);
    const uint32_t Vt_u = (uint32_t)__cvta_generic_to_shared(Vt);
    const uint32_t qoff = ((wm * 16 + (g8 & 1) * 8 + r8) * 72 + (g8 >> 1) * 8) * 2;
    const uint32_t koff = ((wn * 128 + (g8 >> 1) * 8 + r8) * 72 + (g8 & 1) * 8) * 2;
    const uint32_t voff = (((g8 >> 1) * 8 + r8) * 264 + (g8 & 1) * 8 + wn * 128) * 2;

    // S = Q @ K^T : warp tile m16 x n128
    float sacc[16][4];
#pragma unroll
    for (int t = 0; t < 16; t++)
#pragma unroll
        for (int r = 0; r < 4; r++) sacc[t][r] = 0.f;
#pragma unroll
    for (int kc = 0; kc < 4; kc++) {
        uint32_t af[4], bt[4];
        ldm4(af, Qs_u + qoff + kc * 32);
#pragma unroll
        for (int p = 0; p < 8; p++) {
            ldm4(bt, Ks_u + koff + kc * 32 + p * 16*72*2);
            uint32_t b0[2] = {bt[0], bt[1]}, b1[2] = {bt[2], bt[3]};
            mma_f16(sacc[2*p    ], af, b0);
            mma_f16(sacc[2*p + 1], af, b1);
        }
    }

    // scale + row max (rows lr and lr+8 of warp's m16)
    float mx0 = -1e30f, mx1 = -1e30f;
#pragma unroll
    for (int t = 0; t < 16; t++) {
#pragma unroll
        for (int r = 0; r < 4; r++) sacc[t][r] *= 0.125f;
        mx0 = fmaxf(mx0, fmaxf(sacc[t][0], sacc[t][1]));
        mx1 = fmaxf(mx1, fmaxf(sacc[t][2], sacc[t][3]));
    }
    mx0 = fmaxf(mx0, __shfl_xor_sync(~0u, mx0, 1)); mx0 = fmaxf(mx0, __shfl_xor_sync(~0u, mx0, 2));
    mx1 = fmaxf(mx1, __shfl_xor_sync(~0u, mx1, 1)); mx1 = fmaxf(mx1, __shfl_xor_sync(~0u, mx1, 2));
    if (lc == 0) {
        rstat[wn * 64 + wm * 16 + lr    ] = mx0;
        rstat[wn * 64 + wm * 16 + lr + 8] = mx1;
    }
    __syncthreads();
    const float m0 = fmaxf(rstat[wm*16 + lr    ], rstat[64 + wm*16 + lr    ]);
    const float m1 = fmaxf(rstat[wm*16 + lr + 8], rstat[64 + wm*16 + lr + 8]);

    // exp + row sum
    float sm0 = 0.f, sm1 = 0.f;
#pragma unroll
    for (int t = 0; t < 16; t++) {
        sacc[t][0] = __expf(sacc[t][0] - m0);
        sacc[t][1] = __expf(sacc[t][1] - m0);
        sacc[t][2] = __expf(sacc[t][2] - m1);
        sacc[t][3] = __expf(sacc[t][3] - m1);
        sm0 += sacc[t][0] + sacc[t][1];
        sm1 += sacc[t][2] + sacc[t][3];
    }
    sm0 += __shfl_xor_sync(~0u, sm0, 1); sm0 += __shfl_xor_sync(~0u, sm0, 2);
    sm1 += __shfl_xor_sync(~0u, sm1, 1); sm1 += __shfl_xor_sync(~0u, sm1, 2);
    if (lc == 0) {
        rstat[128 + wn * 64 + wm * 16 + lr    ] = sm0;
        rstat[128 + wn * 64 + wm * 16 + lr + 8] = sm1;
    }

    // O_partial = P @ V  (m16 x n64 over warp's k128)
    float oacc[8][4];
#pragma unroll
    for (int j = 0; j < 8; j++)
#pragma unroll
        for (int r = 0; r < 4; r++) oacc[j][r] = 0.f;
#pragma unroll
    for (int c = 0; c < 8; c++) {           // k16 chunks
        uint32_t pa[4];
        pa[0] = pack_h2(sacc[2*c    ][0], sacc[2*c    ][1]);
        pa[1] = pack_h2(sacc[2*c    ][2], sacc[2*c    ][3]);
        pa[2] = pack_h2(sacc[2*c + 1][0], sacc[2*c + 1][1]);
        pa[3] = pack_h2(sacc[2*c + 1][2], sacc[2*c + 1][3]);
#pragma unroll
        for (int p = 0; p < 4; p++) {       // d n16-groups
            uint32_t bt[4];
            ldm4(bt, Vt_u + voff + c * 32 + p * 16*264*2);
            uint32_t b0[2] = {bt[0], bt[1]}, b1[2] = {bt[2], bt[3]};
            mma_f16(oacc[2*p    ], pa, b0);
            mma_f16(oacc[2*p + 1], pa, b1);
        }
    }

    // combine wn pair partials in Of, then write out with 1/sum
    __syncthreads();   // rstat sums written; Of region free
    if (wn == 0) {
#pragma unroll
        for (int j = 0; j < 8; j++) {
            const int col = 8*j + 2*lc;
            Of[(wm*16 + lr    ) * 72 + col    ] = oacc[j][0];
            Of[(wm*16 + lr    ) * 72 + col + 1] = oacc[j][1];
            Of[(wm*16 + lr + 8) * 72 + col    ] = oacc[j][2];
            Of[(wm*16 + lr + 8) * 72 + col + 1] = oacc[j][3];
        }
    }
    __syncthreads();
    if (wn == 1) {
#pragma unroll
        for (int j = 0; j < 8; j++) {
            const int col = 8*j + 2*lc;
            Of[(wm*16 + lr    ) * 72 + col    ] += oacc[j][0];
            Of[(wm*16 + lr    ) * 72 + col + 1] += oacc[j][1];
            Of[(wm*16 + lr + 8) * 72 + col    ] += oacc[j][2];
            Of[(wm*16 + lr + 8) * 72 + col + 1] += oacc[j][3];
        }
    }
    __syncthreads();
    for (int i = tid; i < 2048; i += 256) {
        const int row = i >> 5, c2 = (i & 31) * 2;
        const float inv = 1.f / (rstat[128 + row] + rstat[128 + 64 + row]);
        *(__half2*)(O + base + (size_t)(q0 + row) * H + c2) =
            __floats2half2_rn(Of[row*72 + c2] * inv, Of[row*72 + c2 + 1] * inv);
    }
}

// ---------------- fused windowed cross-attention core (bf16 staging; half hbar out) ----------------
#define SCORE_SMEM (36*1024*2 + 2*1024*4)
__global__ void __launch_bounds__(512) cross_score_kernel(
    const __nv_bfloat16* __restrict__ qk, const float* __restrict__ hs,
    const float* __restrict__ g, const float* __restrict__ b,
    __half* __restrict__ hbar)
{
    extern __shared__ char smraw[];
    __nv_bfloat16* srows = (__nv_bfloat16*)smraw;        // [36][1024] bf16
    float* sg = (float*)(smraw + 36*1024*2);
    float* sb = sg + 1024;
    __shared__ float sc[16*40];
    __shared__ float smu[36], srs[36];
    __shared__ int spos[36];

    const int row = blockIdx.x;      // b*256 + q
    const int bb = row >> 8, q = row & 255;
    const int tid = threadIdx.x;
    const int base = q * 8;
    const int nj = (base + 9 <= DOC) ? 9 : (DOC - base);
    const int nkv = LAYERS * nj;

    for (int i = tid; i < 1024; i += 512) { sg[i] = g[i]; sb[i] = b[i]; }
    if (tid < nkv) { const int l = tid / nj, jj = tid - l * nj; spos[tid] = l * DOC + base + jj; }
    __syncthreads();

    for (int idx = tid; idx < nkv * 256; idx += 512) {
        const int j = idx >> 8, c4 = (idx & 255) << 2;
        const int gr = bb * KVLEN + spos[j];
        const float4 v = *(const float4*)(hs + (size_t)gr * H + c4);
        __nv_bfloat162* d = (__nv_bfloat162*)(srows + (j << 10) + c4);
        d[0] = __floats2bfloat162_rn(v.x, v.y);
        d[1] = __floats2bfloat162_rn(v.z, v.w);
    }
    __syncthreads();

    const int w = tid >> 5, lane = tid & 31;
    for (int j = w; j < nkv; j += 16) {
        const __nv_bfloat162* r2 = (const __nv_bfloat162*)(srows + (j << 10));
        float s = 0.f, s2 = 0.f;
#pragma unroll
        for (int i = 0; i < 16; i++) {
            const float2 v = __bfloat1622float2(r2[lane + 32*i]);
            s += v.x + v.y; s2 += v.x*v.x + v.y*v.y;
        }
#pragma unroll
        for (int o = 16; o > 0; o >>= 1) { s += __shfl_xor_sync(~0u, s, o); s2 += __shfl_xor_sync(~0u, s2, o); }
        if (lane == 0) {
            const float mu = s * (1.f / H);
            smu[j] = mu;
            srs[j] = rsqrtf(s2 * (1.f / H) - mu * mu + 1e-5f);
        }
    }
    __syncthreads();

    for (int idx = tid; idx < nkv * 512; idx += 512) {
        const int j = idx >> 9, p = idx & 511;
        const float mu = smu[j], rs = srs[j];
        __nv_bfloat162* d = (__nv_bfloat162*)(srows + (j << 10)) + p;
        float2 v = __bfloat1622float2(*d);
        v.x = (v.x - mu) * rs * sg[2*p  ] + sb[2*p  ];
        v.y = (v.y - mu) * rs * sg[2*p+1] + sb[2*p+1];
        *d = __floats2bfloat162_rn(v.x, v.y);
    }
    __syncthreads();

    float2 qv[16];
    const __nv_bfloat162* qrow2 = (const __nv_bfloat162*)(qk + ((size_t)w * M1 + row) * H);
#pragma unroll
    for (int i = 0; i < 16; i++) qv[i] = __bfloat1622float2(qrow2[lane + 32*i]);
    for (int j = 0; j < nkv; j++) {
        const __nv_bfloat162* r2 = (const __nv_bfloat162*)(srows + (j << 10));
        float s = 0.f;
#pragma unroll
        for (int i = 0; i < 16; i++) {
            const float2 v = __bfloat1622float2(r2[lane + 32*i]);
            s += qv[i].x * v.x + qv[i].y * v.y;
        }
#pragma unroll
        for (int o = 16; o > 0; o >>= 1) s += __shfl_xor_sync(~0u, s, o);
        if (lane == 0) sc[w*40 + j] = s * 0.125f;
    }
    __syncthreads();

    {
        float v0 = (lane      < nkv) ? sc[w*40 + lane     ] : -1e30f;
        float v1 = (lane + 32 < nkv) ? sc[w*40 + lane + 32] : -1e30f;
        float m = fmaxf(v0, v1);
#pragma unroll
        for (int o = 16; o > 0; o >>= 1) m = fmaxf(m, __shfl_xor_sync(~0u, m, o));
        float e0 = (lane      < nkv) ? __expf(v0 - m) : 0.f;
        float e1 = (lane + 32 < nkv) ? __expf(v1 - m) : 0.f;
        float su = e0 + e1;
#pragma unroll
        for (int o = 16; o > 0; o >>= 1) su += __shfl_xor_sync(~0u, su, o);
        const float inv = 1.f / su;
        if (lane      < nkv) sc[w*40 + lane     ] = e0 * inv;
        if (lane + 32 < nkv) sc[w*40 + lane + 32] = e1 * inv;
    }
    __syncthreads();

    float acc[16][2];
#pragma unroll
    for (int h = 0; h < 16; h++) { acc[h][0] = 0.f; acc[h][1] = 0.f; }
    for (int j = 0; j < nkv; j++) {
        const float2 v = __bfloat1622float2(((const __nv_bfloat162*)(srows + (j << 10)))[tid]);
#pragma unroll
        for (int h = 0; h < 16; h++) {
            const float p = sc[h*40 + j];
            acc[h][0] += p * v.x;
            acc[h][1] += p * v.y;
        }
    }
    const int c0 = tid * 2;
#pragma unroll
    for (int h = 0; h < 16; h++)
        *(__half2*)(hbar + ((size_t)h * M1 + row) * H + c0) =
            __floats2half2_rn(acc[h][0], acc[h][1]);
}

// ---------------- launch ----------------
extern "C" void kernel_launch(void* const* d_in, const int* in_sizes, int n_in,
                              void* d_out_, int out_size)
{
    (void)in_sizes; (void)n_in; (void)out_size;
    const float* qtok = (const float*)d_in[0];
    const float* hs   = (const float*)d_in[1];
    const float* ln1g = (const float*)d_in[2];
    const float* ln1b = (const float*)d_in[3];
    const float* ln2g = (const float*)d_in[4];
    const float* ln2b = (const float*)d_in[5];
    const float* lnkvg= (const float*)d_in[6];
    const float* lnkvb= (const float*)d_in[7];
    const float* lnfg = (const float*)d_in[8];
    const float* lnfb = (const float*)d_in[9];
    const float* wqs  = (const float*)d_in[10];
    const float* wks  = (const float*)d_in[11];
    const float* wvs  = (const float*)d_in[12];
    const float* wos  = (const float*)d_in[13];
    const float* wqc  = (const float*)d_in[14];
    const float* wkc  = (const float*)d_in[15];
    const float* wvc  = (const float*)d_in[16];
    const float* woc  = (const float*)d_in[17];
    const float* w1   = (const float*)d_in[18];
    const float* w2   = (const float*)d_in[19];
    const float* w3   = (const float*)d_in[20];
    const float* okw  = (const float*)d_in[21];
    const float* ovw  = (const float*)d_in[22];
    float* out = (float*)d_out_;

    void* p;
    cudaGetSymbolAddress(&p, g_qb);    float*  qb   = (float*)p;
    cudaGetSymbolAddress(&p, g_qt1);   float*  qt1  = (float*)p;
    cudaGetSymbolAddress(&p, g_qt2);   float*  qt2  = (float*)p;
    cudaGetSymbolAddress(&p, g_qk);    float*  qk   = (float*)p;
    cudaGetSymbolAddress(&p, g_qkvh);  __half* qkvh = (__half*)p;
    cudaGetSymbolAddress(&p, g_hbarh); __half* hbarh= (__half*)p;
    cudaGetSymbolAddress(&p, g_abh);   __half* abh  = (__half*)p;
    cudaGetSymbolAddress(&p, g_xlnh);  __half* xlnh = (__half*)p;
    cudaGetSymbolAddress(&p, g_h1h);   __half* h1h  = (__half*)p;
    cudaGetSymbolAddress(&p, g_qt1h);  __half* qt1h = (__half*)p;
    cudaGetSymbolAddress(&p, g_w1h);   __half* w1h  = (__half*)p;
    cudaGetSymbolAddress(&p, g_w2h);   __half* w2h  = (__half*)p;
    cudaGetSymbolAddress(&p, g_w3h);   __half* w3h  = (__half*)p;
    cudaGetSymbolAddress(&p, g_okwh);  __half* okwh = (__half*)p;
    cudaGetSymbolAddress(&p, g_ovwh);  __half* ovwh = (__half*)p;
    cudaGetSymbolAddress(&p, g_wqkvh); __half* wqkvh= (__half*)p;
    cudaGetSymbolAddress(&p, g_wosh);  __half* wosh = (__half*)p;
    cudaGetSymbolAddress(&p, g_wqch);  __half* wqch = (__half*)p;
    cudaGetSymbolAddress(&p, g_wvch);  __half* wvch = (__half*)p;
    cudaGetSymbolAddress(&p, g_woch);  __half* woch = (__half*)p;

    constexpr int S_128_64n = smem_g2(128, 64, 0, 32);
    constexpr int SH_128_64 = smem_gh(128, 64);
    constexpr int SH_64_128 = smem_gh(64, 128);
    constexpr int SH_64_64  = smem_gh(64, 64);

    cudaFuncSetAttribute(self_attn_h,        cudaFuncAttributeMaxDynamicSharedMemorySize, SATTH_SMEM);
    cudaFuncSetAttribute(cross_score_kernel, cudaFuncAttributeMaxDynamicSharedMemorySize, SCORE_SMEM);
    cudaFuncSetAttribute(gemm2<0,128,64,32>, cudaFuncAttributeMaxDynamicSharedMemorySize, S_128_64n);
    cudaFuncSetAttribute(gemm2h<128,64>,     cudaFuncAttributeMaxDynamicSharedMemorySize, SH_128_64);
    cudaFuncSetAttribute(gemm2h<64,128>,     cudaFuncAttributeMaxDynamicSharedMemorySize, SH_64_128);
    cudaFuncSetAttribute(gemm2h<64,64>,      cudaFuncAttributeMaxDynamicSharedMemorySize, SH_64_64);
    cudaFuncSetAttribute(gemm_ffn_h,         cudaFuncAttributeMaxDynamicSharedMemorySize, FFNH_SMEM);
    cudaFuncSetAttribute(gemm_w3_h,          cudaFuncAttributeMaxDynamicSharedMemorySize, W3H_SMEM);
    cudaFuncSetAttribute(gemm_okv_h,         cudaFuncAttributeMaxDynamicSharedMemorySize, OKVH_SMEM);

    const dim3 gQKV (H/64, M1/128, 3);        // 384
    const dim3 gHH  (H/128, M1/64, 1);        // 128
    const dim3 gFFN (FFN_D/64, M1/128, 1);    // 512
    const dim3 gQK  (H/64, M1/128, NHEADS);   // 2048
    const dim3 gVP  (1, M1/64, NHEADS);       // 256
    const dim3 gOKV (4096/128, M1/128, 2);    // 512
    const dim3 gW3  (H/128, M1/64, 2);        // 256

    // 0) all weight conversions in ONE launch
    convert_all<<<dim3(1024, 12), 256>>>(
        w1, w2, w3, okw, ovw, wqs, wks, wvs, wos, wqc, wvc, woc,
        w1h, w2h, w3h, okwh, ovwh,
        wqkvh, wqkvh + (size_t)H*H, wqkvh + 2*(size_t)H*H,
        wosh, wqch, wvch, woch);

    // 1) self-attention block (fp16 GEMMs + tensor-core attention)
    ln_kernel_h<<<M1, 256>>>(qtok, ln1g, ln1b, xlnh);
    gemm2h<128,64><<<gQKV, 256, SH_128_64>>>(xlnh, H, 0, wqkvh, H, (long)H*H,
                                             qkvh, H, (long)M1*H, nullptr, H, 0);
    self_attn_h<<<dim3(4, 64), 256, SATTH_SMEM>>>(qkvh, abh);
    gemm2h<64,128><<<gHH, 256, SH_64_128>>>(abh, H, 0, wosh, H, 0,
                                            qt1, H, 0, qtok, H, 1);

    // 2) windowed cross-attention (factorized)
    ln_kernel_h<<<M1, 256>>>(qt1, ln2g, ln2b, xlnh);
    gemm2h<64,128><<<gHH, 256, SH_64_128>>>(xlnh, H, 0, wqch, H, 0,
                                            qb, H, 0, nullptr, H, 2);
    gemm2<0,128,64,32><<<gQK, 256, S_128_64n>>>(qb, H, 64, wkc, H, (long)64*H,
                                                qk, H, (long)M1*H/2, nullptr, nullptr, 64, 4);
    cross_score_kernel<<<M1, 512, SCORE_SMEM>>>((const __nv_bfloat16*)qk, hs, lnkvg, lnkvb, hbarh);
    gemm2h<64,64><<<gVP, 256, SH_64_64>>>(hbarh, H, (long)M1*H, wvch, H, (long)64*H,
                                          abh, H, 64, nullptr, H, 0);
    gemm2h<64,128><<<gHH, 256, SH_64_128>>>(abh, H, 0, woch, H, 0,
                                            qt2, H, 0, qt1, H, 1);

    // 3) SwiGLU FFN in fp16 (fused w1/w2 + silu; w3 via split-K=2 + reduce)
    ln_kernel_h<<<M1, 256>>>(qt2, lnfg, lnfb, xlnh);
    gemm_ffn_h<<<gFFN, 256, FFNH_SMEM>>>(xlnh, w1h, w2h, h1h);
    gemm_w3_h<<<gW3, 256, W3H_SMEM>>>(h1h, w3h, qk);
    reduce_w3<<<M1*H/1024, 256>>>(qk, qt2, qt1h, out);

    // 4) per-layer K/V output projections in fp16 (staged epilogue)
    gemm_okv_h<<<gOKV, 256, OKVH_SMEM>>>(qt1h, okwh, ovwh, out + (size_t)M1*H);
}

// round 17
// speedup vs baseline: 1.5870x; 1.0142x over previous
#include <cuda_runtime.h>
#include <cuda_bf16.h>
#include <cuda_fp16.h>
#include <cstdint>

#define H      1024
#define NHEADS 16
#define HDIM   64
#define NQ     256
#define BATCH  4
#define LAYERS 4
#define DOC    2048
#define KVLEN  8192
#define FFN_D  4096
#define M1     (BATCH*NQ)      /* 1024  */
#define MH     (BATCH*KVLEN)   /* 32768 */

// ---------------- device scratch ----------------
__device__ float  g_qt1 [M1*H];
__device__ float  g_qt2 [M1*H];
__device__ float  g_qk  [(size_t)NHEADS*M1*H];   // bf16 qk (low half); later w3 split-K float partials
__device__ __half g_qkvh[(size_t)3*M1*H];
__device__ __half g_qbh [M1*H];
__device__ __half g_hbarh[(size_t)NHEADS*M1*H];
__device__ __half g_abh [M1*H];
__device__ __half g_xlnh[M1*H];
__device__ __half g_h1h [(size_t)M1*FFN_D];
__device__ __half g_qt1h[M1*H];
__device__ __half g_w1h [(size_t)FFN_D*H];
__device__ __half g_w2h [(size_t)FFN_D*H];
__device__ __half g_w3h [(size_t)H*FFN_D];
__device__ __half g_okwh[(size_t)LAYERS*H*H];
__device__ __half g_ovwh[(size_t)LAYERS*H*H];
__device__ __half g_wqkvh[(size_t)3*H*H];
__device__ __half g_wosh[(size_t)H*H];
__device__ __half g_wqch[(size_t)H*H];
__device__ __half g_wkcTh[(size_t)H*H];          // transposed wkc (half): [i][o]
__device__ __half g_wvch[(size_t)H*H];
__device__ __half g_woch[(size_t)H*H];

// ---------------- helpers ----------------
__device__ __forceinline__ void mma_f16(float c[4], const uint32_t a[4], const uint32_t b[2]) {
    asm volatile(
        "mma.sync.aligned.m16n8k16.row.col.f32.f16.f16.f32 "
        "{%0,%1,%2,%3}, {%4,%5,%6,%7}, {%8,%9}, {%0,%1,%2,%3};\n"
        : "+f"(c[0]), "+f"(c[1]), "+f"(c[2]), "+f"(c[3])
        : "r"(a[0]), "r"(a[1]), "r"(a[2]), "r"(a[3]), "r"(b[0]), "r"(b[1]));
}
__device__ __forceinline__ void ldm4(uint32_t a[4], uint32_t addr) {
    asm volatile("ldmatrix.sync.aligned.m8n8.x4.shared.b16 {%0,%1,%2,%3}, [%4];\n"
                 : "=r"(a[0]), "=r"(a[1]), "=r"(a[2]), "=r"(a[3]) : "r"(addr));
}
__device__ __forceinline__ void cp16h(__half* s, const __half* g) {
    uint32_t sa = (uint32_t)__cvta_generic_to_shared(s);
    asm volatile("cp.async.cg.shared.global [%0], [%1], 16;\n" :: "r"(sa), "l"(g));
}
__device__ __forceinline__ uint32_t pack_h2(float a, float b) {
    __half2 h = __floats2half2_rn(a, b);
    return *(uint32_t*)&h;
}
#define CP_COMMIT() asm volatile("cp.async.commit_group;\n")
#define CP_WAIT(n)  asm volatile("cp.async.wait_group %0;\n" :: "n"(n))

// ---------------- single mega weight fp32 -> fp16 conversion (+ wkc transpose) ----------------
__global__ void convert_all(
    const float* s0, const float* s1, const float* s2, const float* s3,
    const float* s4, const float* s5, const float* s6, const float* s7,
    const float* s8, const float* s9, const float* s10, const float* s11,
    const float* s12,
    __half* d0, __half* d1, __half* d2, __half* d3, __half* d4, __half* d5,
    __half* d6, __half* d7, __half* d8, __half* d9, __half* d10, __half* d11,
    __half* d12)
{
    const int seg = blockIdx.y;
    if (seg == 12) {
        // transpose wkc [1024][1024] fp32 -> half, 32x32 tiles, 1024 blocks
        __shared__ __half tile[32][40];
        const int ti = blockIdx.x;
        const int tr = (ti >> 5) * 32, tc = (ti & 31) * 32;
        const int tx = threadIdx.x & 31, ty = threadIdx.x >> 5;   // 32 x 8
#pragma unroll
        for (int i = 0; i < 32; i += 8)
            tile[ty + i][tx] = __float2half_rn(s12[(size_t)(tr + ty + i) * H + tc + tx]);
        __syncthreads();
#pragma unroll
        for (int i = 0; i < 32; i += 8)
            d12[(size_t)(tc + ty + i) * H + tr + tx] = tile[tx][ty + i];
        return;
    }
    const float* s; __half* d; int n4;
    switch (seg) {
        case 0:  s = s0;  d = d0;  n4 = 1048576; break;   // w1
        case 1:  s = s1;  d = d1;  n4 = 1048576; break;   // w2
        case 2:  s = s2;  d = d2;  n4 = 1048576; break;   // w3
        case 3:  s = s3;  d = d3;  n4 = 1048576; break;   // okw
        case 4:  s = s4;  d = d4;  n4 = 1048576; break;   // ovw
        case 5:  s = s5;  d = d5;  n4 = 262144;  break;   // wqs
        case 6:  s = s6;  d = d6;  n4 = 262144;  break;   // wks
        case 7:  s = s7;  d = d7;  n4 = 262144;  break;   // wvs
        case 8:  s = s8;  d = d8;  n4 = 262144;  break;   // wos
        case 9:  s = s9;  d = d9;  n4 = 262144;  break;   // wqc
        case 10: s = s10; d = d10; n4 = 262144;  break;   // wvc
        default: s = s11; d = d11; n4 = 262144;  break;   // woc
    }
    for (int i = blockIdx.x * 256 + threadIdx.x; i < n4; i += gridDim.x * 256) {
        const float4 v = ((const float4*)s)[i];
        __half2* d2p = (__half2*)d;
        d2p[2*i    ] = __floats2half2_rn(v.x, v.y);
        d2p[2*i + 1] = __floats2half2_rn(v.z, v.w);
    }
}

// ---------------- LayerNorm with fp16 output ----------------
__global__ void ln_kernel_h(const float* __restrict__ x, const float* __restrict__ g,
                            const float* __restrict__ b, __half* __restrict__ y)
{
    __shared__ float red[16];
    const int row = blockIdx.x, tid = threadIdx.x;
    const float* xr = x + (size_t)row * H;
    float v[4]; float s = 0.f, s2 = 0.f;
#pragma unroll
    for (int i = 0; i < 4; i++) { v[i] = xr[tid + i*256]; s += v[i]; s2 += v[i]*v[i]; }
#pragma unroll
    for (int o = 16; o > 0; o >>= 1) { s += __shfl_xor_sync(~0u, s, o); s2 += __shfl_xor_sync(~0u, s2, o); }
    if ((tid & 31) == 0) { red[tid>>5] = s; red[8 + (tid>>5)] = s2; }
    __syncthreads();
    if (tid < 32) {
        s  = (tid < 8) ? red[tid]     : 0.f;
        s2 = (tid < 8) ? red[8 + tid] : 0.f;
#pragma unroll
        for (int o = 4; o > 0; o >>= 1) { s += __shfl_xor_sync(~0u, s, o); s2 += __shfl_xor_sync(~0u, s2, o); }
        if (tid == 0) { red[0] = s; red[1] = s2; }
    }
    __syncthreads();
    const float mu  = red[0] * (1.f / H);
    const float var = red[1] * (1.f / H) - mu * mu;
    const float rs  = rsqrtf(var + 1e-5f);
    __half* yr = y + (size_t)row * H;
#pragma unroll
    for (int i = 0; i < 4; i++) { int c = tid + i*256; yr[c] = __float2half_rn((v[i] - mu) * rs * g[c] + b[c]); }
}

// ================= fp16 GEMM core (m16n8k16, 2-stage, RS=40 halfs, 2x4 warp grid) =================
// C = A@B^T, B stored [N,K] half.
// epi 0: store half; epi 1: C(f32) = R + acc; epi 2: store float; epi 3: store bf16.
constexpr int smem_gh(int BM, int BN) { return (2*BM*40 + 2*BN*40) * 2; }

template<int BM, int BN>
__global__ void __launch_bounds__(256) gemm2h(
    const __half* __restrict__ A, int lda, long Az,
    const __half* __restrict__ B, int ldb, long Bz,
    void* __restrict__ Cv, int ldc, long Cz,
    const float* __restrict__ R,
    int K, int epi)
{
    extern __shared__ __half smh[];
    constexpr int ASZ = BM * 40;
    constexpr int BSZ = BN * 40;
    constexpr int MI = BM / 32;
    constexpr int NI = BN / 32;
    __half* As = smh;
    __half* Bs = smh + 2*ASZ;

    const int tid  = threadIdx.x;
    const int lane = tid & 31, warp = tid >> 5;
    const int wm = (warp & 1) * (BM/2);
    const int wn = (warp >> 1) * (BN/4);
    const int lr = lane >> 2, lc = lane & 3;
    const int g8 = lane >> 3, r8 = lane & 7;
    const int m0 = blockIdx.y * BM, n0 = blockIdx.x * BN;
    const __half* Ab = A + (size_t)blockIdx.z * Az;
    const __half* Bb = B + (size_t)blockIdx.z * Bz;

    const uint32_t As_u = (uint32_t)__cvta_generic_to_shared(As);
    const uint32_t Bs_u = (uint32_t)__cvta_generic_to_shared(Bs);
    const uint32_t aoff = ((wm + (g8 & 1) * 8 + r8) * 40 + (g8 >> 1) * 8) * 2;
    const uint32_t boff = ((wn + (g8 >> 1) * 8 + r8) * 40 + (g8 & 1) * 8) * 2;

    float acc[MI][NI][4];
#pragma unroll
    for (int i = 0; i < MI; i++)
#pragma unroll
        for (int j = 0; j < NI; j++)
#pragma unroll
            for (int r = 0; r < 4; r++) acc[i][j][r] = 0.f;

    auto loadA = [&](int buf, int k0) {
        __half* dst = As + buf * ASZ;
#pragma unroll
        for (int i = 0; i < BM/64; i++) {
            const int c = tid + i * 256;
            const int r = c >> 2, c16 = c & 3;
            cp16h(dst + r * 40 + c16 * 8, Ab + (size_t)(m0 + r) * lda + k0 + c16 * 8);
        }
    };
    auto loadB = [&](int buf, int k0) {
        __half* dst = Bs + buf * BSZ;
#pragma unroll
        for (int i = 0; i < BN/64; i++) {
            const int c = tid + i * 256;
            const int r = c >> 2, c16 = c & 3;
            cp16h(dst + r * 40 + c16 * 8, Bb + (size_t)(n0 + r) * ldb + k0 + c16 * 8);
        }
    };

    const int ntiles = K >> 5;
    loadA(0, 0); loadB(0, 0); CP_COMMIT();
    for (int t = 0; t < ntiles; t++) {
        const int cur = t & 1;
        if (t + 1 < ntiles) {
            loadA(cur ^ 1, (t + 1) << 5);
            loadB(cur ^ 1, (t + 1) << 5);
            CP_COMMIT();
            CP_WAIT(1);
        } else {
            CP_WAIT(0);
        }
        __syncthreads();
        const uint32_t aB = As_u + cur * ASZ * 2;
        const uint32_t bB = Bs_u + cur * BSZ * 2;
#pragma unroll
        for (int kc = 0; kc < 2; kc++) {
            const uint32_t kk = kc * 32;
            uint32_t af[MI][4], bf[NI][2], bt[4];
#pragma unroll
            for (int mi = 0; mi < MI; mi++)
                ldm4(af[mi], aB + aoff + kk + mi * 16*40*2);
#pragma unroll
            for (int p = 0; p < NI/2; p++) {
                ldm4(bt, bB + boff + kk + p * 16*40*2);
                bf[2*p][0]=bt[0]; bf[2*p][1]=bt[1]; bf[2*p+1][0]=bt[2]; bf[2*p+1][1]=bt[3];
            }
#pragma unroll
            for (int mi = 0; mi < MI; mi++)
#pragma unroll
                for (int ni = 0; ni < NI; ni++)
                    mma_f16(acc[mi][ni], af[mi], bf[ni]);
        }
        __syncthreads();
    }

#pragma unroll
    for (int mi = 0; mi < MI; mi++)
#pragma unroll
        for (int ni = 0; ni < NI; ni++)
#pragma unroll
            for (int hh = 0; hh < 2; hh++) {
                const int row = m0 + wm + mi*16 + lr + hh*8;
                const int col = n0 + wn + ni*8  + lc*2;
                const float v0 = acc[mi][ni][hh*2+0];
                const float v1 = acc[mi][ni][hh*2+1];
                if (epi == 0) {
                    __half* Ch = (__half*)Cv + (size_t)blockIdx.z * Cz;
                    *(__half2*)(Ch + (size_t)row * ldc + col) = __floats2half2_rn(v0, v1);
                } else if (epi == 1) {
                    float* Cf = (float*)Cv + (size_t)blockIdx.z * Cz;
                    const size_t o = (size_t)row * ldc + col;
                    *(float2*)(Cf + o) = make_float2(R[o] + v0, R[o+1] + v1);
                } else if (epi == 3) {
                    __nv_bfloat16* Cb = (__nv_bfloat16*)Cv + (size_t)blockIdx.z * Cz;
                    *(__nv_bfloat162*)(Cb + (size_t)row * ldc + col) = __floats2bfloat162_rn(v0, v1);
                } else {
                    float* Cf = (float*)Cv + (size_t)blockIdx.z * Cz;
                    *(float2*)(Cf + (size_t)row * ldc + col) = make_float2(v0, v1);
                }
            }
}

// ---- fused FFN fp16 (validated) ----
#define FFNH_SMEM ((2*128*40 + 2*64*40 + 2*64*40) * 2)
__global__ void __launch_bounds__(256) gemm_ffn_h(
    const __half* __restrict__ A, const __half* __restrict__ W1, const __half* __restrict__ W2,
    __half* __restrict__ C)
{
    extern __shared__ __half smh[];
    __half* As  = smh;
    __half* Bs1 = smh + 2*5120;
    __half* Bs2 = Bs1 + 2*2560;

    const int tid  = threadIdx.x;
    const int lane = tid & 31, warp = tid >> 5;
    const int wm = (warp & 3) * 32, wn = (warp >> 2) * 32;
    const int lr = lane >> 2, lc = lane & 3;
    const int g8 = lane >> 3, r8 = lane & 7;
    const int m0 = blockIdx.y * 128, n0 = blockIdx.x * 64;

    const uint32_t As_u  = (uint32_t)__cvta_generic_to_shared(As);
    const uint32_t Bs1_u = (uint32_t)__cvta_generic_to_shared(Bs1);
    const uint32_t Bs2_u = (uint32_t)__cvta_generic_to_shared(Bs2);
    const uint32_t aoff = ((wm + (g8 & 1) * 8 + r8) * 40 + (g8 >> 1) * 8) * 2;
    const uint32_t boff = ((wn + (g8 >> 1) * 8 + r8) * 40 + (g8 & 1) * 8) * 2;

    float a1[2][4][4], a2[2][4][4];
#pragma unroll
    for (int i = 0; i < 2; i++)
#pragma unroll
        for (int j = 0; j < 4; j++)
#pragma unroll
            for (int r = 0; r < 4; r++) { a1[i][j][r] = 0.f; a2[i][j][r] = 0.f; }

    auto loadA = [&](int buf, int k0) {
        __half* dst = As + buf * 5120;
#pragma unroll
        for (int i = 0; i < 2; i++) {
            const int c = tid + i * 256;
            const int r = c >> 2, c16 = c & 3;
            cp16h(dst + r * 40 + c16 * 8, A + (size_t)(m0 + r) * H + k0 + c16 * 8);
        }
    };
    auto loadB = [&](int buf, int k0) {
        const int r = tid >> 2, c16 = tid & 3;
        cp16h(Bs1 + buf * 2560 + r * 40 + c16 * 8, W1 + (size_t)(n0 + r) * H + k0 + c16 * 8);
        cp16h(Bs2 + buf * 2560 + r * 40 + c16 * 8, W2 + (size_t)(n0 + r) * H + k0 + c16 * 8);
    };

    loadA(0, 0); loadB(0, 0); CP_COMMIT();
    for (int t = 0; t < 32; t++) {
        const int cur = t & 1;
        if (t + 1 < 32) {
            loadA(cur ^ 1, (t + 1) << 5);
            loadB(cur ^ 1, (t + 1) << 5);
            CP_COMMIT();
            CP_WAIT(1);
        } else {
            CP_WAIT(0);
        }
        __syncthreads();
        const uint32_t aB  = As_u  + cur * 5120 * 2;
        const uint32_t b1B = Bs1_u + cur * 2560 * 2;
        const uint32_t b2B = Bs2_u + cur * 2560 * 2;
#pragma unroll
        for (int kc = 0; kc < 2; kc++) {
            const uint32_t kk = kc * 32;
            uint32_t af[2][4], b1f[4][2], b2f[4][2], bt[4];
            ldm4(af[0], aB + aoff + kk);
            ldm4(af[1], aB + aoff + kk + 16*40*2);
#pragma unroll
            for (int p = 0; p < 2; p++) {
                ldm4(bt, b1B + boff + kk + p * 16*40*2);
                b1f[2*p][0]=bt[0]; b1f[2*p][1]=bt[1]; b1f[2*p+1][0]=bt[2]; b1f[2*p+1][1]=bt[3];
                ldm4(bt, b2B + boff + kk + p * 16*40*2);
                b2f[2*p][0]=bt[0]; b2f[2*p][1]=bt[1]; b2f[2*p+1][0]=bt[2]; b2f[2*p+1][1]=bt[3];
            }
#pragma unroll
            for (int mi = 0; mi < 2; mi++)
#pragma unroll
                for (int ni = 0; ni < 4; ni++) {
                    mma_f16(a1[mi][ni], af[mi], b1f[ni]);
                    mma_f16(a2[mi][ni], af[mi], b2f[ni]);
                }
        }
        __syncthreads();
    }
#pragma unroll
    for (int mi = 0; mi < 2; mi++)
#pragma unroll
        for (int ni = 0; ni < 4; ni++)
#pragma unroll
            for (int hh = 0; hh < 2; hh++) {
                const int row = m0 + wm + mi*16 + lr + hh*8;
                const int col = n0 + wn + ni*8  + lc*2;
                const float x0 = a1[mi][ni][hh*2],  x1 = a1[mi][ni][hh*2+1];
                const float g0 = x0 / (1.f + __expf(-x0));
                const float g1 = x1 / (1.f + __expf(-x1));
                *(__half2*)(C + (size_t)row * FFN_D + col) =
                    __floats2half2_rn(g0 * a2[mi][ni][hh*2], g1 * a2[mi][ni][hh*2+1]);
            }
}

// ---- w3 fp16 (BM64/BN128, split-K via z, float partials; validated) ----
#define W3H_SMEM ((2*64*40 + 2*128*40) * 2)
__global__ void __launch_bounds__(256) gemm_w3_h(
    const __half* __restrict__ A, const __half* __restrict__ B, float* __restrict__ P)
{
    extern __shared__ __half smh[];
    __half* As = smh;
    __half* Bs = smh + 2*2560;

    const int tid  = threadIdx.x;
    const int lane = tid & 31, warp = tid >> 5;
    const int wm = (warp & 1) * 32, wn = (warp >> 1) * 32;
    const int lr = lane >> 2, lc = lane & 3;
    const int g8 = lane >> 3, r8 = lane & 7;
    const int m0 = blockIdx.y * 64, n0 = blockIdx.x * 128;
    const int z  = blockIdx.z;
    const __half* Ab = A + z * 2048;
    const __half* Bb = B + z * 2048;
    float* Pb = P + (size_t)z * M1 * H;

    const uint32_t As_u = (uint32_t)__cvta_generic_to_shared(As);
    const uint32_t Bs_u = (uint32_t)__cvta_generic_to_shared(Bs);
    const uint32_t aoff = ((wm + (g8 & 1) * 8 + r8) * 40 + (g8 >> 1) * 8) * 2;
    const uint32_t boff = ((wn + (g8 >> 1) * 8 + r8) * 40 + (g8 & 1) * 8) * 2;

    float acc[2][4][4];
#pragma unroll
    for (int i = 0; i < 2; i++)
#pragma unroll
        for (int j = 0; j < 4; j++)
#pragma unroll
            for (int r = 0; r < 4; r++) acc[i][j][r] = 0.f;

    auto loadA = [&](int buf, int k0) {
        const int r = tid >> 2, c16 = tid & 3;
        cp16h(As + buf * 2560 + r * 40 + c16 * 8, Ab + (size_t)(m0 + r) * FFN_D + k0 + c16 * 8);
    };
    auto loadB = [&](int buf, int k0) {
        __half* dst = Bs + buf * 5120;
#pragma unroll
        for (int i = 0; i < 2; i++) {
            const int c = tid + i * 256;
            const int r = c >> 2, c16 = c & 3;
            cp16h(dst + r * 40 + c16 * 8, Bb + (size_t)(n0 + r) * FFN_D + k0 + c16 * 8);
        }
    };

    loadA(0, 0); loadB(0, 0); CP_COMMIT();
    for (int t = 0; t < 64; t++) {
        const int cur = t & 1;
        if (t + 1 < 64) {
            loadA(cur ^ 1, (t + 1) << 5);
            loadB(cur ^ 1, (t + 1) << 5);
            CP_COMMIT();
            CP_WAIT(1);
        } else {
            CP_WAIT(0);
        }
        __syncthreads();
        const uint32_t aB = As_u + cur * 2560 * 2;
        const uint32_t bB = Bs_u + cur * 5120 * 2;
#pragma unroll
        for (int kc = 0; kc < 2; kc++) {
            const uint32_t kk = kc * 32;
            uint32_t af[2][4], bf[4][2], bt[4];
            ldm4(af[0], aB + aoff + kk);
            ldm4(af[1], aB + aoff + kk + 16*40*2);
#pragma unroll
            for (int p = 0; p < 2; p++) {
                ldm4(bt, bB + boff + kk + p * 16*40*2);
                bf[2*p][0]=bt[0]; bf[2*p][1]=bt[1]; bf[2*p+1][0]=bt[2]; bf[2*p+1][1]=bt[3];
            }
#pragma unroll
            for (int mi = 0; mi < 2; mi++)
#pragma unroll
                for (int ni = 0; ni < 4; ni++)
                    mma_f16(acc[mi][ni], af[mi], bf[ni]);
        }
        __syncthreads();
    }
#pragma unroll
    for (int mi = 0; mi < 2; mi++)
#pragma unroll
        for (int ni = 0; ni < 4; ni++)
#pragma unroll
            for (int hh = 0; hh < 2; hh++) {
                const int row = m0 + wm + mi*16 + lr + hh*8;
                const int col = n0 + wn + ni*8  + lc*2;
                *(float2*)(Pb + (size_t)row * H + col) =
                    make_float2(acc[mi][ni][hh*2], acc[mi][ni][hh*2+1]);
            }
}

// ---- okv fp16 (BM128/BN128), smem-staged coalesced epilogue (validated) ----
#define OKVH_SMEM (132*128*4)
__global__ void __launch_bounds__(256) gemm_okv_h(
    const __half* __restrict__ A,
    const __half* __restrict__ BK_, const __half* __restrict__ BV_,
    float* __restrict__ OutBase)
{
    extern __shared__ char smraw[];
    __half* As = (__half*)smraw;
    __half* Bs = As + 2*5120;
    float* smf = (float*)smraw;
    const int z = blockIdx.z;
    const __half* B = z ? BV_ : BK_;
    float* Ob = OutBase + (size_t)z * 4194304;

    const int tid  = threadIdx.x;
    const int lane = tid & 31, warp = tid >> 5;
    const int wm = (warp & 1) * 64, wn = (warp >> 1) * 32;
    const int lr = lane >> 2, lc = lane & 3;
    const int g8 = lane >> 3, r8 = lane & 7;
    const int m0 = blockIdx.y * 128, n0 = blockIdx.x * 128;

    const uint32_t As_u = (uint32_t)__cvta_generic_to_shared(As);
    const uint32_t Bs_u = (uint32_t)__cvta_generic_to_shared(Bs);
    const uint32_t aoff = ((wm + (g8 & 1) * 8 + r8) * 40 + (g8 >> 1) * 8) * 2;
    const uint32_t boff = ((wn + (g8 >> 1) * 8 + r8) * 40 + (g8 & 1) * 8) * 2;

    float acc[4][4][4];
#pragma unroll
    for (int i = 0; i < 4; i++)
#pragma unroll
        for (int j = 0; j < 4; j++)
#pragma unroll
            for (int r = 0; r < 4; r++) acc[i][j][r] = 0.f;

    auto loadT = [&](int buf, int k0) {
        __half* dA = As + buf * 5120;
        __half* dB = Bs + buf * 5120;
#pragma unroll
        for (int i = 0; i < 2; i++) {
            const int c = tid + i * 256;
            const int r = c >> 2, c16 = c & 3;
            cp16h(dA + r * 40 + c16 * 8, A + (size_t)(m0 + r) * H + k0 + c16 * 8);
            cp16h(dB + r * 40 + c16 * 8, B + (size_t)(n0 + r) * H + k0 + c16 * 8);
        }
    };

    loadT(0, 0); CP_COMMIT();
    for (int t = 0; t < 32; t++) {
        const int cur = t & 1;
        if (t + 1 < 32) {
            loadT(cur ^ 1, (t + 1) << 5);
            CP_COMMIT();
            CP_WAIT(1);
        } else {
            CP_WAIT(0);
        }
        __syncthreads();
        const uint32_t aB = As_u + cur * 5120 * 2;
        const uint32_t bB = Bs_u + cur * 5120 * 2;
#pragma unroll
        for (int kc = 0; kc < 2; kc++) {
            const uint32_t kk = kc * 32;
            uint32_t af[4][4], bf[4][2], bt[4];
#pragma unroll
            for (int mi = 0; mi < 4; mi++)
                ldm4(af[mi], aB + aoff + kk + mi * 16*40*2);
#pragma unroll
            for (int p = 0; p < 2; p++) {
                ldm4(bt, bB + boff + kk + p * 16*40*2);
                bf[2*p][0]=bt[0]; bf[2*p][1]=bt[1]; bf[2*p+1][0]=bt[2]; bf[2*p+1][1]=bt[3];
            }
#pragma unroll
            for (int mi = 0; mi < 4; mi++)
#pragma unroll
                for (int ni = 0; ni < 4; ni++)
                    mma_f16(acc[mi][ni], af[mi], bf[ni]);
        }
        __syncthreads();
    }

#pragma unroll
    for (int mi = 0; mi < 4; mi++)
#pragma unroll
        for (int ni = 0; ni < 4; ni++)
#pragma unroll
            for (int hh = 0; hh < 2; hh++) {
                const int rr = wm + mi*16 + lr + hh*8;
                const int cc = wn + ni*8  + lc*2;
                smf[rr*132 + cc    ] = acc[mi][ni][hh*2+0];
                smf[rr*132 + cc + 1] = acc[mi][ni][hh*2+1];
            }
    __syncthreads();
    const int l = n0 >> 10, kvh = (n0 & 1023) >> 7;
    const int bb = m0 >> 8, q0 = m0 & 255;
    float* ob = Ob + ((((size_t)l * BATCH + bb) * 8 + kvh) * NQ + q0) * 128;
#pragma unroll
    for (int i = 0; i < 16; i++) {
        const int idx = tid + i * 256;
        const int q = idx >> 5, c4 = (idx & 31) * 4;
        *(float4*)(ob + q*128 + c4) = *(const float4*)(smf + q*132 + c4);
    }
}

// ---- split-K(2) reduce for w3 ----
__global__ void reduce_w3(const float* __restrict__ P, const float* __restrict__ R,
                          __half* __restrict__ Ch, float* __restrict__ C2)
{
    const int i = blockIdx.x * 256 + threadIdx.x;
    const float4 a = ((const float4*)P)[i];
    const float4 b = ((const float4*)(P + M1*H))[i];
    const float4 r = ((const float4*)R)[i];
    float4 o;
    o.x = r.x + a.x + b.x;
    o.y = r.y + a.y + b.y;
    o.z = r.z + a.z + b.z;
    o.w = r.w + a.w + b.w;
    ((float4*)C2)[i] = o;
    __half2* ch2 = (__half2*)Ch;
    ch2[2*i    ] = __floats2half2_rn(o.x, o.y);
    ch2[2*i + 1] = __floats2half2_rn(o.z, o.w);
}

// ---------------- tensor-core self-attention (fp16, one block per (b,h,q64)) ----------------
#define SATTH_SMEM (9216 + 36864 + 33792 + 18432 + 1024)
__global__ void __launch_bounds__(256) self_attn_h(
    const __half* __restrict__ QKV, __half* __restrict__ O)
{
    extern __shared__ char smraw[];
    __half* Qs = (__half*)smraw;                              // [64][72]
    __half* Ks = (__half*)(smraw + 9216);                     // [256][72]
    __half* Vt = (__half*)(smraw + 9216 + 36864);             // [64][264]
    float*  Of = (float*)(smraw + 9216 + 36864 + 33792);      // [64][72]
    float*  rstat = (float*)(smraw + 9216 + 36864 + 33792 + 18432);

    const int tid = threadIdx.x, lane = tid & 31, warp = tid >> 5;
    const int wm = warp & 3, wn = warp >> 2;
    const int lr = lane >> 2, lc = lane & 3;
    const int g8 = lane >> 3, r8 = lane & 7;
    const int bh = blockIdx.y;
    const int b = bh >> 4, h = bh & 15;
    const int q0 = blockIdx.x * 64;
    const size_t base = ((size_t)b * NQ) * H + h * HDIM;
    const __half* Qg = QKV + base;
    const __half* Kg = QKV + (size_t)M1 * H + base;
    const __half* Vg = QKV + 2 * (size_t)M1 * H + base;

    for (int i = tid; i < 512; i += 256) {
        const int r = i >> 3, c = (i & 7) * 8;
        cp16h(Qs + r * 72 + c, Qg + (size_t)(q0 + r) * H + c);
    }
    for (int i = tid; i < 2048; i += 256) {
        const int r = i >> 3, c = (i & 7) * 8;
        cp16h(Ks + r * 72 + c, Kg + (size_t)r * H + c);
    }
    CP_COMMIT(); CP_WAIT(0);
    __syncthreads();
    for (int i = tid; i < 8192; i += 256) {
        const int j = i & 31, kv = i >> 5;
        const __half2 v = *(const __half2*)(Vg + (size_t)kv * H + 2 * j);
        Vt[(2*j    ) * 264 + kv] = __low2half(v);
        Vt[(2*j + 1) * 264 + kv] = __high2half(v);
    }
    __syncthreads();

    const uint32_t Qs_u = (uint32_t)__cvta_generic_to_shared(Qs);
    const uint32_t Ks_u = (uint32_t)__cvta_generic_to_shared(Ks);
    const uint32_t Vt_u = (uint32_t)__cvta_generic_to_shared(Vt);
    const uint32_t qoff = ((wm * 16 + (g8 & 1) * 8 + r8) * 72 + (g8 >> 1) * 8) * 2;
    const uint32_t koff = ((wn * 128 + (g8 >> 1) * 8 + r8) * 72 + (g8 & 1) * 8) * 2;
    const uint32_t voff = (((g8 >> 1) * 8 + r8) * 264 + (g8 & 1) * 8 + wn * 128) * 2;

    float sacc[16][4];
#pragma unroll
    for (int t = 0; t < 16; t++)
#pragma unroll
        for (int r = 0; r < 4; r++) sacc[t][r] = 0.f;
#pragma unroll
    for (int kc = 0; kc < 4; kc++) {
        uint32_t af[4], bt[4];
        ldm4(af, Qs_u + qoff + kc * 32);
#pragma unroll
        for (int p = 0; p < 8; p++) {
            ldm4(bt, Ks_u + koff + kc * 32 + p * 16*72*2);
            uint32_t b0[2] = {bt[0], bt[1]}, b1[2] = {bt[2], bt[3]};
            mma_f16(sacc[2*p    ], af, b0);
            mma_f16(sacc[2*p + 1], af, b1);
        }
    }

    float mx0 = -1e30f, mx1 = -1e30f;
#pragma unroll
    for (int t = 0; t < 16; t++) {
#pragma unroll
        for (int r = 0; r < 4; r++) sacc[t][r] *= 0.125f;
        mx0 = fmaxf(mx0, fmaxf(sacc[t][0], sacc[t][1]));
        mx1 = fmaxf(mx1, fmaxf(sacc[t][2], sacc[t][3]));
    }
    mx0 = fmaxf(mx0, __shfl_xor_sync(~0u, mx0, 1)); mx0 = fmaxf(mx0, __shfl_xor_sync(~0u, mx0, 2));
    mx1 = fmaxf(mx1, __shfl_xor_sync(~0u, mx1, 1)); mx1 = fmaxf(mx1, __shfl_xor_sync(~0u, mx1, 2));
    if (lc == 0) {
        rstat[wn * 64 + wm * 16 + lr    ] = mx0;
        rstat[wn * 64 + wm * 16 + lr + 8] = mx1;
    }
    __syncthreads();
    const float m0 = fmaxf(rstat[wm*16 + lr    ], rstat[64 + wm*16 + lr    ]);
    const float m1 = fmaxf(rstat[wm*16 + lr + 8], rstat[64 + wm*16 + lr + 8]);

    float sm0 = 0.f, sm1 = 0.f;
#pragma unroll
    for (int t = 0; t < 16; t++) {
        sacc[t][0] = __expf(sacc[t][0] - m0);
        sacc[t][1] = __expf(sacc[t][1] - m0);
        sacc[t][2] = __expf(sacc[t][2] - m1);
        sacc[t][3] = __expf(sacc[t][3] - m1);
        sm0 += sacc[t][0] + sacc[t][1];
        sm1 += sacc[t][2] + sacc[t][3];
    }
    sm0 += __shfl_xor_sync(~0u, sm0, 1); sm0 += __shfl_xor_sync(~0u, sm0, 2);
    sm1 += __shfl_xor_sync(~0u, sm1, 1); sm1 += __shfl_xor_sync(~0u, sm1, 2);
    if (lc == 0) {
        rstat[128 + wn * 64 + wm * 16 + lr    ] = sm0;
        rstat[128 + wn * 64 + wm * 16 + lr + 8] = sm1;
    }

    float oacc[8][4];
#pragma unroll
    for (int j = 0; j < 8; j++)
#pragma unroll
        for (int r = 0; r < 4; r++) oacc[j][r] = 0.f;
#pragma unroll
    for (int c = 0; c < 8; c++) {
        uint32_t pa[4];
        pa[0] = pack_h2(sacc[2*c    ][0], sacc[2*c    ][1]);
        pa[1] = pack_h2(sacc[2*c    ][2], sacc[2*c    ][3]);
        pa[2] = pack_h2(sacc[2*c + 1][0], sacc[2*c + 1][1]);
        pa[3] = pack_h2(sacc[2*c + 1][2], sacc[2*c + 1][3]);
#pragma unroll
        for (int p = 0; p < 4; p++) {
            uint32_t bt[4];
            ldm4(bt, Vt_u + voff + c * 32 + p * 16*264*2);
            uint32_t b0[2] = {bt[0], bt[1]}, b1[2] = {bt[2], bt[3]};
            mma_f16(oacc[2*p    ], pa, b0);
            mma_f16(oacc[2*p + 1], pa, b1);
        }
    }

    __syncthreads();
    if (wn == 0) {
#pragma unroll
        for (int j = 0; j < 8; j++) {
            const int col = 8*j + 2*lc;
            Of[(wm*16 + lr    ) * 72 + col    ] = oacc[j][0];
            Of[(wm*16 + lr    ) * 72 + col + 1] = oacc[j][1];
            Of[(wm*16 + lr + 8) * 72 + col    ] = oacc[j][2];
            Of[(wm*16 + lr + 8) * 72 + col + 1] = oacc[j][3];
        }
    }
    __syncthreads();
    if (wn == 1) {
#pragma unroll
        for (int j = 0; j < 8; j++) {
            const int col = 8*j + 2*lc;
            Of[(wm*16 + lr    ) * 72 + col    ] += oacc[j][0];
            Of[(wm*16 + lr    ) * 72 + col + 1] += oacc[j][1];
            Of[(wm*16 + lr + 8) * 72 + col    ] += oacc[j][2];
            Of[(wm*16 + lr + 8) * 72 + col + 1] += oacc[j][3];
        }
    }
    __syncthreads();
    for (int i = tid; i < 2048; i += 256) {
        const int row = i >> 5, c2 = (i & 31) * 2;
        const float inv = 1.f / (rstat[128 + row] + rstat[128 + 64 + row]);
        *(__half2*)(O + base + (size_t)(q0 + row) * H + c2) =
            __floats2half2_rn(Of[row*72 + c2] * inv, Of[row*72 + c2 + 1] * inv);
    }
}

// ---------------- fused windowed cross-attention core (bf16 staging; half hbar out) ----------------
#define SCORE_SMEM (36*1024*2 + 2*1024*4)
__global__ void __launch_bounds__(512) cross_score_kernel(
    const __nv_bfloat16* __restrict__ qk, const float* __restrict__ hs,
    const float* __restrict__ g, const float* __restrict__ b,
    __half* __restrict__ hbar)
{
    extern __shared__ char smraw[];
    __nv_bfloat16* srows = (__nv_bfloat16*)smraw;        // [36][1024] bf16
    float* sg = (float*)(smraw + 36*1024*2);
    float* sb = sg + 1024;
    __shared__ float sc[16*40];
    __shared__ float smu[36], srs[36];
    __shared__ int spos[36];

    const int row = blockIdx.x;      // b*256 + q
    const int bb = row >> 8, q = row & 255;
    const int tid = threadIdx.x;
    const int base = q * 8;
    const int nj = (base + 9 <= DOC) ? 9 : (DOC - base);
    const int nkv = LAYERS * nj;

    for (int i = tid; i < 1024; i += 512) { sg[i] = g[i]; sb[i] = b[i]; }
    if (tid < nkv) { const int l = tid / nj, jj = tid - l * nj; spos[tid] = l * DOC + base + jj; }
    __syncthreads();

    for (int idx = tid; idx < nkv * 256; idx += 512) {
        const int j = idx >> 8, c4 = (idx & 255) << 2;
        const int gr = bb * KVLEN + spos[j];
        const float4 v = *(const float4*)(hs + (size_t)gr * H + c4);
        __nv_bfloat162* d = (__nv_bfloat162*)(srows + (j << 10) + c4);
        d[0] = __floats2bfloat162_rn(v.x, v.y);
        d[1] = __floats2bfloat162_rn(v.z, v.w);
    }
    __syncthreads();

    const int w = tid >> 5, lane = tid & 31;
    for (int j = w; j < nkv; j += 16) {
        const __nv_bfloat162* r2 = (const __nv_bfloat162*)(srows + (j << 10));
        float s = 0.f, s2 = 0.f;
#pragma unroll
        for (int i = 0; i < 16; i++) {
            const float2 v = __bfloat1622float2(r2[lane + 32*i]);
            s += v.x + v.y; s2 += v.x*v.x + v.y*v.y;
        }
#pragma unroll
        for (int o = 16; o > 0; o >>= 1) { s += __shfl_xor_sync(~0u, s, o); s2 += __shfl_xor_sync(~0u, s2, o); }
        if (lane == 0) {
            const float mu = s * (1.f / H);
            smu[j] = mu;
            srs[j] = rsqrtf(s2 * (1.f / H) - mu * mu + 1e-5f);
        }
    }
    __syncthreads();

    for (int idx = tid; idx < nkv * 512; idx += 512) {
        const int j = idx >> 9, p = idx & 511;
        const float mu = smu[j], rs = srs[j];
        __nv_bfloat162* d = (__nv_bfloat162*)(srows + (j << 10)) + p;
        float2 v = __bfloat1622float2(*d);
        v.x = (v.x - mu) * rs * sg[2*p  ] + sb[2*p  ];
        v.y = (v.y - mu) * rs * sg[2*p+1] + sb[2*p+1];
        *d = __floats2bfloat162_rn(v.x, v.y);
    }
    __syncthreads();

    float2 qv[16];
    const __nv_bfloat162* qrow2 = (const __nv_bfloat162*)(qk + ((size_t)w * M1 + row) * H);
#pragma unroll
    for (int i = 0; i < 16; i++) qv[i] = __bfloat1622float2(qrow2[lane + 32*i]);
    for (int j = 0; j < nkv; j++) {
        const __nv_bfloat162* r2 = (const __nv_bfloat162*)(srows + (j << 10));
        float s = 0.f;
#pragma unroll
        for (int i = 0; i < 16; i++) {
            const float2 v = __bfloat1622float2(r2[lane + 32*i]);
            s += qv[i].x * v.x + qv[i].y * v.y;
        }
#pragma unroll
        for (int o = 16; o > 0; o >>= 1) s += __shfl_xor_sync(~0u, s, o);
        if (lane == 0) sc[w*40 + j] = s * 0.125f;
    }
    __syncthreads();

    {
        float v0 = (lane      < nkv) ? sc[w*40 + lane     ] : -1e30f;
        float v1 = (lane + 32 < nkv) ? sc[w*40 + lane + 32] : -1e30f;
        float m = fmaxf(v0, v1);
#pragma unroll
        for (int o = 16; o > 0; o >>= 1) m = fmaxf(m, __shfl_xor_sync(~0u, m, o));
        float e0 = (lane      < nkv) ? __expf(v0 - m) : 0.f;
        float e1 = (lane + 32 < nkv) ? __expf(v1 - m) : 0.f;
        float su = e0 + e1;
#pragma unroll
        for (int o = 16; o > 0; o >>= 1) su += __shfl_xor_sync(~0u, su, o);
        const float inv = 1.f / su;
        if (lane      < nkv) sc[w*40 + lane     ] = e0 * inv;
        if (lane + 32 < nkv) sc[w*40 + lane + 32] = e1 * inv;
    }
    __syncthreads();

    float acc[16][2];
#pragma unroll
    for (int h = 0; h < 16; h++) { acc[h][0] = 0.f; acc[h][1] = 0.f; }
    for (int j = 0; j < nkv; j++) {
        const float2 v = __bfloat1622float2(((const __nv_bfloat162*)(srows + (j << 10)))[tid]);
#pragma unroll
        for (int h = 0; h < 16; h++) {
            const float p = sc[h*40 + j];
            acc[h][0] += p * v.x;
            acc[h][1] += p * v.y;
        }
    }
    const int c0 = tid * 2;
#pragma unroll
    for (int h = 0; h < 16; h++)
        *(__half2*)(hbar + ((size_t)h * M1 + row) * H + c0) =
            __floats2half2_rn(acc[h][0], acc[h][1]);
}

// ---------------- launch ----------------
extern "C" void kernel_launch(void* const* d_in, const int* in_sizes, int n_in,
                              void* d_out_, int out_size)
{
    (void)in_sizes; (void)n_in; (void)out_size;
    const float* qtok = (const float*)d_in[0];
    const float* hs   = (const float*)d_in[1];
    const float* ln1g = (const float*)d_in[2];
    const float* ln1b = (const float*)d_in[3];
    const float* ln2g = (const float*)d_in[4];
    const float* ln2b = (const float*)d_in[5];
    const float* lnkvg= (const float*)d_in[6];
    const float* lnkvb= (const float*)d_in[7];
    const float* lnfg = (const float*)d_in[8];
    const float* lnfb = (const float*)d_in[9];
    const float* wqs  = (const float*)d_in[10];
    const float* wks  = (const float*)d_in[11];
    const float* wvs  = (const float*)d_in[12];
    const float* wos  = (const float*)d_in[13];
    const float* wqc  = (const float*)d_in[14];
    const float* wkc  = (const float*)d_in[15];
    const float* wvc  = (const float*)d_in[16];
    const float* woc  = (const float*)d_in[17];
    const float* w1   = (const float*)d_in[18];
    const float* w2   = (const float*)d_in[19];
    const float* w3   = (const float*)d_in[20];
    const float* okw  = (const float*)d_in[21];
    const float* ovw  = (const float*)d_in[22];
    float* out = (float*)d_out_;

    void* p;
    cudaGetSymbolAddress(&p, g_qt1);   float*  qt1  = (float*)p;
    cudaGetSymbolAddress(&p, g_qt2);   float*  qt2  = (float*)p;
    cudaGetSymbolAddress(&p, g_qk);    float*  qk   = (float*)p;
    cudaGetSymbolAddress(&p, g_qkvh);  __half* qkvh = (__half*)p;
    cudaGetSymbolAddress(&p, g_qbh);   __half* qbh  = (__half*)p;
    cudaGetSymbolAddress(&p, g_hbarh); __half* hbarh= (__half*)p;
    cudaGetSymbolAddress(&p, g_abh);   __half* abh  = (__half*)p;
    cudaGetSymbolAddress(&p, g_xlnh);  __half* xlnh = (__half*)p;
    cudaGetSymbolAddress(&p, g_h1h);   __half* h1h  = (__half*)p;
    cudaGetSymbolAddress(&p, g_qt1h);  __half* qt1h = (__half*)p;
    cudaGetSymbolAddress(&p, g_w1h);   __half* w1h  = (__half*)p;
    cudaGetSymbolAddress(&p, g_w2h);   __half* w2h  = (__half*)p;
    cudaGetSymbolAddress(&p, g_w3h);   __half* w3h  = (__half*)p;
    cudaGetSymbolAddress(&p, g_okwh);  __half* okwh = (__half*)p;
    cudaGetSymbolAddress(&p, g_ovwh);  __half* ovwh = (__half*)p;
    cudaGetSymbolAddress(&p, g_wqkvh); __half* wqkvh= (__half*)p;
    cudaGetSymbolAddress(&p, g_wosh);  __half* wosh = (__half*)p;
    cudaGetSymbolAddress(&p, g_wqch);  __half* wqch = (__half*)p;
    cudaGetSymbolAddress(&p, g_wkcTh); __half* wkcTh= (__half*)p;
    cudaGetSymbolAddress(&p, g_wvch);  __half* wvch = (__half*)p;
    cudaGetSymbolAddress(&p, g_woch);  __half* woch = (__half*)p;

    constexpr int SH_128_64  = smem_gh(128, 64);
    constexpr int SH_64_128  = smem_gh(64, 128);
    constexpr int SH_64_64   = smem_gh(64, 64);
    constexpr int SH_128_128 = smem_gh(128, 128);

    cudaFuncSetAttribute(self_attn_h,        cudaFuncAttributeMaxDynamicSharedMemorySize, SATTH_SMEM);
    cudaFuncSetAttribute(cross_score_kernel, cudaFuncAttributeMaxDynamicSharedMemorySize, SCORE_SMEM);
    cudaFuncSetAttribute(gemm2h<128,64>,     cudaFuncAttributeMaxDynamicSharedMemorySize, SH_128_64);
    cudaFuncSetAttribute(gemm2h<64,128>,     cudaFuncAttributeMaxDynamicSharedMemorySize, SH_64_128);
    cudaFuncSetAttribute(gemm2h<64,64>,      cudaFuncAttributeMaxDynamicSharedMemorySize, SH_64_64);
    cudaFuncSetAttribute(gemm2h<128,128>,    cudaFuncAttributeMaxDynamicSharedMemorySize, SH_128_128);
    cudaFuncSetAttribute(gemm_ffn_h,         cudaFuncAttributeMaxDynamicSharedMemorySize, FFNH_SMEM);
    cudaFuncSetAttribute(gemm_w3_h,          cudaFuncAttributeMaxDynamicSharedMemorySize, W3H_SMEM);
    cudaFuncSetAttribute(gemm_okv_h,         cudaFuncAttributeMaxDynamicSharedMemorySize, OKVH_SMEM);

    const dim3 gQKV (H/64, M1/128, 3);        // 384
    const dim3 gHH  (H/128, M1/64, 1);        // 128
    const dim3 gFFN (FFN_D/64, M1/128, 1);    // 512
    const dim3 gQK  (H/128, M1/128, NHEADS);  // 8 x 8 x 16 = 1024
    const dim3 gVP  (1, M1/64, NHEADS);       // 256
    const dim3 gOKV (4096/128, M1/128, 2);    // 512
    const dim3 gW3  (H/128, M1/64, 2);        // 256

    // 0) all weight conversions + wkc transpose in ONE launch
    convert_all<<<dim3(1024, 13), 256>>>(
        w1, w2, w3, okw, ovw, wqs, wks, wvs, wos, wqc, wvc, woc, wkc,
        w1h, w2h, w3h, okwh, ovwh,
        wqkvh, wqkvh + (size_t)H*H, wqkvh + 2*(size_t)H*H,
        wosh, wqch, wvch, woch, wkcTh);

    // 1) self-attention block (fp16 GEMMs + tensor-core attention)
    ln_kernel_h<<<M1, 256>>>(qtok, ln1g, ln1b, xlnh);
    gemm2h<128,64><<<gQKV, 256, SH_128_64>>>(xlnh, H, 0, wqkvh, H, (long)H*H,
                                             qkvh, H, (long)M1*H, nullptr, H, 0);
    self_attn_h<<<dim3(4, 64), 256, SATTH_SMEM>>>(qkvh, abh);
    gemm2h<64,128><<<gHH, 256, SH_64_128>>>(abh, H, 0, wosh, H, 0,
                                            qt1, H, 0, qtok, H, 1);

    // 2) windowed cross-attention (factorized; all-fp16 path, qk in bf16)
    ln_kernel_h<<<M1, 256>>>(qt1, ln2g, ln2b, xlnh);
    gemm2h<64,128><<<gHH, 256, SH_64_128>>>(xlnh, H, 0, wqch, H, 0,
                                            qbh, H, 0, nullptr, H, 0);
    gemm2h<128,128><<<gQK, 256, SH_128_128>>>(qbh, H, 64, wkcTh, H, 64,
                                              qk, H, (long)M1*H, nullptr, 64, 3);
    cross_score_kernel<<<M1, 512, SCORE_SMEM>>>((const __nv_bfloat16*)qk, hs, lnkvg, lnkvb, hbarh);
    gemm2h<64,64><<<gVP, 256, SH_64_64>>>(hbarh, H, (long)M1*H, wvch, H, (long)64*H,
                                          abh, H, 64, nullptr, H, 0);
    gemm2h<64,128><<<gHH, 256, SH_64_128>>>(abh, H, 0, woch, H, 0,
                                            qt2, H, 0, qt1, H, 1);

    // 3) SwiGLU FFN in fp16 (fused w1/w2 + silu; w3 via split-K=2 + reduce)
    ln_kernel_h<<<M1, 256>>>(qt2, lnfg, lnfb, xlnh);
    gemm_ffn_h<<<gFFN, 256, FFNH_SMEM>>>(xlnh, w1h, w2h, h1h);
    gemm_w3_h<<<gW3, 256, W3H_SMEM>>>(h1h, w3h, qk);
    reduce_w3<<<M1*H/1024, 256>>>(qk, qt2, qt1h, out);

    // 4) per-layer K/V output projections in fp16 (staged epilogue)
    gemm_okv_h<<<gOKV, 256, OKVH_SMEM>>>(qt1h, okwh, ovwh, out + (size_t)M1*H);
}